// round 1
// baseline (speedup 1.0000x reference)
#include <cuda_runtime.h>
#include <math.h>

// Problem constants
#define B_   64
#define S_   512
#define F_   512
#define HS_  1024
#define G3_  (3 * HS_)
#define M_   (B_ * S_)      // 32768 rows of gx

// Scratch: gx = x @ W_ih + bias, [B*S, 3H] = 384 MB (device bss — allowed)
__device__ float g_gx[(size_t)M_ * G3_];
// Ping-pong hidden state buffers [B, HS]
__device__ float g_h[2][B_ * HS_];

// ---------------------------------------------------------------------------
// Zero initial hidden state (h0 = 0). Must run every launch (deterministic).
// ---------------------------------------------------------------------------
__global__ void zero_h0_kernel() {
    int i = blockIdx.x * blockDim.x + threadIdx.x;   // 64 blocks x 1024 = B*HS
    g_h[0][i] = 0.0f;
}

// ---------------------------------------------------------------------------
// Phase 1: gx[m, n] = sum_k x[m,k] * Wih[k,n] + bias[n]
// M=32768, K=512, N=3072. 128x128x16 tiles, 256 threads, 8x8 register block.
// ---------------------------------------------------------------------------
__global__ void __launch_bounds__(256) gemm_gx_kernel(
    const float* __restrict__ A,     // x flattened [M, K]
    const float* __restrict__ Bw,    // W_ih [K, N]
    const float* __restrict__ bias)  // [N]
{
    const int K = F_;
    const int N = G3_;

    __shared__ float As[16][128];   // transposed A tile
    __shared__ float Bs[16][128];

    const int tid = threadIdx.x;
    const int tx  = tid & 15;       // 0..15 (N direction)
    const int ty  = tid >> 4;       // 0..15 (M direction)
    const int m0  = blockIdx.y * 128;
    const int n0  = blockIdx.x * 128;

    float acc[8][8];
#pragma unroll
    for (int i = 0; i < 8; i++)
#pragma unroll
        for (int j = 0; j < 8; j++) acc[i][j] = 0.0f;

    for (int k0 = 0; k0 < K; k0 += 16) {
        // Load A tile: 128 rows x 16 cols = 512 float4 (2 per thread), transpose into As
#pragma unroll
        for (int it = 0; it < 2; it++) {
            int idx  = tid + it * 256;
            int arow = idx >> 2;
            int ac4  = idx & 3;
            float4 va = *(const float4*)(A + (size_t)(m0 + arow) * K + k0 + ac4 * 4);
            As[ac4 * 4 + 0][arow] = va.x;
            As[ac4 * 4 + 1][arow] = va.y;
            As[ac4 * 4 + 2][arow] = va.z;
            As[ac4 * 4 + 3][arow] = va.w;

            int brow = idx >> 5;
            int bc4  = idx & 31;
            float4 vb = *(const float4*)(Bw + (size_t)(k0 + brow) * N + n0 + bc4 * 4);
            *(float4*)(&Bs[brow][bc4 * 4]) = vb;
        }
        __syncthreads();

#pragma unroll
        for (int k = 0; k < 16; k++) {
            float a[8], b[8];
#pragma unroll
            for (int i = 0; i < 8; i++) a[i] = As[k][ty * 8 + i];
#pragma unroll
            for (int j = 0; j < 8; j++) b[j] = Bs[k][tx * 8 + j];
#pragma unroll
            for (int i = 0; i < 8; i++)
#pragma unroll
                for (int j = 0; j < 8; j++)
                    acc[i][j] = fmaf(a[i], b[j], acc[i][j]);
        }
        __syncthreads();
    }

    // Epilogue: add bias, store
#pragma unroll
    for (int i = 0; i < 8; i++) {
        size_t mrow = (size_t)(m0 + ty * 8 + i) * N;
#pragma unroll
        for (int j = 0; j < 8; j++) {
            int n = n0 + tx * 8 + j;
            g_gx[mrow + n] = acc[i][j] + bias[n];
        }
    }
}

// ---------------------------------------------------------------------------
// Phase 2: one recurrence step.
// Grid: (32 col-tiles of 32 cols, 4 batch-tiles of 16 batches), 256 threads.
// smem: h tile [16][1024] fp32 = 64KB (dynamic).
// Thread t: column j = t&31 of the tile, batches 2*(t>>5), 2*(t>>5)+1.
// Per k: 3 coalesced W_hh loads (shared across warps via L1) + 2 smem
// broadcasts + 6 FFMA.
// ---------------------------------------------------------------------------
__global__ void __launch_bounds__(256) gru_step_kernel(
    const float* __restrict__ Whh,   // [HS, 3H]
    float* __restrict__ out,         // [B, S, HS]
    float* __restrict__ lastdst,     // [B, HS] or nullptr
    int t)
{
    extern __shared__ float hs[];    // [16][HS_]

    const float* __restrict__ h_in  = g_h[t & 1];
    float* __restrict__       h_out = g_h[(t + 1) & 1];

    const int tid   = threadIdx.x;
    const int ct    = blockIdx.x;        // 0..31
    const int bt    = blockIdx.y;        // 0..3
    const int bbase = bt * 16;

    // Load h tile: 16*1024 floats = 4096 float4, 16 per thread
    {
        const float4* src = (const float4*)(h_in + (size_t)bbase * HS_);
        float4*       dst = (float4*)hs;
#pragma unroll
        for (int i = 0; i < 16; i++)
            dst[tid + i * 256] = src[tid + i * 256];
    }
    __syncthreads();

    const int j   = tid & 31;
    const int bg  = tid >> 5;            // 0..7
    const int bl0 = bg * 2;
    const int bl1 = bg * 2 + 1;
    const int col = ct * 32 + j;         // 0..1023

    const float* __restrict__ wp  = Whh + col;
    const float* __restrict__ h0p = hs + bl0 * HS_;
    const float* __restrict__ h1p = hs + bl1 * HS_;

    float az0 = 0.f, az1 = 0.f, ar0 = 0.f, ar1 = 0.f, ae0 = 0.f, ae1 = 0.f;

#pragma unroll 4
    for (int k = 0; k < HS_; k++) {
        float vz = wp[0];
        float vr = wp[HS_];
        float ve = wp[2 * HS_];
        float h0 = h0p[k];
        float h1 = h1p[k];
        az0 = fmaf(h0, vz, az0);  az1 = fmaf(h1, vz, az1);
        ar0 = fmaf(h0, vr, ar0);  ar1 = fmaf(h1, vr, ar1);
        ae0 = fmaf(h0, ve, ae0);  ae1 = fmaf(h1, ve, ae1);
        wp += G3_;
    }

    float accz[2] = {az0, az1};
    float accr[2] = {ar0, ar1};
    float acce[2] = {ae0, ae1};

#pragma unroll
    for (int u = 0; u < 2; u++) {
        int bl = bg * 2 + u;
        int b  = bbase + bl;
        const float* __restrict__ gxp = g_gx + ((size_t)b * S_ + t) * G3_;

        float zpre = gxp[col]            + accz[u];
        float rpre = gxp[HS_ + col]      + accr[u];
        float epre = gxp[2 * HS_ + col];

        float z   = 1.0f / (1.0f + expf(-zpre));
        float r   = 1.0f / (1.0f + expf(-rpre));
        float eta = tanhf(epre + r * tanhf(acce[u]));

        float hp = hs[bl * HS_ + col];
        float hn = z * hp + (1.0f - z) * eta;

        h_out[(size_t)b * HS_ + col]          = hn;
        out[((size_t)b * S_ + t) * HS_ + col] = hn;
        if (lastdst) lastdst[(size_t)b * HS_ + col] = hn;
    }
}

// ---------------------------------------------------------------------------
// Launch: h0 zero -> gx GEMM -> 512 sequential step kernels (graph nodes give
// the inter-step grid sync). Graph-capturable: kernel launches only.
// ---------------------------------------------------------------------------
extern "C" void kernel_launch(void* const* d_in, const int* in_sizes, int n_in,
                              void* d_out, int out_size) {
    const float* x    = (const float*)d_in[0];   // [B, S, F]
    const float* wih  = (const float*)d_in[1];   // [F, 3H]
    const float* whh  = (const float*)d_in[2];   // [HS, 3H]
    const float* bias = (const float*)d_in[3];   // [3H]
    float* out = (float*)d_out;

    // Allow 64KB dynamic shared memory for the step kernel (idempotent).
    cudaFuncSetAttribute(gru_step_kernel,
                         cudaFuncAttributeMaxDynamicSharedMemorySize,
                         16 * HS_ * (int)sizeof(float));

    zero_h0_kernel<<<64, 1024>>>();

    gemm_gx_kernel<<<dim3(G3_ / 128, M_ / 128), 256>>>(x, wih, bias);

    // h_last segment only if the harness output includes it
    const long long seq_elems = (long long)B_ * S_ * HS_;
    float* lastdst = ((long long)out_size >= seq_elems + (long long)B_ * HS_)
                         ? out + seq_elems : nullptr;

    const int smem = 16 * HS_ * (int)sizeof(float);
    for (int t = 0; t < S_; t++) {
        gru_step_kernel<<<dim3(32, 4), 256, smem>>>(
            whh, out, (t == S_ - 1) ? lastdst : nullptr, t);
    }
}

// round 5
// speedup vs baseline: 2.7656x; 2.7656x over previous
#include <cuda_runtime.h>
#include <cuda_bf16.h>
#include <math.h>
#include <stdint.h>

// ---------------------------------------------------------------------------
// Problem constants
// ---------------------------------------------------------------------------
#define B_   64
#define S_   512
#define F_   512
#define HS_  1024
#define G3_  3072
#define M_   (B_ * S_)

#define NBLK 48          // persistent grid
#define NT2  64          // n-cols per persistent block
#define KC   32          // k chunk (bf16, 64B row)

// ---------------------------------------------------------------------------
// Device scratch
// ---------------------------------------------------------------------------
__device__ float g_gx[(size_t)M_ * G3_];
__device__ float g_gh[B_ * G3_];
__device__ float g_hf[2][B_ * HS_];
__device__ __nv_bfloat16 g_hhi[2][B_ * HS_];
__device__ __nv_bfloat16 g_hlo[2][B_ * HS_];
__device__ __nv_bfloat16 g_wthi[(size_t)G3_ * HS_];
__device__ __nv_bfloat16 g_wtlo[(size_t)G3_ * HS_];
__device__ __nv_bfloat16 g_wihi[(size_t)G3_ * F_];
__device__ __nv_bfloat16 g_wilo[(size_t)G3_ * F_];
__device__ __nv_bfloat16 g_xhi[(size_t)M_ * F_];
__device__ __nv_bfloat16 g_xlo[(size_t)M_ * F_];

__device__ unsigned g_bar_arrive;
__device__ unsigned g_bar_gen;

// ---------------------------------------------------------------------------
// PTX helpers (compute_80-level only — target is compute_103 non-'a')
// ---------------------------------------------------------------------------
__device__ __forceinline__ uint32_t s2u(const void* p) {
    uint32_t r;
    asm("{ .reg .u64 t; cvta.to.shared.u64 t, %1; cvt.u32.u64 %0, t; }"
        : "=r"(r) : "l"(p));
    return r;
}
__device__ __forceinline__ void cpasync16(uint32_t dst, const void* src) {
    asm volatile("cp.async.cg.shared.global [%0], [%1], 16;"
                 :: "r"(dst), "l"(src));
}
__device__ __forceinline__ void ldsm4(uint32_t* r, uint32_t addr) {
    asm volatile("ldmatrix.sync.aligned.m8n8.x4.shared.b16 {%0,%1,%2,%3}, [%4];"
                 : "=r"(r[0]), "=r"(r[1]), "=r"(r[2]), "=r"(r[3]) : "r"(addr));
}
__device__ __forceinline__ void mma_bf16(float* c, const uint32_t* a,
                                         const uint32_t* b) {
    asm volatile(
        "mma.sync.aligned.m16n8k16.row.col.f32.bf16.bf16.f32 "
        "{%0,%1,%2,%3}, {%4,%5,%6,%7}, {%8,%9}, {%0,%1,%2,%3};"
        : "+f"(c[0]), "+f"(c[1]), "+f"(c[2]), "+f"(c[3])
        : "r"(a[0]), "r"(a[1]), "r"(a[2]), "r"(a[3]), "r"(b[0]), "r"(b[1]));
}
// 16B-granule swizzle for 64B rows: conflict-free for 8-row ldmatrix phases.
__device__ __forceinline__ uint32_t swz(int r, int q) {
    return (uint32_t)(r * 64 + ((q ^ ((r >> 1) & 3)) << 4));
}

// Sense-reversing software grid barrier (all NBLK blocks co-resident).
__device__ __forceinline__ void grid_barrier() {
    __syncthreads();
    if (threadIdx.x == 0) {
        __threadfence();
        unsigned my = *((volatile unsigned*)&g_bar_gen);
        unsigned old = atomicAdd(&g_bar_arrive, 1u);
        if (old == NBLK - 1) {
            *((volatile unsigned*)&g_bar_arrive) = 0u;
            __threadfence();
            atomicAdd(&g_bar_gen, 1u);
        } else {
            while (*((volatile unsigned*)&g_bar_gen) == my) {
                __nanosleep(40);
            }
        }
        __threadfence();
    }
    __syncthreads();
}

// ---------------------------------------------------------------------------
// Prep kernels
// ---------------------------------------------------------------------------
__global__ void init_kernel() {
    int i = blockIdx.x * blockDim.x + threadIdx.x;   // 64 x 1024
    __nv_bfloat16 z = __float2bfloat16(0.0f);
    g_hf[0][i] = 0.0f;
    g_hhi[0][i] = z;
    g_hlo[0][i] = z;
    if (i == 0) { g_bar_arrive = 0u; g_bar_gen = 0u; }
}
__global__ void wprep_whh(const float* __restrict__ whh) {
    int i = blockIdx.x * blockDim.x + threadIdx.x;   // 3072 x 1024
    int k = i / G3_, n = i % G3_;
    float w = whh[i];
    __nv_bfloat16 hi = __float2bfloat16(w);
    g_wthi[(size_t)n * HS_ + k] = hi;
    g_wtlo[(size_t)n * HS_ + k] = __float2bfloat16(w - __bfloat162float(hi));
}
__global__ void wprep_wih(const float* __restrict__ wih) {
    int i = blockIdx.x * blockDim.x + threadIdx.x;   // 1536 x 1024
    int k = i / G3_, n = i % G3_;
    float w = wih[i];
    __nv_bfloat16 hi = __float2bfloat16(w);
    g_wihi[(size_t)n * F_ + k] = hi;
    g_wilo[(size_t)n * F_ + k] = __float2bfloat16(w - __bfloat162float(hi));
}
__global__ void xprep(const float* __restrict__ x) {
    size_t i = (size_t)blockIdx.x * blockDim.x + threadIdx.x;
    float v = x[i];
    __nv_bfloat16 hi = __float2bfloat16(v);
    g_xhi[i] = hi;
    g_xlo[i] = __float2bfloat16(v - __bfloat162float(hi));
}

// ---------------------------------------------------------------------------
// Phase 1 GEMM (validated in R4): out = A @ B^T (+bias), 3-term bf16 hi/lo.
// Block 64m x 128n, 4 warps 2x2, warp 32x64, KC=32 double-buffered.
// ---------------------------------------------------------------------------
__global__ void __launch_bounds__(128) mma_gemm_kernel(
    const __nv_bfloat16* __restrict__ Ahi, const __nv_bfloat16* __restrict__ Alo,
    const __nv_bfloat16* __restrict__ Bhi, const __nv_bfloat16* __restrict__ Blo,
    float* __restrict__ out, const float* __restrict__ bias, int K)
{
    __shared__ __align__(16) uint8_t smem_raw[2][24576];
    const int tid = threadIdx.x, lid = tid & 31, wid = tid >> 5;
    const int wm = wid & 1, wn = wid >> 1;
    const int m0 = blockIdx.y * 64, n0 = blockIdx.x * 128;
    const uint32_t sm0 = s2u(smem_raw[0]), sm1 = s2u(smem_raw[1]);

    float acc[2][8][4];
#pragma unroll
    for (int i = 0; i < 2; i++)
#pragma unroll
        for (int j = 0; j < 8; j++)
#pragma unroll
            for (int v = 0; v < 4; v++) acc[i][j][v] = 0.0f;

    const int NC = K >> 5;
    auto load_chunk = [&](uint32_t sb, int k0) {
#pragma unroll
        for (int t = 0; t < 2; t++) {
            const __nv_bfloat16* src = (t ? Alo : Ahi);
            uint32_t base = sb + t * 4096;
#pragma unroll
            for (int i = 0; i < 2; i++) {
                int cid = tid + i * 128;
                int r = cid >> 2, q = cid & 3;
                cpasync16(base + swz(r, q), src + (size_t)(m0 + r) * K + k0 + q * 8);
            }
        }
#pragma unroll
        for (int t = 0; t < 2; t++) {
            const __nv_bfloat16* src = (t ? Blo : Bhi);
            uint32_t base = sb + 8192 + t * 8192;
#pragma unroll
            for (int i = 0; i < 4; i++) {
                int cid = tid + i * 128;
                int r = cid >> 2, q = cid & 3;
                cpasync16(base + swz(r, q), src + (size_t)(n0 + r) * K + k0 + q * 8);
            }
        }
        asm volatile("cp.async.commit_group;");
    };

    load_chunk(sm0, 0);
    for (int c = 0; c < NC; c++) {
        if (c + 1 < NC) {
            load_chunk(((c + 1) & 1) ? sm1 : sm0, (c + 1) * KC);
            asm volatile("cp.async.wait_group 1;");
        } else {
            asm volatile("cp.async.wait_group 0;");
        }
        __syncthreads();
        const uint32_t sb = (c & 1) ? sm1 : sm0;
#pragma unroll
        for (int kk = 0; kk < 2; kk++) {
            const int qq = kk * 2 + (lid >> 4);
            uint32_t a_hi[2][4], a_lo[2][4];
#pragma unroll
            for (int i = 0; i < 2; i++) {
                int r = wm * 32 + i * 16 + (lid & 15);
                ldsm4(a_hi[i], sb + swz(r, qq));
                ldsm4(a_lo[i], sb + 4096 + swz(r, qq));
            }
            uint32_t b_hi[8][2], b_lo[8][2];
#pragma unroll
            for (int jj = 0; jj < 4; jj++) {
                int r = wn * 64 + jj * 16 + (lid & 15);
                uint32_t t4[4];
                ldsm4(t4, sb + 8192 + swz(r, qq));
                b_hi[2 * jj][0] = t4[0]; b_hi[2 * jj][1] = t4[2];
                b_hi[2 * jj + 1][0] = t4[1]; b_hi[2 * jj + 1][1] = t4[3];
                ldsm4(t4, sb + 16384 + swz(r, qq));
                b_lo[2 * jj][0] = t4[0]; b_lo[2 * jj][1] = t4[2];
                b_lo[2 * jj + 1][0] = t4[1]; b_lo[2 * jj + 1][1] = t4[3];
            }
#pragma unroll
            for (int i = 0; i < 2; i++)
#pragma unroll
                for (int j = 0; j < 8; j++) {
                    mma_bf16(acc[i][j], a_hi[i], b_hi[j]);
                    mma_bf16(acc[i][j], a_lo[i], b_hi[j]);
                    mma_bf16(acc[i][j], a_hi[i], b_lo[j]);
                }
        }
        __syncthreads();
    }
#pragma unroll
    for (int i = 0; i < 2; i++) {
        int m = m0 + wm * 32 + 16 * i + (lid >> 2);
#pragma unroll
        for (int j = 0; j < 8; j++) {
            int n = n0 + wn * 64 + 8 * j + 2 * (lid & 3);
            float2 v0 = make_float2(acc[i][j][0], acc[i][j][1]);
            float2 v1 = make_float2(acc[i][j][2], acc[i][j][3]);
            if (bias) {
                float b0 = bias[n], b1 = bias[n + 1];
                v0.x += b0; v0.y += b1;
                v1.x += b0; v1.y += b1;
            }
            *(float2*)(out + (size_t)m * G3_ + n) = v0;
            *(float2*)(out + (size_t)(m + 8) * G3_ + n) = v1;
        }
    }
}

// ---------------------------------------------------------------------------
// Persistent recurrence: 48 blocks, 128 threads. Per step:
//   GEMM tile (64m x 64n of gh) -> barrier -> fused pointwise -> barrier.
// ---------------------------------------------------------------------------
__global__ void __launch_bounds__(128) gru_persist_kernel(
    float* __restrict__ out, float* __restrict__ lastdst)
{
    __shared__ __align__(16) uint8_t smem_raw[2][16384];
    const int tid = threadIdx.x, lid = tid & 31, wid = tid >> 5;
    const int wm = wid & 1, wn = wid >> 1;
    const int n0 = blockIdx.x * NT2;
    const uint32_t sm0 = s2u(smem_raw[0]), sm1 = s2u(smem_raw[1]);

    const __nv_bfloat16* __restrict__ Bhi = g_wthi + (size_t)n0 * HS_;
    const __nv_bfloat16* __restrict__ Blo = g_wtlo + (size_t)n0 * HS_;

    for (int t = 0; t < S_; t++) {
        const __nv_bfloat16* __restrict__ Ahi = g_hhi[t & 1];
        const __nv_bfloat16* __restrict__ Alo = g_hlo[t & 1];

        float acc[2][4][4];
#pragma unroll
        for (int i = 0; i < 2; i++)
#pragma unroll
            for (int j = 0; j < 4; j++)
#pragma unroll
                for (int v = 0; v < 4; v++) acc[i][j][v] = 0.0f;

        // stage layout: Ahi[0,4K) Alo[4K,8K) Bhi[8K,12K) Blo[12K,16K)
        auto load_chunk = [&](uint32_t sb, int k0) {
#pragma unroll
            for (int tt = 0; tt < 2; tt++) {
                const __nv_bfloat16* src = (tt ? Alo : Ahi);
                uint32_t base = sb + tt * 4096;
                int cid = tid;                 // 64 rows x 4 q = 256 -> 2/thread
#pragma unroll
                for (int i = 0; i < 2; i++, cid += 128) {
                    int r = cid >> 2, q = cid & 3;
                    cpasync16(base + swz(r, q), src + (size_t)r * HS_ + k0 + q * 8);
                }
            }
#pragma unroll
            for (int tt = 0; tt < 2; tt++) {
                const __nv_bfloat16* src = (tt ? Blo : Bhi);
                uint32_t base = sb + 8192 + tt * 4096;
                int cid = tid;
#pragma unroll
                for (int i = 0; i < 2; i++, cid += 128) {
                    int r = cid >> 2, q = cid & 3;
                    cpasync16(base + swz(r, q), src + (size_t)r * HS_ + k0 + q * 8);
                }
            }
            asm volatile("cp.async.commit_group;");
        };

        const int NC = HS_ / KC;   // 32
        load_chunk(sm0, 0);
        for (int c = 0; c < NC; c++) {
            if (c + 1 < NC) {
                load_chunk(((c + 1) & 1) ? sm1 : sm0, (c + 1) * KC);
                asm volatile("cp.async.wait_group 1;");
            } else {
                asm volatile("cp.async.wait_group 0;");
            }
            __syncthreads();
            const uint32_t sb = (c & 1) ? sm1 : sm0;
#pragma unroll
            for (int kk = 0; kk < 2; kk++) {
                const int qq = kk * 2 + (lid >> 4);
                uint32_t a_hi[2][4], a_lo[2][4];
#pragma unroll
                for (int i = 0; i < 2; i++) {
                    int r = wm * 32 + i * 16 + (lid & 15);
                    ldsm4(a_hi[i], sb + swz(r, qq));
                    ldsm4(a_lo[i], sb + 4096 + swz(r, qq));
                }
                uint32_t b_hi[4][2], b_lo[4][2];
#pragma unroll
                for (int jj = 0; jj < 2; jj++) {
                    int r = wn * 32 + jj * 16 + (lid & 15);
                    uint32_t t4[4];
                    ldsm4(t4, sb + 8192 + swz(r, qq));
                    b_hi[2 * jj][0] = t4[0]; b_hi[2 * jj][1] = t4[2];
                    b_hi[2 * jj + 1][0] = t4[1]; b_hi[2 * jj + 1][1] = t4[3];
                    ldsm4(t4, sb + 12288 + swz(r, qq));
                    b_lo[2 * jj][0] = t4[0]; b_lo[2 * jj][1] = t4[2];
                    b_lo[2 * jj + 1][0] = t4[1]; b_lo[2 * jj + 1][1] = t4[3];
                }
#pragma unroll
                for (int i = 0; i < 2; i++)
#pragma unroll
                    for (int j = 0; j < 4; j++) {
                        mma_bf16(acc[i][j], a_hi[i], b_hi[j]);
                        mma_bf16(acc[i][j], a_lo[i], b_hi[j]);
                        mma_bf16(acc[i][j], a_hi[i], b_lo[j]);
                    }
            }
            __syncthreads();
        }

        // store gh tile
#pragma unroll
        for (int i = 0; i < 2; i++) {
            int m = wm * 32 + 16 * i + (lid >> 2);
#pragma unroll
            for (int j = 0; j < 4; j++) {
                int n = n0 + wn * 32 + 8 * j + 2 * (lid & 3);
                *(float2*)(g_gh + (size_t)m * G3_ + n) =
                    make_float2(acc[i][j][0], acc[i][j][1]);
                *(float2*)(g_gh + (size_t)(m + 8) * G3_ + n) =
                    make_float2(acc[i][j][2], acc[i][j][3]);
            }
        }

        grid_barrier();   // gh complete

        // fused pointwise: 65536 elems over 6144 threads
        int o = (t + 1) & 1;
        for (int idx = blockIdx.x * 128 + tid; idx < B_ * HS_; idx += NBLK * 128) {
            int b = idx >> 10;
            int cc = idx & (HS_ - 1);
            const float* __restrict__ ghp = g_gh + (size_t)b * G3_;
            const float* __restrict__ gxp = g_gx + ((size_t)b * S_ + t) * G3_;
            float z   = 1.0f / (1.0f + expf(-(gxp[cc] + ghp[cc])));
            float r   = 1.0f / (1.0f + expf(-(gxp[HS_ + cc] + ghp[HS_ + cc])));
            float eta = tanhf(gxp[2 * HS_ + cc] + r * tanhf(ghp[2 * HS_ + cc]));
            float hp = g_hf[t & 1][idx];
            float hn = z * hp + (1.0f - z) * eta;
            g_hf[o][idx] = hn;
            __nv_bfloat16 hi = __float2bfloat16(hn);
            g_hhi[o][idx] = hi;
            g_hlo[o][idx] = __float2bfloat16(hn - __bfloat162float(hi));
            out[((size_t)b * S_ + t) * HS_ + cc] = hn;
            if (lastdst && t == S_ - 1) lastdst[idx] = hn;
        }

        grid_barrier();   // h(t+1) complete
    }
}

// ---------------------------------------------------------------------------
// Host launch — 6 graph nodes total.
// ---------------------------------------------------------------------------
extern "C" void kernel_launch(void* const* d_in, const int* in_sizes, int n_in,
                              void* d_out, int out_size) {
    const float* x    = (const float*)d_in[0];
    const float* wih  = (const float*)d_in[1];
    const float* whh  = (const float*)d_in[2];
    const float* bias = (const float*)d_in[3];
    float* out = (float*)d_out;

    void *p_xhi, *p_xlo, *p_wihi, *p_wilo, *p_gx;
    cudaGetSymbolAddress(&p_xhi,  g_xhi);
    cudaGetSymbolAddress(&p_xlo,  g_xlo);
    cudaGetSymbolAddress(&p_wihi, g_wihi);
    cudaGetSymbolAddress(&p_wilo, g_wilo);
    cudaGetSymbolAddress(&p_gx,   g_gx);

    init_kernel<<<64, 1024>>>();
    wprep_whh<<<3072, 1024>>>(whh);
    wprep_wih<<<1536, 1024>>>(wih);
    xprep<<<16384, 1024>>>(x);

    mma_gemm_kernel<<<dim3(24, M_ / 64), 128>>>(
        (const __nv_bfloat16*)p_xhi, (const __nv_bfloat16*)p_xlo,
        (const __nv_bfloat16*)p_wihi, (const __nv_bfloat16*)p_wilo,
        (float*)p_gx, bias, F_);

    const long long seq_elems = (long long)B_ * S_ * HS_;
    float* lastdst = ((long long)out_size >= seq_elems + (long long)B_ * HS_)
                         ? out + seq_elems : nullptr;

    gru_persist_kernel<<<NBLK, 128>>>(out, lastdst);
}

// round 6
// speedup vs baseline: 4.0384x; 1.4602x over previous
#include <cuda_runtime.h>
#include <cuda_bf16.h>
#include <math.h>
#include <stdint.h>

// ---------------------------------------------------------------------------
// Problem constants
// ---------------------------------------------------------------------------
#define B_   64
#define S_   512
#define F_   512
#define HS_  1024
#define G3_  3072
#define M_   (B_ * S_)

#define NTILES 48        // n-tiles of 64 cols
#define KSPLIT 2         // K halves
#define NBLK_P (NTILES * KSPLIT)   // 96 persistent blocks
#define KH     (HS_ / KSPLIT)      // 512 per half
#define KC     32        // k chunk

// ---------------------------------------------------------------------------
// Device scratch
// ---------------------------------------------------------------------------
__device__ float g_gx[(size_t)M_ * G3_];
__device__ float g_ghp[KSPLIT][B_ * G3_];            // partial gh per K-half
__device__ float g_hf[2][B_ * HS_];
__device__ __nv_bfloat16 g_hhi[2][B_ * HS_];
__device__ __nv_bfloat16 g_hlo[2][B_ * HS_];
__device__ __nv_bfloat16 g_wthi[(size_t)G3_ * HS_];
__device__ __nv_bfloat16 g_wtlo[(size_t)G3_ * HS_];
__device__ __nv_bfloat16 g_wihi[(size_t)G3_ * F_];
__device__ __nv_bfloat16 g_wilo[(size_t)G3_ * F_];
__device__ __nv_bfloat16 g_xhi[(size_t)M_ * F_];
__device__ __nv_bfloat16 g_xlo[(size_t)M_ * F_];

__device__ unsigned g_bar_arrive;
__device__ unsigned g_bar_gen;

// ---------------------------------------------------------------------------
// PTX helpers (compute_80-level — target is compute_103 non-'a')
// ---------------------------------------------------------------------------
__device__ __forceinline__ uint32_t s2u(const void* p) {
    uint32_t r;
    asm("{ .reg .u64 t; cvta.to.shared.u64 t, %1; cvt.u32.u64 %0, t; }"
        : "=r"(r) : "l"(p));
    return r;
}
__device__ __forceinline__ void cpasync16(uint32_t dst, const void* src) {
    asm volatile("cp.async.cg.shared.global [%0], [%1], 16;"
                 :: "r"(dst), "l"(src));
}
__device__ __forceinline__ void ldsm4(uint32_t* r, uint32_t addr) {
    asm volatile("ldmatrix.sync.aligned.m8n8.x4.shared.b16 {%0,%1,%2,%3}, [%4];"
                 : "=r"(r[0]), "=r"(r[1]), "=r"(r[2]), "=r"(r[3]) : "r"(addr));
}
__device__ __forceinline__ void mma_bf16(float* c, const uint32_t* a,
                                         const uint32_t* b) {
    asm volatile(
        "mma.sync.aligned.m16n8k16.row.col.f32.bf16.bf16.f32 "
        "{%0,%1,%2,%3}, {%4,%5,%6,%7}, {%8,%9}, {%0,%1,%2,%3};"
        : "+f"(c[0]), "+f"(c[1]), "+f"(c[2]), "+f"(c[3])
        : "r"(a[0]), "r"(a[1]), "r"(a[2]), "r"(a[3]), "r"(b[0]), "r"(b[1]));
}
// 16B-granule swizzle for 64B rows: conflict-free 8-row ldmatrix phases.
__device__ __forceinline__ uint32_t swz(int r, int q) {
    return (uint32_t)(r * 64 + ((q ^ ((r >> 1) & 3)) << 4));
}

// Sense-reversing software grid barrier (all NBLK_P blocks co-resident).
__device__ __forceinline__ void grid_barrier() {
    __syncthreads();
    if (threadIdx.x == 0) {
        __threadfence();
        unsigned my = *((volatile unsigned*)&g_bar_gen);
        unsigned old = atomicAdd(&g_bar_arrive, 1u);
        if (old == NBLK_P - 1) {
            *((volatile unsigned*)&g_bar_arrive) = 0u;
            __threadfence();
            atomicAdd(&g_bar_gen, 1u);
        } else {
            while (*((volatile unsigned*)&g_bar_gen) == my) {
                __nanosleep(40);
            }
        }
        __threadfence();
    }
    __syncthreads();
}

// ---------------------------------------------------------------------------
// Prep kernels
// ---------------------------------------------------------------------------
__global__ void init_kernel() {
    int i = blockIdx.x * blockDim.x + threadIdx.x;   // 64 x 1024
    __nv_bfloat16 z = __float2bfloat16(0.0f);
    g_hf[0][i] = 0.0f;
    g_hhi[0][i] = z;
    g_hlo[0][i] = z;
    if (i == 0) { g_bar_arrive = 0u; g_bar_gen = 0u; }
}
__global__ void wprep_whh(const float* __restrict__ whh) {
    int i = blockIdx.x * blockDim.x + threadIdx.x;   // 3072 x 1024
    int k = i / G3_, n = i % G3_;
    float w = whh[i];
    __nv_bfloat16 hi = __float2bfloat16(w);
    g_wthi[(size_t)n * HS_ + k] = hi;
    g_wtlo[(size_t)n * HS_ + k] = __float2bfloat16(w - __bfloat162float(hi));
}
__global__ void wprep_wih(const float* __restrict__ wih) {
    int i = blockIdx.x * blockDim.x + threadIdx.x;   // 1536 x 1024
    int k = i / G3_, n = i % G3_;
    float w = wih[i];
    __nv_bfloat16 hi = __float2bfloat16(w);
    g_wihi[(size_t)n * F_ + k] = hi;
    g_wilo[(size_t)n * F_ + k] = __float2bfloat16(w - __bfloat162float(hi));
}
__global__ void xprep(const float* __restrict__ x) {
    size_t i = (size_t)blockIdx.x * blockDim.x + threadIdx.x;
    float v = x[i];
    __nv_bfloat16 hi = __float2bfloat16(v);
    g_xhi[i] = hi;
    g_xlo[i] = __float2bfloat16(v - __bfloat162float(hi));
}

// ---------------------------------------------------------------------------
// Phase 1 GEMM (validated): out = A @ B^T (+bias), 3-term bf16 hi/lo.
// Block 64m x 128n, 4 warps 2x2, warp 32x64, KC=32 double-buffered.
// ---------------------------------------------------------------------------
__global__ void __launch_bounds__(128) mma_gemm_kernel(
    const __nv_bfloat16* __restrict__ Ahi, const __nv_bfloat16* __restrict__ Alo,
    const __nv_bfloat16* __restrict__ Bhi, const __nv_bfloat16* __restrict__ Blo,
    float* __restrict__ out, const float* __restrict__ bias, int K)
{
    __shared__ __align__(16) uint8_t smem_raw[2][24576];
    const int tid = threadIdx.x, lid = tid & 31, wid = tid >> 5;
    const int wm = wid & 1, wn = wid >> 1;
    const int m0 = blockIdx.y * 64, n0 = blockIdx.x * 128;
    const uint32_t sm0 = s2u(smem_raw[0]), sm1 = s2u(smem_raw[1]);

    float acc[2][8][4];
#pragma unroll
    for (int i = 0; i < 2; i++)
#pragma unroll
        for (int j = 0; j < 8; j++)
#pragma unroll
            for (int v = 0; v < 4; v++) acc[i][j][v] = 0.0f;

    const int NC = K >> 5;
    auto load_chunk = [&](uint32_t sb, int k0) {
#pragma unroll
        for (int t = 0; t < 2; t++) {
            const __nv_bfloat16* src = (t ? Alo : Ahi);
            uint32_t base = sb + t * 4096;
#pragma unroll
            for (int i = 0; i < 2; i++) {
                int cid = tid + i * 128;
                int r = cid >> 2, q = cid & 3;
                cpasync16(base + swz(r, q), src + (size_t)(m0 + r) * K + k0 + q * 8);
            }
        }
#pragma unroll
        for (int t = 0; t < 2; t++) {
            const __nv_bfloat16* src = (t ? Blo : Bhi);
            uint32_t base = sb + 8192 + t * 8192;
#pragma unroll
            for (int i = 0; i < 4; i++) {
                int cid = tid + i * 128;
                int r = cid >> 2, q = cid & 3;
                cpasync16(base + swz(r, q), src + (size_t)(n0 + r) * K + k0 + q * 8);
            }
        }
        asm volatile("cp.async.commit_group;");
    };

    load_chunk(sm0, 0);
    for (int c = 0; c < NC; c++) {
        if (c + 1 < NC) {
            load_chunk(((c + 1) & 1) ? sm1 : sm0, (c + 1) * KC);
            asm volatile("cp.async.wait_group 1;");
        } else {
            asm volatile("cp.async.wait_group 0;");
        }
        __syncthreads();
        const uint32_t sb = (c & 1) ? sm1 : sm0;
#pragma unroll
        for (int kk = 0; kk < 2; kk++) {
            const int qq = kk * 2 + (lid >> 4);
            uint32_t a_hi[2][4], a_lo[2][4];
#pragma unroll
            for (int i = 0; i < 2; i++) {
                int r = wm * 32 + i * 16 + (lid & 15);
                ldsm4(a_hi[i], sb + swz(r, qq));
                ldsm4(a_lo[i], sb + 4096 + swz(r, qq));
            }
            uint32_t b_hi[8][2], b_lo[8][2];
#pragma unroll
            for (int jj = 0; jj < 4; jj++) {
                int r = wn * 64 + jj * 16 + (lid & 15);
                uint32_t t4[4];
                ldsm4(t4, sb + 8192 + swz(r, qq));
                b_hi[2 * jj][0] = t4[0]; b_hi[2 * jj][1] = t4[2];
                b_hi[2 * jj + 1][0] = t4[1]; b_hi[2 * jj + 1][1] = t4[3];
                ldsm4(t4, sb + 16384 + swz(r, qq));
                b_lo[2 * jj][0] = t4[0]; b_lo[2 * jj][1] = t4[2];
                b_lo[2 * jj + 1][0] = t4[1]; b_lo[2 * jj + 1][1] = t4[3];
            }
#pragma unroll
            for (int i = 0; i < 2; i++)
#pragma unroll
                for (int j = 0; j < 8; j++) {
                    mma_bf16(acc[i][j], a_hi[i], b_hi[j]);
                    mma_bf16(acc[i][j], a_lo[i], b_hi[j]);
                    mma_bf16(acc[i][j], a_hi[i], b_lo[j]);
                }
        }
        __syncthreads();
    }
#pragma unroll
    for (int i = 0; i < 2; i++) {
        int m = m0 + wm * 32 + 16 * i + (lid >> 2);
#pragma unroll
        for (int j = 0; j < 8; j++) {
            int n = n0 + wn * 64 + 8 * j + 2 * (lid & 3);
            float2 v0 = make_float2(acc[i][j][0], acc[i][j][1]);
            float2 v1 = make_float2(acc[i][j][2], acc[i][j][3]);
            if (bias) {
                float b0 = bias[n], b1 = bias[n + 1];
                v0.x += b0; v0.y += b1;
                v1.x += b0; v1.y += b1;
            }
            *(float2*)(out + (size_t)m * G3_ + n) = v0;
            *(float2*)(out + (size_t)(m + 8) * G3_ + n) = v1;
        }
    }
}

// ---------------------------------------------------------------------------
// Persistent recurrence: 96 blocks (48 n-tiles x 2 K-halves), 256 threads.
// Each block: 64m x 64n x K=512 partial GEMM -> barrier -> pointwise -> barrier.
// 8 warps (2m x 4n), warp tile 32m x 16n.
// ---------------------------------------------------------------------------
__global__ void __launch_bounds__(256) gru_persist_kernel(
    float* __restrict__ out, float* __restrict__ lastdst)
{
    __shared__ __align__(16) uint8_t smem_raw[2][16384];
    const int tid = threadIdx.x, lid = tid & 31, wid = tid >> 5;
    const int wm = wid & 1;          // 0..1 (m)
    const int wn = wid >> 1;         // 0..3 (n)
    const int nt = blockIdx.x % NTILES;
    const int kh = blockIdx.x / NTILES;   // 0..1
    const int n0 = nt * 64;
    const int kbase = kh * KH;
    const uint32_t sm0 = s2u(smem_raw[0]), sm1 = s2u(smem_raw[1]);

    const __nv_bfloat16* __restrict__ Bhi = g_wthi + (size_t)n0 * HS_ + kbase;
    const __nv_bfloat16* __restrict__ Blo = g_wtlo + (size_t)n0 * HS_ + kbase;
    float* __restrict__ ghdst = g_ghp[kh];

    for (int t = 0; t < S_; t++) {
        const __nv_bfloat16* __restrict__ Ahi = g_hhi[t & 1] + kbase;
        const __nv_bfloat16* __restrict__ Alo = g_hlo[t & 1] + kbase;

        float acc[2][2][4];
#pragma unroll
        for (int i = 0; i < 2; i++)
#pragma unroll
            for (int j = 0; j < 2; j++)
#pragma unroll
                for (int v = 0; v < 4; v++) acc[i][j][v] = 0.0f;

        // stage layout: Ahi[0,4K) Alo[4K,8K) Bhi[8K,12K) Blo[12K,16K)
        // 256 granules per 4KB buffer -> 1 cp.async per thread per buffer.
        auto load_chunk = [&](uint32_t sb, int k0) {
            int r = tid >> 2, q = tid & 3;
            size_t off = (size_t)r * HS_ + k0 + q * 8;
            cpasync16(sb + swz(r, q),          Ahi + off);
            cpasync16(sb + 4096 + swz(r, q),   Alo + off);
            cpasync16(sb + 8192 + swz(r, q),   Bhi + off);
            cpasync16(sb + 12288 + swz(r, q),  Blo + off);
            asm volatile("cp.async.commit_group;");
        };

        const int NC = KH / KC;   // 16
        load_chunk(sm0, 0);
        for (int c = 0; c < NC; c++) {
            if (c + 1 < NC) {
                load_chunk(((c + 1) & 1) ? sm1 : sm0, (c + 1) * KC);
                asm volatile("cp.async.wait_group 1;");
            } else {
                asm volatile("cp.async.wait_group 0;");
            }
            __syncthreads();
            const uint32_t sb = (c & 1) ? sm1 : sm0;
#pragma unroll
            for (int kk = 0; kk < 2; kk++) {
                const int qq = kk * 2 + (lid >> 4);
                uint32_t a_hi[2][4], a_lo[2][4];
#pragma unroll
                for (int i = 0; i < 2; i++) {
                    int r = wm * 32 + i * 16 + (lid & 15);
                    ldsm4(a_hi[i], sb + swz(r, qq));
                    ldsm4(a_lo[i], sb + 4096 + swz(r, qq));
                }
                uint32_t b_hi[2][2], b_lo[2][2];
                {
                    int r = wn * 16 + (lid & 15);
                    uint32_t t4[4];
                    ldsm4(t4, sb + 8192 + swz(r, qq));
                    b_hi[0][0] = t4[0]; b_hi[0][1] = t4[2];
                    b_hi[1][0] = t4[1]; b_hi[1][1] = t4[3];
                    ldsm4(t4, sb + 12288 + swz(r, qq));
                    b_lo[0][0] = t4[0]; b_lo[0][1] = t4[2];
                    b_lo[1][0] = t4[1]; b_lo[1][1] = t4[3];
                }
#pragma unroll
                for (int i = 0; i < 2; i++)
#pragma unroll
                    for (int j = 0; j < 2; j++) {
                        mma_bf16(acc[i][j], a_hi[i], b_hi[j]);
                        mma_bf16(acc[i][j], a_lo[i], b_hi[j]);
                        mma_bf16(acc[i][j], a_hi[i], b_lo[j]);
                    }
            }
            __syncthreads();
        }

        // store partial gh tile
#pragma unroll
        for (int i = 0; i < 2; i++) {
            int m = wm * 32 + 16 * i + (lid >> 2);
#pragma unroll
            for (int j = 0; j < 2; j++) {
                int n = n0 + wn * 16 + 8 * j + 2 * (lid & 3);
                *(float2*)(ghdst + (size_t)m * G3_ + n) =
                    make_float2(acc[i][j][0], acc[i][j][1]);
                *(float2*)(ghdst + (size_t)(m + 8) * G3_ + n) =
                    make_float2(acc[i][j][2], acc[i][j][3]);
            }
        }

        grid_barrier();   // all partial gh complete

        // fused pointwise: 65536 elems over 96*256 = 24576 threads
        int o = (t + 1) & 1;
        for (int idx = blockIdx.x * 256 + tid; idx < B_ * HS_; idx += NBLK_P * 256) {
            int b = idx >> 10;
            int cc = idx & (HS_ - 1);
            const float* __restrict__ g0 = g_ghp[0] + (size_t)b * G3_;
            const float* __restrict__ g1 = g_ghp[1] + (size_t)b * G3_;
            const float* __restrict__ gxp = g_gx + ((size_t)b * S_ + t) * G3_;
            float ghz = g0[cc]            + g1[cc];
            float ghr = g0[HS_ + cc]      + g1[HS_ + cc];
            float ghe = g0[2 * HS_ + cc]  + g1[2 * HS_ + cc];
            float z   = 1.0f / (1.0f + expf(-(gxp[cc] + ghz)));
            float r   = 1.0f / (1.0f + expf(-(gxp[HS_ + cc] + ghr)));
            float eta = tanhf(gxp[2 * HS_ + cc] + r * tanhf(ghe));
            float hp = g_hf[t & 1][idx];
            float hn = z * hp + (1.0f - z) * eta;
            g_hf[o][idx] = hn;
            __nv_bfloat16 hi = __float2bfloat16(hn);
            g_hhi[o][idx] = hi;
            g_hlo[o][idx] = __float2bfloat16(hn - __bfloat162float(hi));
            out[((size_t)b * S_ + t) * HS_ + cc] = hn;
            if (lastdst && t == S_ - 1) lastdst[idx] = hn;
        }

        grid_barrier();   // h(t+1) complete
    }
}

// ---------------------------------------------------------------------------
// Host launch — 6 graph nodes total.
// ---------------------------------------------------------------------------
extern "C" void kernel_launch(void* const* d_in, const int* in_sizes, int n_in,
                              void* d_out, int out_size) {
    const float* x    = (const float*)d_in[0];
    const float* wih  = (const float*)d_in[1];
    const float* whh  = (const float*)d_in[2];
    const float* bias = (const float*)d_in[3];
    float* out = (float*)d_out;

    void *p_xhi, *p_xlo, *p_wihi, *p_wilo, *p_gx;
    cudaGetSymbolAddress(&p_xhi,  g_xhi);
    cudaGetSymbolAddress(&p_xlo,  g_xlo);
    cudaGetSymbolAddress(&p_wihi, g_wihi);
    cudaGetSymbolAddress(&p_wilo, g_wilo);
    cudaGetSymbolAddress(&p_gx,   g_gx);

    init_kernel<<<64, 1024>>>();
    wprep_whh<<<3072, 1024>>>(whh);
    wprep_wih<<<1536, 1024>>>(wih);
    xprep<<<16384, 1024>>>(x);

    mma_gemm_kernel<<<dim3(24, M_ / 64), 128>>>(
        (const __nv_bfloat16*)p_xhi, (const __nv_bfloat16*)p_xlo,
        (const __nv_bfloat16*)p_wihi, (const __nv_bfloat16*)p_wilo,
        (float*)p_gx, bias, F_);

    const long long seq_elems = (long long)B_ * S_ * HS_;
    float* lastdst = ((long long)out_size >= seq_elems + (long long)B_ * HS_)
                         ? out + seq_elems : nullptr;

    gru_persist_kernel<<<NBLK_P, 256>>>(out, lastdst);
}

// round 7
// speedup vs baseline: 7.0061x; 1.7349x over previous
#include <cuda_runtime.h>
#include <cuda_bf16.h>
#include <math.h>
#include <stdint.h>

// ---------------------------------------------------------------------------
// Problem constants
// ---------------------------------------------------------------------------
#define B_   64
#define S_   512
#define F_   512
#define HS_  1024
#define G3_  3072
#define M_   (B_ * S_)

// Persistent kernel config: 24 n-tiles x 4 K-splits = 96 blocks
#define NTILES 24
#define KSPLIT 4
#define NBLK_P (NTILES * KSPLIT)     // 96
#define NTC    128                   // n cols per block
#define KPER   256                   // k per block
#define KC     32                    // k chunk
#define NCH    (KPER / KC)           // 8 chunks

// smem layout (dynamic, 192 KB):
//   W: 8 chunks x (8KB hi + 8KB lo) = 131072 B at offset 0
//   A: 8 chunks x (4KB hi + 4KB lo) =  65536 B at offset 131072
#define SMW_CH   16384
#define SMA_OFF  131072
#define SMA_CH   8192
#define SMEM_TOT 196608

// ---------------------------------------------------------------------------
// Device scratch
// ---------------------------------------------------------------------------
__device__ float g_gx[(size_t)M_ * G3_];
__device__ float g_ghp[KSPLIT][B_ * G3_];
__device__ float g_hf[2][B_ * HS_];
__device__ __nv_bfloat16 g_hhi[2][B_ * HS_];
__device__ __nv_bfloat16 g_hlo[2][B_ * HS_];
__device__ __nv_bfloat16 g_wthi[(size_t)G3_ * HS_];
__device__ __nv_bfloat16 g_wtlo[(size_t)G3_ * HS_];
__device__ __nv_bfloat16 g_wihi[(size_t)G3_ * F_];
__device__ __nv_bfloat16 g_wilo[(size_t)G3_ * F_];
__device__ __nv_bfloat16 g_xhi[(size_t)M_ * F_];
__device__ __nv_bfloat16 g_xlo[(size_t)M_ * F_];

__device__ unsigned g_bar_arrive;
__device__ unsigned g_bar_gen;

// ---------------------------------------------------------------------------
// PTX helpers (compute_80-level — target is compute_103 non-'a')
// ---------------------------------------------------------------------------
__device__ __forceinline__ uint32_t s2u(const void* p) {
    uint32_t r;
    asm("{ .reg .u64 t; cvta.to.shared.u64 t, %1; cvt.u32.u64 %0, t; }"
        : "=r"(r) : "l"(p));
    return r;
}
__device__ __forceinline__ void cpasync16(uint32_t dst, const void* src) {
    asm volatile("cp.async.cg.shared.global [%0], [%1], 16;"
                 :: "r"(dst), "l"(src));
}
__device__ __forceinline__ void ldsm4(uint32_t* r, uint32_t addr) {
    asm volatile("ldmatrix.sync.aligned.m8n8.x4.shared.b16 {%0,%1,%2,%3}, [%4];"
                 : "=r"(r[0]), "=r"(r[1]), "=r"(r[2]), "=r"(r[3]) : "r"(addr));
}
__device__ __forceinline__ void mma_bf16(float* c, const uint32_t* a,
                                         const uint32_t* b) {
    asm volatile(
        "mma.sync.aligned.m16n8k16.row.col.f32.bf16.bf16.f32 "
        "{%0,%1,%2,%3}, {%4,%5,%6,%7}, {%8,%9}, {%0,%1,%2,%3};"
        : "+f"(c[0]), "+f"(c[1]), "+f"(c[2]), "+f"(c[3])
        : "r"(a[0]), "r"(a[1]), "r"(a[2]), "r"(a[3]), "r"(b[0]), "r"(b[1]));
}
__device__ __forceinline__ void prefetchL2(const void* p) {
    asm volatile("prefetch.global.L2 [%0];" :: "l"(p));
}
// 16B-granule swizzle for 64B rows: conflict-free 8-row ldmatrix phases.
__device__ __forceinline__ uint32_t swz(int r, int q) {
    return (uint32_t)(r * 64 + ((q ^ ((r >> 1) & 3)) << 4));
}

// Sense-reversing grid barrier: plain volatile spin (no nanosleep).
__device__ __forceinline__ void grid_barrier() {
    __syncthreads();
    if (threadIdx.x == 0) {
        __threadfence();
        unsigned my = *((volatile unsigned*)&g_bar_gen);
        unsigned old = atomicAdd(&g_bar_arrive, 1u);
        if (old == NBLK_P - 1) {
            *((volatile unsigned*)&g_bar_arrive) = 0u;
            __threadfence();
            atomicAdd(&g_bar_gen, 1u);
        } else {
            while (*((volatile unsigned*)&g_bar_gen) == my) { }
        }
        __threadfence();
    }
    __syncthreads();
}

// ---------------------------------------------------------------------------
// Prep kernels
// ---------------------------------------------------------------------------
__global__ void init_kernel() {
    int i = blockIdx.x * blockDim.x + threadIdx.x;   // 64 x 1024
    __nv_bfloat16 z = __float2bfloat16(0.0f);
    g_hf[0][i] = 0.0f;
    g_hhi[0][i] = z;
    g_hlo[0][i] = z;
    if (i == 0) { g_bar_arrive = 0u; g_bar_gen = 0u; }
}
__global__ void wprep_whh(const float* __restrict__ whh) {
    int i = blockIdx.x * blockDim.x + threadIdx.x;   // 3072 x 1024
    int k = i / G3_, n = i % G3_;
    float w = whh[i];
    __nv_bfloat16 hi = __float2bfloat16(w);
    g_wthi[(size_t)n * HS_ + k] = hi;
    g_wtlo[(size_t)n * HS_ + k] = __float2bfloat16(w - __bfloat162float(hi));
}
__global__ void wprep_wih(const float* __restrict__ wih) {
    int i = blockIdx.x * blockDim.x + threadIdx.x;   // 1536 x 1024
    int k = i / G3_, n = i % G3_;
    float w = wih[i];
    __nv_bfloat16 hi = __float2bfloat16(w);
    g_wihi[(size_t)n * F_ + k] = hi;
    g_wilo[(size_t)n * F_ + k] = __float2bfloat16(w - __bfloat162float(hi));
}
__global__ void xprep(const float* __restrict__ x) {
    size_t i = (size_t)blockIdx.x * blockDim.x + threadIdx.x;
    float v = x[i];
    __nv_bfloat16 hi = __float2bfloat16(v);
    g_xhi[i] = hi;
    g_xlo[i] = __float2bfloat16(v - __bfloat162float(hi));
}

// ---------------------------------------------------------------------------
// Phase 1 GEMM (validated): out = A @ B^T (+bias), 3-term bf16 hi/lo.
// ---------------------------------------------------------------------------
__global__ void __launch_bounds__(128) mma_gemm_kernel(
    const __nv_bfloat16* __restrict__ Ahi, const __nv_bfloat16* __restrict__ Alo,
    const __nv_bfloat16* __restrict__ Bhi, const __nv_bfloat16* __restrict__ Blo,
    float* __restrict__ out, const float* __restrict__ bias, int K)
{
    __shared__ __align__(16) uint8_t smem_raw[2][24576];
    const int tid = threadIdx.x, lid = tid & 31, wid = tid >> 5;
    const int wm = wid & 1, wn = wid >> 1;
    const int m0 = blockIdx.y * 64, n0 = blockIdx.x * 128;
    const uint32_t sm0 = s2u(smem_raw[0]), sm1 = s2u(smem_raw[1]);

    float acc[2][8][4];
#pragma unroll
    for (int i = 0; i < 2; i++)
#pragma unroll
        for (int j = 0; j < 8; j++)
#pragma unroll
            for (int v = 0; v < 4; v++) acc[i][j][v] = 0.0f;

    const int NC = K >> 5;
    auto load_chunk = [&](uint32_t sb, int k0) {
#pragma unroll
        for (int t = 0; t < 2; t++) {
            const __nv_bfloat16* src = (t ? Alo : Ahi);
            uint32_t base = sb + t * 4096;
#pragma unroll
            for (int i = 0; i < 2; i++) {
                int cid = tid + i * 128;
                int r = cid >> 2, q = cid & 3;
                cpasync16(base + swz(r, q), src + (size_t)(m0 + r) * K + k0 + q * 8);
            }
        }
#pragma unroll
        for (int t = 0; t < 2; t++) {
            const __nv_bfloat16* src = (t ? Blo : Bhi);
            uint32_t base = sb + 8192 + t * 8192;
#pragma unroll
            for (int i = 0; i < 4; i++) {
                int cid = tid + i * 128;
                int r = cid >> 2, q = cid & 3;
                cpasync16(base + swz(r, q), src + (size_t)(n0 + r) * K + k0 + q * 8);
            }
        }
        asm volatile("cp.async.commit_group;");
    };

    load_chunk(sm0, 0);
    for (int c = 0; c < NC; c++) {
        if (c + 1 < NC) {
            load_chunk(((c + 1) & 1) ? sm1 : sm0, (c + 1) * KC);
            asm volatile("cp.async.wait_group 1;");
        } else {
            asm volatile("cp.async.wait_group 0;");
        }
        __syncthreads();
        const uint32_t sb = (c & 1) ? sm1 : sm0;
#pragma unroll
        for (int kk = 0; kk < 2; kk++) {
            const int qq = kk * 2 + (lid >> 4);
            uint32_t a_hi[2][4], a_lo[2][4];
#pragma unroll
            for (int i = 0; i < 2; i++) {
                int r = wm * 32 + i * 16 + (lid & 15);
                ldsm4(a_hi[i], sb + swz(r, qq));
                ldsm4(a_lo[i], sb + 4096 + swz(r, qq));
            }
            uint32_t b_hi[8][2], b_lo[8][2];
#pragma unroll
            for (int jj = 0; jj < 4; jj++) {
                int r = wn * 64 + jj * 16 + (lid & 15);
                uint32_t t4[4];
                ldsm4(t4, sb + 8192 + swz(r, qq));
                b_hi[2 * jj][0] = t4[0]; b_hi[2 * jj][1] = t4[2];
                b_hi[2 * jj + 1][0] = t4[1]; b_hi[2 * jj + 1][1] = t4[3];
                ldsm4(t4, sb + 16384 + swz(r, qq));
                b_lo[2 * jj][0] = t4[0]; b_lo[2 * jj][1] = t4[2];
                b_lo[2 * jj + 1][0] = t4[1]; b_lo[2 * jj + 1][1] = t4[3];
            }
#pragma unroll
            for (int i = 0; i < 2; i++)
#pragma unroll
                for (int j = 0; j < 8; j++) {
                    mma_bf16(acc[i][j], a_hi[i], b_hi[j]);
                    mma_bf16(acc[i][j], a_lo[i], b_hi[j]);
                    mma_bf16(acc[i][j], a_hi[i], b_lo[j]);
                }
        }
        __syncthreads();
    }
#pragma unroll
    for (int i = 0; i < 2; i++) {
        int m = m0 + wm * 32 + 16 * i + (lid >> 2);
#pragma unroll
        for (int j = 0; j < 8; j++) {
            int n = n0 + wn * 64 + 8 * j + 2 * (lid & 3);
            float2 v0 = make_float2(acc[i][j][0], acc[i][j][1]);
            float2 v1 = make_float2(acc[i][j][2], acc[i][j][3]);
            if (bias) {
                float b0 = bias[n], b1 = bias[n + 1];
                v0.x += b0; v0.y += b1;
                v1.x += b0; v1.y += b1;
            }
            *(float2*)(out + (size_t)m * G3_ + n) = v0;
            *(float2*)(out + (size_t)(m + 8) * G3_ + n) = v1;
        }
    }
}

// ---------------------------------------------------------------------------
// Persistent recurrence: 96 blocks (24 n-tiles x 4 K-quarters), 256 threads.
// W tile (128n x 256k hi/lo, 128 KB) resident in smem for all 512 steps.
// Per step: A burst-load (64 KB) -> sync-free 8-chunk mainloop -> barrier ->
// pointwise -> barrier.  8 warps: 2m x 4n, warp tile 32m x 32n.
// ---------------------------------------------------------------------------
__global__ void __launch_bounds__(256) gru_persist_kernel(
    float* __restrict__ out, float* __restrict__ lastdst)
{
    extern __shared__ __align__(16) uint8_t smem[];
    const uint32_t wbase = s2u(smem);
    const uint32_t abase = wbase + SMA_OFF;

    const int tid = threadIdx.x, lid = tid & 31, wid = tid >> 5;
    const int wm = wid & 1;          // 0..1 (m)
    const int wn = wid >> 1;         // 0..3 (n)
    const int nt = blockIdx.x % NTILES;
    const int kh = blockIdx.x / NTILES;      // 0..3
    const int n0 = nt * NTC;
    const int kbase = kh * KPER;

    const __nv_bfloat16* __restrict__ Whi = g_wthi;
    const __nv_bfloat16* __restrict__ Wlo = g_wtlo;
    float* __restrict__ ghdst = g_ghp[kh];

    // ---- one-time: load W tile (8192 granules, 32 per thread) ----
#pragma unroll
    for (int i = 0; i < 32; i++) {
        int gid = tid + i * 256;
        int c   = gid >> 10;                 // chunk 0..7
        int rem = gid & 1023;
        int dt  = rem >> 9;                  // 0=hi, 1=lo
        int rr  = (rem & 511) >> 2;          // row 0..127
        int q   = rem & 3;
        const __nv_bfloat16* src = dt ? Wlo : Whi;
        cpasync16(wbase + c * SMW_CH + dt * 8192 + swz(rr, q),
                  src + (size_t)(n0 + rr) * HS_ + kbase + c * KC + q * 8);
    }
    asm volatile("cp.async.commit_group;");
    asm volatile("cp.async.wait_group 0;");
    __syncthreads();

    for (int t = 0; t < S_; t++) {
        // ---- prefetch this step's gx slice for the pointwise phase ----
        {
            const float* gxt = g_gx + (size_t)t * G3_;   // indexed per-batch below
#pragma unroll
            for (int u = 0; u < 3; u++) {
                int idx = blockIdx.x * 256 + tid + u * NBLK_P * 256;
                if (idx < B_ * HS_) {
                    int b = idx >> 10, cc = idx & (HS_ - 1);
                    const float* p = g_gx + ((size_t)b * S_ + t) * G3_;
                    prefetchL2(p + cc);
                    prefetchL2(p + HS_ + cc);
                    prefetchL2(p + 2 * HS_ + cc);
                }
            }
            (void)gxt;
        }

        // ---- load A (h) tile: 4096 granules, 16 per thread ----
        const __nv_bfloat16* __restrict__ Ahi = g_hhi[t & 1] + kbase;
        const __nv_bfloat16* __restrict__ Alo = g_hlo[t & 1] + kbase;
#pragma unroll
        for (int i = 0; i < 16; i++) {
            int gid = tid + i * 256;
            int c   = gid >> 9;               // chunk 0..7
            int rem = gid & 511;
            int dt  = rem >> 8;
            int rr  = (rem & 255) >> 2;       // row 0..63
            int q   = rem & 3;
            const __nv_bfloat16* src = dt ? Alo : Ahi;
            cpasync16(abase + c * SMA_CH + dt * 4096 + swz(rr, q),
                      src + (size_t)rr * HS_ + c * KC + q * 8);
        }
        asm volatile("cp.async.commit_group;");
        asm volatile("cp.async.wait_group 0;");
        __syncthreads();

        // ---- sync-free mainloop: 8 chunks of pure ldsm + mma ----
        float acc[2][4][4];
#pragma unroll
        for (int i = 0; i < 2; i++)
#pragma unroll
            for (int j = 0; j < 4; j++)
#pragma unroll
                for (int v = 0; v < 4; v++) acc[i][j][v] = 0.0f;

#pragma unroll
        for (int c = 0; c < NCH; c++) {
            const uint32_t sbA = abase + c * SMA_CH;
            const uint32_t sbW = wbase + c * SMW_CH;
#pragma unroll
            for (int kk = 0; kk < 2; kk++) {
                const int qq = kk * 2 + (lid >> 4);
                uint32_t a_hi[2][4], a_lo[2][4];
#pragma unroll
                for (int i = 0; i < 2; i++) {
                    int r = wm * 32 + i * 16 + (lid & 15);
                    ldsm4(a_hi[i], sbA + swz(r, qq));
                    ldsm4(a_lo[i], sbA + 4096 + swz(r, qq));
                }
                uint32_t b_hi[4][2], b_lo[4][2];
#pragma unroll
                for (int jj = 0; jj < 2; jj++) {
                    int r = wn * 32 + jj * 16 + (lid & 15);
                    uint32_t t4[4];
                    ldsm4(t4, sbW + swz(r, qq));
                    b_hi[2 * jj][0] = t4[0]; b_hi[2 * jj][1] = t4[2];
                    b_hi[2 * jj + 1][0] = t4[1]; b_hi[2 * jj + 1][1] = t4[3];
                    ldsm4(t4, sbW + 8192 + swz(r, qq));
                    b_lo[2 * jj][0] = t4[0]; b_lo[2 * jj][1] = t4[2];
                    b_lo[2 * jj + 1][0] = t4[1]; b_lo[2 * jj + 1][1] = t4[3];
                }
#pragma unroll
                for (int i = 0; i < 2; i++)
#pragma unroll
                    for (int j = 0; j < 4; j++) {
                        mma_bf16(acc[i][j], a_hi[i], b_hi[j]);
                        mma_bf16(acc[i][j], a_lo[i], b_hi[j]);
                        mma_bf16(acc[i][j], a_hi[i], b_lo[j]);
                    }
            }
        }

        // ---- store partial gh tile ----
#pragma unroll
        for (int i = 0; i < 2; i++) {
            int m = wm * 32 + 16 * i + (lid >> 2);
#pragma unroll
            for (int j = 0; j < 4; j++) {
                int n = n0 + wn * 32 + 8 * j + 2 * (lid & 3);
                *(float2*)(ghdst + (size_t)m * G3_ + n) =
                    make_float2(acc[i][j][0], acc[i][j][1]);
                *(float2*)(ghdst + (size_t)(m + 8) * G3_ + n) =
                    make_float2(acc[i][j][2], acc[i][j][3]);
            }
        }

        grid_barrier();   // all partial gh complete

        // ---- fused pointwise: 65536 elems over 24576 threads ----
        int o = (t + 1) & 1;
        for (int idx = blockIdx.x * 256 + tid; idx < B_ * HS_; idx += NBLK_P * 256) {
            int b = idx >> 10;
            int cc = idx & (HS_ - 1);
            const float* __restrict__ g0 = g_ghp[0] + (size_t)b * G3_;
            const float* __restrict__ g1 = g_ghp[1] + (size_t)b * G3_;
            const float* __restrict__ g2 = g_ghp[2] + (size_t)b * G3_;
            const float* __restrict__ g3 = g_ghp[3] + (size_t)b * G3_;
            const float* __restrict__ gxp = g_gx + ((size_t)b * S_ + t) * G3_;
            float ghz = (g0[cc] + g1[cc]) + (g2[cc] + g3[cc]);
            float ghr = (g0[HS_ + cc] + g1[HS_ + cc]) + (g2[HS_ + cc] + g3[HS_ + cc]);
            float ghe = (g0[2 * HS_ + cc] + g1[2 * HS_ + cc]) +
                        (g2[2 * HS_ + cc] + g3[2 * HS_ + cc]);
            float z   = 1.0f / (1.0f + expf(-(gxp[cc] + ghz)));
            float r   = 1.0f / (1.0f + expf(-(gxp[HS_ + cc] + ghr)));
            float eta = tanhf(gxp[2 * HS_ + cc] + r * tanhf(ghe));
            float hp = g_hf[t & 1][idx];
            float hn = z * hp + (1.0f - z) * eta;
            g_hf[o][idx] = hn;
            __nv_bfloat16 hi = __float2bfloat16(hn);
            g_hhi[o][idx] = hi;
            g_hlo[o][idx] = __float2bfloat16(hn - __bfloat162float(hi));
            out[((size_t)b * S_ + t) * HS_ + cc] = hn;
            if (lastdst && t == S_ - 1) lastdst[idx] = hn;
        }

        grid_barrier();   // h(t+1) complete
    }
}

// ---------------------------------------------------------------------------
// Host launch — 6 graph nodes total.
// ---------------------------------------------------------------------------
extern "C" void kernel_launch(void* const* d_in, const int* in_sizes, int n_in,
                              void* d_out, int out_size) {
    const float* x    = (const float*)d_in[0];
    const float* wih  = (const float*)d_in[1];
    const float* whh  = (const float*)d_in[2];
    const float* bias = (const float*)d_in[3];
    float* out = (float*)d_out;

    void *p_xhi, *p_xlo, *p_wihi, *p_wilo, *p_gx;
    cudaGetSymbolAddress(&p_xhi,  g_xhi);
    cudaGetSymbolAddress(&p_xlo,  g_xlo);
    cudaGetSymbolAddress(&p_wihi, g_wihi);
    cudaGetSymbolAddress(&p_wilo, g_wilo);
    cudaGetSymbolAddress(&p_gx,   g_gx);

    cudaFuncSetAttribute(gru_persist_kernel,
                         cudaFuncAttributeMaxDynamicSharedMemorySize, SMEM_TOT);

    init_kernel<<<64, 1024>>>();
    wprep_whh<<<3072, 1024>>>(whh);
    wprep_wih<<<1536, 1024>>>(wih);
    xprep<<<16384, 1024>>>(x);

    mma_gemm_kernel<<<dim3(24, M_ / 64), 128>>>(
        (const __nv_bfloat16*)p_xhi, (const __nv_bfloat16*)p_xlo,
        (const __nv_bfloat16*)p_wihi, (const __nv_bfloat16*)p_wilo,
        (float*)p_gx, bias, F_);

    const long long seq_elems = (long long)B_ * S_ * HS_;
    float* lastdst = ((long long)out_size >= seq_elems + (long long)B_ * HS_)
                         ? out + seq_elems : nullptr;

    gru_persist_kernel<<<NBLK_P, 256, SMEM_TOT>>>(out, lastdst);
}

// round 8
// speedup vs baseline: 8.6205x; 1.2304x over previous
#include <cuda_runtime.h>
#include <cuda_bf16.h>
#include <math.h>
#include <stdint.h>

// ---------------------------------------------------------------------------
// Problem constants
// ---------------------------------------------------------------------------
#define B_   64
#define S_   512
#define F_   512
#define HS_  1024
#define G3_  3072
#define M_   (B_ * S_)

// Persistent config: 32 gate-grouped n-tiles (96 cols) x 4 K-splits = 128 blocks
#define NTILES 32
#define KSPLIT 4
#define NBLK_P (NTILES * KSPLIT)     // 128
#define NTC    96                    // cols per tile (3 gates x 32 cc)
#define KPER   256                   // k per block
#define KC     32                    // k chunk
#define NCH    (KPER / KC)           // 8
#define NTHR   384                   // 12 warps

// smem: W 8 chunks x (6KB hi + 6KB lo) = 98304, A 8 chunks x (4KB+4KB) = 65536
#define SMW_CH   12288
#define SMA_OFF  98304
#define SMA_CH   8192
#define SMEM_TOT 163840

// ---------------------------------------------------------------------------
// Device scratch
// ---------------------------------------------------------------------------
__device__ float g_gx[(size_t)M_ * G3_];
__device__ float g_ghp[KSPLIT][B_ * G3_];           // partials, PERMUTED col space
__device__ float g_hf[2][B_ * HS_];
__device__ __nv_bfloat16 g_hhi[2][B_ * HS_];
__device__ __nv_bfloat16 g_hlo[2][B_ * HS_];
__device__ __nv_bfloat16 g_wthi[(size_t)G3_ * HS_]; // W_hh^T, PERMUTED rows
__device__ __nv_bfloat16 g_wtlo[(size_t)G3_ * HS_];
__device__ __nv_bfloat16 g_wihi[(size_t)G3_ * F_];
__device__ __nv_bfloat16 g_wilo[(size_t)G3_ * F_];
__device__ __nv_bfloat16 g_xhi[(size_t)M_ * F_];
__device__ __nv_bfloat16 g_xlo[(size_t)M_ * F_];

// Monotone counters, prezeroed each launch (no reset races)
__device__ unsigned g_pdone[S_ * NTILES];   // per-step per-tile partial count (->4)
__device__ unsigned g_hready[S_ + 1];       // per-time h writers done (->128)

// ---------------------------------------------------------------------------
// PTX helpers (compute_80-level — target is compute_103 non-'a')
// ---------------------------------------------------------------------------
__device__ __forceinline__ uint32_t s2u(const void* p) {
    uint32_t r;
    asm("{ .reg .u64 t; cvta.to.shared.u64 t, %1; cvt.u32.u64 %0, t; }"
        : "=r"(r) : "l"(p));
    return r;
}
__device__ __forceinline__ void cpasync16(uint32_t dst, const void* src) {
    asm volatile("cp.async.cg.shared.global [%0], [%1], 16;"
                 :: "r"(dst), "l"(src));
}
__device__ __forceinline__ void ldsm4(uint32_t* r, uint32_t addr) {
    asm volatile("ldmatrix.sync.aligned.m8n8.x4.shared.b16 {%0,%1,%2,%3}, [%4];"
                 : "=r"(r[0]), "=r"(r[1]), "=r"(r[2]), "=r"(r[3]) : "r"(addr));
}
__device__ __forceinline__ void mma_bf16(float* c, const uint32_t* a,
                                         const uint32_t* b) {
    asm volatile(
        "mma.sync.aligned.m16n8k16.row.col.f32.bf16.bf16.f32 "
        "{%0,%1,%2,%3}, {%4,%5,%6,%7}, {%8,%9}, {%0,%1,%2,%3};"
        : "+f"(c[0]), "+f"(c[1]), "+f"(c[2]), "+f"(c[3])
        : "r"(a[0]), "r"(a[1]), "r"(a[2]), "r"(a[3]), "r"(b[0]), "r"(b[1]));
}
__device__ __forceinline__ void prefetchL2(const void* p) {
    asm volatile("prefetch.global.L2 [%0];" :: "l"(p));
}
__device__ __forceinline__ float ldcg(const float* p) {
    float v;
    asm volatile("ld.global.cg.f32 %0, [%1];" : "=f"(v) : "l"(p));
    return v;
}
// 16B-granule swizzle for 64B rows: conflict-free 8-row ldmatrix phases.
__device__ __forceinline__ uint32_t swz(int r, int q) {
    return (uint32_t)(r * 64 + ((q ^ ((r >> 1) & 3)) << 4));
}

// ---------------------------------------------------------------------------
// Prep kernels
// ---------------------------------------------------------------------------
__global__ void init_kernel() {
    int i = blockIdx.x * blockDim.x + threadIdx.x;   // 64 x 1024 = 65536
    __nv_bfloat16 z = __float2bfloat16(0.0f);
    g_hf[0][i] = 0.0f;
    g_hhi[0][i] = z;
    g_hlo[0][i] = z;
    if (i < S_ * NTILES) g_pdone[i] = 0u;
    if (i < S_ + 1)      g_hready[i] = 0u;
}
// W_hh^T with gate-grouped column permutation:
//   orig col n: gate=n/HS, cc=n%HS  ->  n_new = (cc/32)*96 + gate*32 + (cc%32)
__global__ void wprep_whh(const float* __restrict__ whh) {
    int i = blockIdx.x * blockDim.x + threadIdx.x;   // 3072 x 1024
    int k = i / G3_, n = i % G3_;
    int gate = n / HS_, cc = n % HS_;
    int n_new = (cc >> 5) * NTC + gate * 32 + (cc & 31);
    float w = whh[i];
    __nv_bfloat16 hi = __float2bfloat16(w);
    g_wthi[(size_t)n_new * HS_ + k] = hi;
    g_wtlo[(size_t)n_new * HS_ + k] = __float2bfloat16(w - __bfloat162float(hi));
}
__global__ void wprep_wih(const float* __restrict__ wih) {
    int i = blockIdx.x * blockDim.x + threadIdx.x;   // 1536 x 1024
    int k = i / G3_, n = i % G3_;
    float w = wih[i];
    __nv_bfloat16 hi = __float2bfloat16(w);
    g_wihi[(size_t)n * F_ + k] = hi;
    g_wilo[(size_t)n * F_ + k] = __float2bfloat16(w - __bfloat162float(hi));
}
__global__ void xprep(const float* __restrict__ x) {
    size_t i = (size_t)blockIdx.x * blockDim.x + threadIdx.x;
    float v = x[i];
    __nv_bfloat16 hi = __float2bfloat16(v);
    g_xhi[i] = hi;
    g_xlo[i] = __float2bfloat16(v - __bfloat162float(hi));
}

// ---------------------------------------------------------------------------
// Phase 1 GEMM (validated, unchanged): gx = x @ Wih^T (+bias), original layout.
// ---------------------------------------------------------------------------
__global__ void __launch_bounds__(128) mma_gemm_kernel(
    const __nv_bfloat16* __restrict__ Ahi, const __nv_bfloat16* __restrict__ Alo,
    const __nv_bfloat16* __restrict__ Bhi, const __nv_bfloat16* __restrict__ Blo,
    float* __restrict__ out, const float* __restrict__ bias, int K)
{
    __shared__ __align__(16) uint8_t smem_raw[2][24576];
    const int tid = threadIdx.x, lid = tid & 31, wid = tid >> 5;
    const int wm = wid & 1, wn = wid >> 1;
    const int m0 = blockIdx.y * 64, n0 = blockIdx.x * 128;
    const uint32_t sm0 = s2u(smem_raw[0]), sm1 = s2u(smem_raw[1]);

    float acc[2][8][4];
#pragma unroll
    for (int i = 0; i < 2; i++)
#pragma unroll
        for (int j = 0; j < 8; j++)
#pragma unroll
            for (int v = 0; v < 4; v++) acc[i][j][v] = 0.0f;

    const int NC = K >> 5;
    auto load_chunk = [&](uint32_t sb, int k0) {
#pragma unroll
        for (int t = 0; t < 2; t++) {
            const __nv_bfloat16* src = (t ? Alo : Ahi);
            uint32_t base = sb + t * 4096;
#pragma unroll
            for (int i = 0; i < 2; i++) {
                int cid = tid + i * 128;
                int r = cid >> 2, q = cid & 3;
                cpasync16(base + swz(r, q), src + (size_t)(m0 + r) * K + k0 + q * 8);
            }
        }
#pragma unroll
        for (int t = 0; t < 2; t++) {
            const __nv_bfloat16* src = (t ? Blo : Bhi);
            uint32_t base = sb + 8192 + t * 8192;
#pragma unroll
            for (int i = 0; i < 4; i++) {
                int cid = tid + i * 128;
                int r = cid >> 2, q = cid & 3;
                cpasync16(base + swz(r, q), src + (size_t)(n0 + r) * K + k0 + q * 8);
            }
        }
        asm volatile("cp.async.commit_group;");
    };

    load_chunk(sm0, 0);
    for (int c = 0; c < NC; c++) {
        if (c + 1 < NC) {
            load_chunk(((c + 1) & 1) ? sm1 : sm0, (c + 1) * KC);
            asm volatile("cp.async.wait_group 1;");
        } else {
            asm volatile("cp.async.wait_group 0;");
        }
        __syncthreads();
        const uint32_t sb = (c & 1) ? sm1 : sm0;
#pragma unroll
        for (int kk = 0; kk < 2; kk++) {
            const int qq = kk * 2 + (lid >> 4);
            uint32_t a_hi[2][4], a_lo[2][4];
#pragma unroll
            for (int i = 0; i < 2; i++) {
                int r = wm * 32 + i * 16 + (lid & 15);
                ldsm4(a_hi[i], sb + swz(r, qq));
                ldsm4(a_lo[i], sb + 4096 + swz(r, qq));
            }
            uint32_t b_hi[8][2], b_lo[8][2];
#pragma unroll
            for (int jj = 0; jj < 4; jj++) {
                int r = wn * 64 + jj * 16 + (lid & 15);
                uint32_t t4[4];
                ldsm4(t4, sb + 8192 + swz(r, qq));
                b_hi[2 * jj][0] = t4[0]; b_hi[2 * jj][1] = t4[2];
                b_hi[2 * jj + 1][0] = t4[1]; b_hi[2 * jj + 1][1] = t4[3];
                ldsm4(t4, sb + 16384 + swz(r, qq));
                b_lo[2 * jj][0] = t4[0]; b_lo[2 * jj][1] = t4[2];
                b_lo[2 * jj + 1][0] = t4[1]; b_lo[2 * jj + 1][1] = t4[3];
            }
#pragma unroll
            for (int i = 0; i < 2; i++)
#pragma unroll
                for (int j = 0; j < 8; j++) {
                    mma_bf16(acc[i][j], a_hi[i], b_hi[j]);
                    mma_bf16(acc[i][j], a_lo[i], b_hi[j]);
                    mma_bf16(acc[i][j], a_hi[i], b_lo[j]);
                }
        }
        __syncthreads();
    }
#pragma unroll
    for (int i = 0; i < 2; i++) {
        int m = m0 + wm * 32 + 16 * i + (lid >> 2);
#pragma unroll
        for (int j = 0; j < 8; j++) {
            int n = n0 + wn * 64 + 8 * j + 2 * (lid & 3);
            float2 v0 = make_float2(acc[i][j][0], acc[i][j][1]);
            float2 v1 = make_float2(acc[i][j][2], acc[i][j][3]);
            if (bias) {
                float b0 = bias[n], b1 = bias[n + 1];
                v0.x += b0; v0.y += b1;
                v1.x += b0; v1.y += b1;
            }
            *(float2*)(out + (size_t)m * G3_ + n) = v0;
            *(float2*)(out + (size_t)(m + 8) * G3_ + n) = v1;
        }
    }
}

// ---------------------------------------------------------------------------
// Persistent recurrence. 128 blocks = 32 tiles x 4 K-splits, 384 threads.
// W tile (96n x 256k hi/lo = 96 KB) resident all steps. Per step:
//   [spin h_ready] -> A load (pipelined) -> GEMM -> partial store ->
//   tile counter (4-way) -> pointwise for own 16-batch slice -> h_ready inc.
// ---------------------------------------------------------------------------
__global__ void __launch_bounds__(NTHR) gru_persist_kernel(
    float* __restrict__ out, float* __restrict__ lastdst)
{
    extern __shared__ __align__(16) uint8_t smem[];
    const uint32_t wbase = s2u(smem);
    const uint32_t abase = wbase + SMA_OFF;

    const int tid = threadIdx.x, lid = tid & 31, wid = tid >> 5;
    const int wm = wid & 1;            // 0..1
    const int wn = wid >> 1;           // 0..5
    const int tile = blockIdx.x % NTILES;     // 0..31
    const int kh   = blockIdx.x / NTILES;     // 0..3
    const int n0   = tile * NTC;
    const int kbase = kh * KPER;

    // ---- one-time: W tile load (6144 granules, 16/thread) ----
#pragma unroll
    for (int i = 0; i < 16; i++) {
        int gid = tid + i * NTHR;
        int c   = gid / 768;
        int rem = gid % 768;
        int dt  = rem / 384;
        int g   = rem % 384;
        int r   = g >> 2, q = g & 3;
        const __nv_bfloat16* src = dt ? g_wtlo : g_wthi;
        cpasync16(wbase + c * SMW_CH + dt * 6144 + swz(r, q),
                  src + (size_t)(n0 + r) * HS_ + kbase + c * KC + q * 8);
    }
    asm volatile("cp.async.commit_group;");
    asm volatile("cp.async.wait_group 0;");
    __syncthreads();

    float* __restrict__ ghdst = g_ghp[kh];
    const int b0 = kh * 16;            // pointwise batch slice

    for (int t = 0; t < S_; t++) {
        // ---- wait for h(t) ----
        if (t > 0) {
            if (tid == 0) {
                while (*((volatile unsigned*)&g_hready[t]) != (unsigned)NBLK_P) { }
            }
            __syncthreads();
            __threadfence();
        }

        // ---- A (h) load: 8 chunks, one commit group each ----
        const __nv_bfloat16* __restrict__ Ahi = g_hhi[t & 1] + kbase;
        const __nv_bfloat16* __restrict__ Alo = g_hlo[t & 1] + kbase;
#pragma unroll
        for (int c = 0; c < NCH; c++) {
#pragma unroll
            for (int p = 0; p < 2; p++) {
                int idx = tid + p * NTHR;
                if (idx < 512) {
                    int dt = idx >> 8;
                    int g  = idx & 255;
                    int r  = g >> 2, q = g & 3;
                    const __nv_bfloat16* src = dt ? Alo : Ahi;
                    cpasync16(abase + c * SMA_CH + dt * 4096 + swz(r, q),
                              src + (size_t)r * HS_ + c * KC + q * 8);
                }
            }
            asm volatile("cp.async.commit_group;");
        }

        // ---- prefetch this step's gx slice (own batches/cc) into L2 ----
        {
            int e = tid;                               // 512 elems, first 384
            int b = b0 + (e >> 5);
            int cc = tile * 32 + (e & 31);
            const float* p = g_gx + ((size_t)b * S_ + t) * G3_;
            prefetchL2(p + cc);
            prefetchL2(p + HS_ + cc);
            prefetchL2(p + 2 * HS_ + cc);
        }

        float acc[2][2][4];
#pragma unroll
        for (int i = 0; i < 2; i++)
#pragma unroll
            for (int j = 0; j < 2; j++)
#pragma unroll
                for (int v = 0; v < 4; v++) acc[i][j][v] = 0.0f;

        // ---- mainloop: two halves (chunks 0-3, 4-7), sync-free inside ----
#pragma unroll
        for (int half = 0; half < 2; half++) {
            if (half == 0) asm volatile("cp.async.wait_group 4;");
            else           asm volatile("cp.async.wait_group 0;");
            __syncthreads();
#pragma unroll
            for (int cc_ = 0; cc_ < 4; cc_++) {
                const int c = half * 4 + cc_;
                const uint32_t sbA = abase + c * SMA_CH;
                const uint32_t sbW = wbase + c * SMW_CH;
#pragma unroll
                for (int kk = 0; kk < 2; kk++) {
                    const int qq = kk * 2 + (lid >> 4);
                    uint32_t a_hi[2][4], a_lo[2][4];
#pragma unroll
                    for (int i = 0; i < 2; i++) {
                        int r = wm * 32 + i * 16 + (lid & 15);
                        ldsm4(a_hi[i], sbA + swz(r, qq));
                        ldsm4(a_lo[i], sbA + 4096 + swz(r, qq));
                    }
                    uint32_t b_hi[2][2], b_lo[2][2];
                    {
                        int r = wn * 16 + (lid & 15);
                        uint32_t t4[4];
                        ldsm4(t4, sbW + swz(r, qq));
                        b_hi[0][0] = t4[0]; b_hi[0][1] = t4[2];
                        b_hi[1][0] = t4[1]; b_hi[1][1] = t4[3];
                        ldsm4(t4, sbW + 6144 + swz(r, qq));
                        b_lo[0][0] = t4[0]; b_lo[0][1] = t4[2];
                        b_lo[1][0] = t4[1]; b_lo[1][1] = t4[3];
                    }
#pragma unroll
                    for (int i = 0; i < 2; i++)
#pragma unroll
                        for (int j = 0; j < 2; j++) {
                            mma_bf16(acc[i][j], a_hi[i], b_hi[j]);
                            mma_bf16(acc[i][j], a_lo[i], b_hi[j]);
                            mma_bf16(acc[i][j], a_hi[i], b_lo[j]);
                        }
                }
            }
        }

        // ---- store partial gh tile (permuted col space) ----
#pragma unroll
        for (int i = 0; i < 2; i++) {
            int m = wm * 32 + 16 * i + (lid >> 2);
#pragma unroll
            for (int j = 0; j < 2; j++) {
                int nc = n0 + wn * 16 + 8 * j + 2 * (lid & 3);
                *(float2*)(ghdst + (size_t)m * G3_ + nc) =
                    make_float2(acc[i][j][0], acc[i][j][1]);
                *(float2*)(ghdst + (size_t)(m + 8) * G3_ + nc) =
                    make_float2(acc[i][j][2], acc[i][j][3]);
            }
        }

        // ---- tile-local 4-way sync ----
        __threadfence();
        __syncthreads();
        if (tid == 0) {
            atomicAdd(&g_pdone[t * NTILES + tile], 1u);
            while (*((volatile unsigned*)&g_pdone[t * NTILES + tile]) != 4u) { }
        }
        __syncthreads();
        __threadfence();

        // ---- pointwise for own slice: 16 b x 32 cc = 512 elems ----
        int o = (t + 1) & 1;
#pragma unroll
        for (int p = 0; p < 2; p++) {
            int e = tid + p * NTHR;
            if (e < 512) {
                int b  = b0 + (e >> 5);
                int ccl = e & 31;
                int cc  = tile * 32 + ccl;
                size_t base = (size_t)b * G3_ + n0 + ccl;
                float ghz = ldcg(g_ghp[0] + base)      + ldcg(g_ghp[1] + base)
                          + ldcg(g_ghp[2] + base)      + ldcg(g_ghp[3] + base);
                float ghr = ldcg(g_ghp[0] + base + 32) + ldcg(g_ghp[1] + base + 32)
                          + ldcg(g_ghp[2] + base + 32) + ldcg(g_ghp[3] + base + 32);
                float ghe = ldcg(g_ghp[0] + base + 64) + ldcg(g_ghp[1] + base + 64)
                          + ldcg(g_ghp[2] + base + 64) + ldcg(g_ghp[3] + base + 64);
                const float* gxp = g_gx + ((size_t)b * S_ + t) * G3_;
                float z   = 1.0f / (1.0f + expf(-(gxp[cc] + ghz)));
                float r   = 1.0f / (1.0f + expf(-(gxp[HS_ + cc] + ghr)));
                float eta = tanhf(gxp[2 * HS_ + cc] + r * tanhf(ghe));
                int hidx = b * HS_ + cc;
                float hp = ldcg(&g_hf[t & 1][hidx]);
                float hn = z * hp + (1.0f - z) * eta;
                g_hf[o][hidx] = hn;
                __nv_bfloat16 hi = __float2bfloat16(hn);
                g_hhi[o][hidx] = hi;
                g_hlo[o][hidx] = __float2bfloat16(hn - __bfloat162float(hi));
                out[((size_t)b * S_ + t) * HS_ + cc] = hn;
                if (lastdst && t == S_ - 1) lastdst[hidx] = hn;
            }
        }

        // ---- publish h(t+1) ----
        __threadfence();
        __syncthreads();
        if (tid == 0) atomicAdd(&g_hready[t + 1], 1u);
    }
}

// ---------------------------------------------------------------------------
// Host launch — 6 graph nodes.
// ---------------------------------------------------------------------------
extern "C" void kernel_launch(void* const* d_in, const int* in_sizes, int n_in,
                              void* d_out, int out_size) {
    const float* x    = (const float*)d_in[0];
    const float* wih  = (const float*)d_in[1];
    const float* whh  = (const float*)d_in[2];
    const float* bias = (const float*)d_in[3];
    float* out = (float*)d_out;

    void *p_xhi, *p_xlo, *p_wihi, *p_wilo, *p_gx;
    cudaGetSymbolAddress(&p_xhi,  g_xhi);
    cudaGetSymbolAddress(&p_xlo,  g_xlo);
    cudaGetSymbolAddress(&p_wihi, g_wihi);
    cudaGetSymbolAddress(&p_wilo, g_wilo);
    cudaGetSymbolAddress(&p_gx,   g_gx);

    cudaFuncSetAttribute(gru_persist_kernel,
                         cudaFuncAttributeMaxDynamicSharedMemorySize, SMEM_TOT);

    init_kernel<<<64, 1024>>>();
    wprep_whh<<<3072, 1024>>>(whh);
    wprep_wih<<<1536, 1024>>>(wih);
    xprep<<<16384, 1024>>>(x);

    mma_gemm_kernel<<<dim3(24, M_ / 64), 128>>>(
        (const __nv_bfloat16*)p_xhi, (const __nv_bfloat16*)p_xlo,
        (const __nv_bfloat16*)p_wihi, (const __nv_bfloat16*)p_wilo,
        (float*)p_gx, bias, F_);

    const long long seq_elems = (long long)B_ * S_ * HS_;
    float* lastdst = ((long long)out_size >= seq_elems + (long long)B_ * HS_)
                         ? out + seq_elems : nullptr;

    gru_persist_kernel<<<NBLK_P, NTHR, SMEM_TOT>>>(out, lastdst);
}

// round 9
// speedup vs baseline: 9.4539x; 1.0967x over previous
#include <cuda_runtime.h>
#include <cuda_bf16.h>
#include <math.h>
#include <stdint.h>

// ---------------------------------------------------------------------------
// Problem constants
// ---------------------------------------------------------------------------
#define B_   64
#define S_   512
#define F_   512
#define HS_  1024
#define G3_  3072
#define M_   (B_ * S_)

// Persistent config: 32 gate-grouped n-tiles (96 cols) x 4 K-splits = 128 blocks
#define NTILES 32
#define KSPLIT 4
#define NBLK_P (NTILES * KSPLIT)     // 128
#define NTC    96                    // cols per tile (3 gates x 32 cc)
#define KPER   256                   // k per block
#define KC     32                    // k chunk
#define NCH    (KPER / KC)           // 8
#define NTHR   384                   // 12 warps

// smem: W 8 chunks x (6KB hi + 6KB lo) = 98304, A 8 chunks x (4KB+4KB) = 65536
#define SMW_CH   12288
#define SMA_OFF  98304
#define SMA_CH   8192
#define SMEM_TOT 163840

// ---------------------------------------------------------------------------
// Device scratch
// ---------------------------------------------------------------------------
__device__ float g_gx[(size_t)M_ * G3_];
__device__ float g_ghp[2][KSPLIT][B_ * G3_];        // partials, dbl-buf by t&1
__device__ float g_hf[4][B_ * HS_];                 // 4-deep (skew<=2 proof)
__device__ __nv_bfloat16 g_hhi[4][B_ * HS_];
__device__ __nv_bfloat16 g_hlo[4][B_ * HS_];
__device__ __nv_bfloat16 g_wthi[(size_t)G3_ * HS_]; // W_hh^T, PERMUTED rows
__device__ __nv_bfloat16 g_wtlo[(size_t)G3_ * HS_];
__device__ __nv_bfloat16 g_wihi[(size_t)G3_ * F_];
__device__ __nv_bfloat16 g_wilo[(size_t)G3_ * F_];
__device__ __nv_bfloat16 g_xhi[(size_t)M_ * F_];
__device__ __nv_bfloat16 g_xlo[(size_t)M_ * F_];

// Monotone counters, prezeroed each launch
__device__ unsigned g_pdone[S_ * NTILES];        // per-step per-tile partials (->4)
__device__ unsigned g_tdone[(S_ + 1) * NTILES];  // h cols of tile ready at t (->4)

// ---------------------------------------------------------------------------
// PTX helpers (compute_80-level — target is compute_103 non-'a')
// ---------------------------------------------------------------------------
__device__ __forceinline__ uint32_t s2u(const void* p) {
    uint32_t r;
    asm("{ .reg .u64 t; cvta.to.shared.u64 t, %1; cvt.u32.u64 %0, t; }"
        : "=r"(r) : "l"(p));
    return r;
}
__device__ __forceinline__ void cpasync16(uint32_t dst, const void* src) {
    asm volatile("cp.async.cg.shared.global [%0], [%1], 16;"
                 :: "r"(dst), "l"(src));
}
__device__ __forceinline__ void ldsm4(uint32_t* r, uint32_t addr) {
    asm volatile("ldmatrix.sync.aligned.m8n8.x4.shared.b16 {%0,%1,%2,%3}, [%4];"
                 : "=r"(r[0]), "=r"(r[1]), "=r"(r[2]), "=r"(r[3]) : "r"(addr));
}
__device__ __forceinline__ void mma_bf16(float* c, const uint32_t* a,
                                         const uint32_t* b) {
    asm volatile(
        "mma.sync.aligned.m16n8k16.row.col.f32.bf16.bf16.f32 "
        "{%0,%1,%2,%3}, {%4,%5,%6,%7}, {%8,%9}, {%0,%1,%2,%3};"
        : "+f"(c[0]), "+f"(c[1]), "+f"(c[2]), "+f"(c[3])
        : "r"(a[0]), "r"(a[1]), "r"(a[2]), "r"(a[3]), "r"(b[0]), "r"(b[1]));
}
__device__ __forceinline__ void prefetchL2(const void* p) {
    asm volatile("prefetch.global.L2 [%0];" :: "l"(p));
}
__device__ __forceinline__ float ldcg(const float* p) {
    float v;
    asm volatile("ld.global.cg.f32 %0, [%1];" : "=f"(v) : "l"(p));
    return v;
}
// Fast activations (error: few ulp — negligible vs 5e-6 budget)
__device__ __forceinline__ float fsig(float x) {
    return __fdividef(1.0f, 1.0f + __expf(-x));
}
__device__ __forceinline__ float ftanh(float x) {
    return 1.0f - __fdividef(2.0f, __expf(2.0f * x) + 1.0f);
}
// 16B-granule swizzle for 64B rows: conflict-free 8-row ldmatrix phases.
__device__ __forceinline__ uint32_t swz(int r, int q) {
    return (uint32_t)(r * 64 + ((q ^ ((r >> 1) & 3)) << 4));
}

// ---------------------------------------------------------------------------
// Prep kernels
// ---------------------------------------------------------------------------
__global__ void init_kernel() {
    int i = blockIdx.x * blockDim.x + threadIdx.x;   // 64 x 1024 = 65536
    __nv_bfloat16 z = __float2bfloat16(0.0f);
    g_hf[0][i] = 0.0f;
    g_hhi[0][i] = z;
    g_hlo[0][i] = z;
    if (i < S_ * NTILES)        g_pdone[i] = 0u;
    if (i < (S_ + 1) * NTILES)  g_tdone[i] = 0u;
}
// W_hh^T with gate-grouped column permutation:
//   orig col n: gate=n/HS, cc=n%HS  ->  n_new = (cc/32)*96 + gate*32 + (cc%32)
__global__ void wprep_whh(const float* __restrict__ whh) {
    int i = blockIdx.x * blockDim.x + threadIdx.x;   // 3072 x 1024
    int k = i / G3_, n = i % G3_;
    int gate = n / HS_, cc = n % HS_;
    int n_new = (cc >> 5) * NTC + gate * 32 + (cc & 31);
    float w = whh[i];
    __nv_bfloat16 hi = __float2bfloat16(w);
    g_wthi[(size_t)n_new * HS_ + k] = hi;
    g_wtlo[(size_t)n_new * HS_ + k] = __float2bfloat16(w - __bfloat162float(hi));
}
__global__ void wprep_wih(const float* __restrict__ wih) {
    int i = blockIdx.x * blockDim.x + threadIdx.x;   // 1536 x 1024
    int k = i / G3_, n = i % G3_;
    float w = wih[i];
    __nv_bfloat16 hi = __float2bfloat16(w);
    g_wihi[(size_t)n * F_ + k] = hi;
    g_wilo[(size_t)n * F_ + k] = __float2bfloat16(w - __bfloat162float(hi));
}
__global__ void xprep(const float* __restrict__ x) {
    size_t i = (size_t)blockIdx.x * blockDim.x + threadIdx.x;
    float v = x[i];
    __nv_bfloat16 hi = __float2bfloat16(v);
    g_xhi[i] = hi;
    g_xlo[i] = __float2bfloat16(v - __bfloat162float(hi));
}

// ---------------------------------------------------------------------------
// Phase 1 GEMM (validated, unchanged): gx = x @ Wih^T (+bias), original layout.
// ---------------------------------------------------------------------------
__global__ void __launch_bounds__(128) mma_gemm_kernel(
    const __nv_bfloat16* __restrict__ Ahi, const __nv_bfloat16* __restrict__ Alo,
    const __nv_bfloat16* __restrict__ Bhi, const __nv_bfloat16* __restrict__ Blo,
    float* __restrict__ out, const float* __restrict__ bias, int K)
{
    __shared__ __align__(16) uint8_t smem_raw[2][24576];
    const int tid = threadIdx.x, lid = tid & 31, wid = tid >> 5;
    const int wm = wid & 1, wn = wid >> 1;
    const int m0 = blockIdx.y * 64, n0 = blockIdx.x * 128;
    const uint32_t sm0 = s2u(smem_raw[0]), sm1 = s2u(smem_raw[1]);

    float acc[2][8][4];
#pragma unroll
    for (int i = 0; i < 2; i++)
#pragma unroll
        for (int j = 0; j < 8; j++)
#pragma unroll
            for (int v = 0; v < 4; v++) acc[i][j][v] = 0.0f;

    const int NC = K >> 5;
    auto load_chunk = [&](uint32_t sb, int k0) {
#pragma unroll
        for (int t = 0; t < 2; t++) {
            const __nv_bfloat16* src = (t ? Alo : Ahi);
            uint32_t base = sb + t * 4096;
#pragma unroll
            for (int i = 0; i < 2; i++) {
                int cid = tid + i * 128;
                int r = cid >> 2, q = cid & 3;
                cpasync16(base + swz(r, q), src + (size_t)(m0 + r) * K + k0 + q * 8);
            }
        }
#pragma unroll
        for (int t = 0; t < 2; t++) {
            const __nv_bfloat16* src = (t ? Blo : Bhi);
            uint32_t base = sb + 8192 + t * 8192;
#pragma unroll
            for (int i = 0; i < 4; i++) {
                int cid = tid + i * 128;
                int r = cid >> 2, q = cid & 3;
                cpasync16(base + swz(r, q), src + (size_t)(n0 + r) * K + k0 + q * 8);
            }
        }
        asm volatile("cp.async.commit_group;");
    };

    load_chunk(sm0, 0);
    for (int c = 0; c < NC; c++) {
        if (c + 1 < NC) {
            load_chunk(((c + 1) & 1) ? sm1 : sm0, (c + 1) * KC);
            asm volatile("cp.async.wait_group 1;");
        } else {
            asm volatile("cp.async.wait_group 0;");
        }
        __syncthreads();
        const uint32_t sb = (c & 1) ? sm1 : sm0;
#pragma unroll
        for (int kk = 0; kk < 2; kk++) {
            const int qq = kk * 2 + (lid >> 4);
            uint32_t a_hi[2][4], a_lo[2][4];
#pragma unroll
            for (int i = 0; i < 2; i++) {
                int r = wm * 32 + i * 16 + (lid & 15);
                ldsm4(a_hi[i], sb + swz(r, qq));
                ldsm4(a_lo[i], sb + 4096 + swz(r, qq));
            }
            uint32_t b_hi[8][2], b_lo[8][2];
#pragma unroll
            for (int jj = 0; jj < 4; jj++) {
                int r = wn * 64 + jj * 16 + (lid & 15);
                uint32_t t4[4];
                ldsm4(t4, sb + 8192 + swz(r, qq));
                b_hi[2 * jj][0] = t4[0]; b_hi[2 * jj][1] = t4[2];
                b_hi[2 * jj + 1][0] = t4[1]; b_hi[2 * jj + 1][1] = t4[3];
                ldsm4(t4, sb + 16384 + swz(r, qq));
                b_lo[2 * jj][0] = t4[0]; b_lo[2 * jj][1] = t4[2];
                b_lo[2 * jj + 1][0] = t4[1]; b_lo[2 * jj + 1][1] = t4[3];
            }
#pragma unroll
            for (int i = 0; i < 2; i++)
#pragma unroll
                for (int j = 0; j < 8; j++) {
                    mma_bf16(acc[i][j], a_hi[i], b_hi[j]);
                    mma_bf16(acc[i][j], a_lo[i], b_hi[j]);
                    mma_bf16(acc[i][j], a_hi[i], b_lo[j]);
                }
        }
        __syncthreads();
    }
#pragma unroll
    for (int i = 0; i < 2; i++) {
        int m = m0 + wm * 32 + 16 * i + (lid >> 2);
#pragma unroll
        for (int j = 0; j < 8; j++) {
            int n = n0 + wn * 64 + 8 * j + 2 * (lid & 3);
            float2 v0 = make_float2(acc[i][j][0], acc[i][j][1]);
            float2 v1 = make_float2(acc[i][j][2], acc[i][j][3]);
            if (bias) {
                float b0 = bias[n], b1 = bias[n + 1];
                v0.x += b0; v0.y += b1;
                v1.x += b0; v1.y += b1;
            }
            *(float2*)(out + (size_t)m * G3_ + n) = v0;
            *(float2*)(out + (size_t)(m + 8) * G3_ + n) = v1;
        }
    }
}

// ---------------------------------------------------------------------------
// Persistent recurrence. 128 blocks = 32 tiles x 4 K-splits, 384 threads.
// Dataflow sync: block (tile,kh) waits only on its 8 producer tiles
// (g_tdone) instead of a global barrier. h buffers 4-deep, gh partials
// double-buffered by step parity (skew bound <= 2 steps, proven via the
// 2-hop dependency closure).
// ---------------------------------------------------------------------------
__global__ void __launch_bounds__(NTHR) gru_persist_kernel(
    float* __restrict__ out, float* __restrict__ lastdst)
{
    extern __shared__ __align__(16) uint8_t smem[];
    const uint32_t wbase = s2u(smem);
    const uint32_t abase = wbase + SMA_OFF;

    const int tid = threadIdx.x, lid = tid & 31, wid = tid >> 5;
    const int wm = wid & 1;            // 0..1
    const int wn = wid >> 1;           // 0..5
    const int tile = blockIdx.x % NTILES;     // 0..31
    const int kh   = blockIdx.x / NTILES;     // 0..3
    const int n0   = tile * NTC;
    const int kbase = kh * KPER;

    // ---- one-time: W tile load (6144 granules, 16/thread) ----
#pragma unroll
    for (int i = 0; i < 16; i++) {
        int gid = tid + i * NTHR;
        int c   = gid / 768;
        int rem = gid % 768;
        int dt  = rem / 384;
        int g   = rem % 384;
        int r   = g >> 2, q = g & 3;
        const __nv_bfloat16* src = dt ? g_wtlo : g_wthi;
        cpasync16(wbase + c * SMW_CH + dt * 6144 + swz(r, q),
                  src + (size_t)(n0 + r) * HS_ + kbase + c * KC + q * 8);
    }
    asm volatile("cp.async.commit_group;");
    asm volatile("cp.async.wait_group 0;");
    __syncthreads();

    const int b0 = kh * 16;            // pointwise batch slice

    for (int t = 0; t < S_; t++) {
        // ---- wait for the 8 producer tiles of this block's k-range ----
        if (t > 0) {
            if (tid == 0) {
#pragma unroll
                for (int c = 0; c < NCH; c++) {
                    volatile unsigned* p = &g_tdone[t * NTILES + 8 * kh + c];
                    while (*p != 4u) { }
                }
            }
            __syncthreads();
        }

        // ---- A (h) load: 8 chunks, one commit group each ----
        const __nv_bfloat16* __restrict__ Ahi = g_hhi[t & 3] + kbase;
        const __nv_bfloat16* __restrict__ Alo = g_hlo[t & 3] + kbase;
#pragma unroll
        for (int c = 0; c < NCH; c++) {
#pragma unroll
            for (int p = 0; p < 2; p++) {
                int idx = tid + p * NTHR;
                if (idx < 512) {
                    int dt = idx >> 8;
                    int g  = idx & 255;
                    int r  = g >> 2, q = g & 3;
                    const __nv_bfloat16* src = dt ? Alo : Ahi;
                    cpasync16(abase + c * SMA_CH + dt * 4096 + swz(r, q),
                              src + (size_t)r * HS_ + c * KC + q * 8);
                }
            }
            asm volatile("cp.async.commit_group;");
        }

        // ---- prefetch this step's gx slice into L2 ----
        {
            int e = tid;
            int b = b0 + (e >> 5);
            int cc = tile * 32 + (e & 31);
            const float* p = g_gx + ((size_t)b * S_ + t) * G3_;
            prefetchL2(p + cc);
            prefetchL2(p + HS_ + cc);
            prefetchL2(p + 2 * HS_ + cc);
        }

        float acc[2][2][4];
#pragma unroll
        for (int i = 0; i < 2; i++)
#pragma unroll
            for (int j = 0; j < 2; j++)
#pragma unroll
                for (int v = 0; v < 4; v++) acc[i][j][v] = 0.0f;

        // ---- mainloop: two halves (chunks 0-3, 4-7), sync-free inside ----
#pragma unroll
        for (int half = 0; half < 2; half++) {
            if (half == 0) asm volatile("cp.async.wait_group 4;");
            else           asm volatile("cp.async.wait_group 0;");
            __syncthreads();
#pragma unroll
            for (int cc_ = 0; cc_ < 4; cc_++) {
                const int c = half * 4 + cc_;
                const uint32_t sbA = abase + c * SMA_CH;
                const uint32_t sbW = wbase + c * SMW_CH;
#pragma unroll
                for (int kk = 0; kk < 2; kk++) {
                    const int qq = kk * 2 + (lid >> 4);
                    uint32_t a_hi[2][4], a_lo[2][4];
#pragma unroll
                    for (int i = 0; i < 2; i++) {
                        int r = wm * 32 + i * 16 + (lid & 15);
                        ldsm4(a_hi[i], sbA + swz(r, qq));
                        ldsm4(a_lo[i], sbA + 4096 + swz(r, qq));
                    }
                    uint32_t b_hi[2][2], b_lo[2][2];
                    {
                        int r = wn * 16 + (lid & 15);
                        uint32_t t4[4];
                        ldsm4(t4, sbW + swz(r, qq));
                        b_hi[0][0] = t4[0]; b_hi[0][1] = t4[2];
                        b_hi[1][0] = t4[1]; b_hi[1][1] = t4[3];
                        ldsm4(t4, sbW + 6144 + swz(r, qq));
                        b_lo[0][0] = t4[0]; b_lo[0][1] = t4[2];
                        b_lo[1][0] = t4[1]; b_lo[1][1] = t4[3];
                    }
#pragma unroll
                    for (int i = 0; i < 2; i++)
#pragma unroll
                        for (int j = 0; j < 2; j++) {
                            mma_bf16(acc[i][j], a_hi[i], b_hi[j]);
                            mma_bf16(acc[i][j], a_lo[i], b_hi[j]);
                            mma_bf16(acc[i][j], a_hi[i], b_lo[j]);
                        }
                }
            }
        }

        // ---- store partial gh tile (parity buffer) ----
        float* __restrict__ ghdst = g_ghp[t & 1][kh];
#pragma unroll
        for (int i = 0; i < 2; i++) {
            int m = wm * 32 + 16 * i + (lid >> 2);
#pragma unroll
            for (int j = 0; j < 2; j++) {
                int nc = n0 + wn * 16 + 8 * j + 2 * (lid & 3);
                *(float2*)(ghdst + (size_t)m * G3_ + nc) =
                    make_float2(acc[i][j][0], acc[i][j][1]);
                *(float2*)(ghdst + (size_t)(m + 8) * G3_ + nc) =
                    make_float2(acc[i][j][2], acc[i][j][3]);
            }
        }

        // ---- tile-local 4-way sync ----
        __threadfence();
        __syncthreads();
        if (tid == 0) {
            atomicAdd(&g_pdone[t * NTILES + tile], 1u);
            while (*((volatile unsigned*)&g_pdone[t * NTILES + tile]) != 4u) { }
        }
        __syncthreads();

        // ---- pointwise for own slice: 16 b x 32 cc = 512 elems ----
        const int tp = t & 1;
        const int o  = (t + 1) & 3;
#pragma unroll
        for (int p = 0; p < 2; p++) {
            int e = tid + p * NTHR;
            if (e < 512) {
                int b  = b0 + (e >> 5);
                int ccl = e & 31;
                int cc  = tile * 32 + ccl;
                size_t base = (size_t)b * G3_ + n0 + ccl;
                float ghz = ldcg(g_ghp[tp][0] + base)      + ldcg(g_ghp[tp][1] + base)
                          + ldcg(g_ghp[tp][2] + base)      + ldcg(g_ghp[tp][3] + base);
                float ghr = ldcg(g_ghp[tp][0] + base + 32) + ldcg(g_ghp[tp][1] + base + 32)
                          + ldcg(g_ghp[tp][2] + base + 32) + ldcg(g_ghp[tp][3] + base + 32);
                float ghe = ldcg(g_ghp[tp][0] + base + 64) + ldcg(g_ghp[tp][1] + base + 64)
                          + ldcg(g_ghp[tp][2] + base + 64) + ldcg(g_ghp[tp][3] + base + 64);
                const float* gxp = g_gx + ((size_t)b * S_ + t) * G3_;
                float z   = fsig(gxp[cc] + ghz);
                float r   = fsig(gxp[HS_ + cc] + ghr);
                float eta = ftanh(gxp[2 * HS_ + cc] + r * ftanh(ghe));
                int hidx = b * HS_ + cc;
                float hp = ldcg(&g_hf[t & 3][hidx]);
                float hn = z * hp + (1.0f - z) * eta;
                g_hf[o][hidx] = hn;
                __nv_bfloat16 hi = __float2bfloat16(hn);
                g_hhi[o][hidx] = hi;
                g_hlo[o][hidx] = __float2bfloat16(hn - __bfloat162float(hi));
                out[((size_t)b * S_ + t) * HS_ + cc] = hn;
                if (lastdst && t == S_ - 1) lastdst[hidx] = hn;
            }
        }

        // ---- publish h(t+1) cols for this tile ----
        __threadfence();
        __syncthreads();
        if (tid == 0) atomicAdd(&g_tdone[(t + 1) * NTILES + tile], 1u);
    }
}

// ---------------------------------------------------------------------------
// Host launch — 6 graph nodes.
// ---------------------------------------------------------------------------
extern "C" void kernel_launch(void* const* d_in, const int* in_sizes, int n_in,
                              void* d_out, int out_size) {
    const float* x    = (const float*)d_in[0];
    const float* wih  = (const float*)d_in[1];
    const float* whh  = (const float*)d_in[2];
    const float* bias = (const float*)d_in[3];
    float* out = (float*)d_out;

    void *p_xhi, *p_xlo, *p_wihi, *p_wilo, *p_gx;
    cudaGetSymbolAddress(&p_xhi,  g_xhi);
    cudaGetSymbolAddress(&p_xlo,  g_xlo);
    cudaGetSymbolAddress(&p_wihi, g_wihi);
    cudaGetSymbolAddress(&p_wilo, g_wilo);
    cudaGetSymbolAddress(&p_gx,   g_gx);

    cudaFuncSetAttribute(gru_persist_kernel,
                         cudaFuncAttributeMaxDynamicSharedMemorySize, SMEM_TOT);

    init_kernel<<<64, 1024>>>();
    wprep_whh<<<3072, 1024>>>(whh);
    wprep_wih<<<1536, 1024>>>(wih);
    xprep<<<16384, 1024>>>(x);

    mma_gemm_kernel<<<dim3(24, M_ / 64), 128>>>(
        (const __nv_bfloat16*)p_xhi, (const __nv_bfloat16*)p_xlo,
        (const __nv_bfloat16*)p_wihi, (const __nv_bfloat16*)p_wilo,
        (float*)p_gx, bias, F_);

    const long long seq_elems = (long long)B_ * S_ * HS_;
    float* lastdst = ((long long)out_size >= seq_elems + (long long)B_ * HS_)
                         ? out + seq_elems : nullptr;

    gru_persist_kernel<<<NBLK_P, NTHR, SMEM_TOT>>>(out, lastdst);
}

// round 10
// speedup vs baseline: 10.4927x; 1.1099x over previous
#include <cuda_runtime.h>
#include <cuda_bf16.h>
#include <math.h>
#include <stdint.h>

// ---------------------------------------------------------------------------
// Problem constants
// ---------------------------------------------------------------------------
#define B_   64
#define S_   512
#define F_   512
#define HS_  1024
#define G3_  3072
#define M_   (B_ * S_)

// Persistent config: 32 gate-grouped n-tiles (96 cols) x 4 K-splits = 128 blocks
#define NTILES 32
#define KSPLIT 4
#define NBLK_P (NTILES * KSPLIT)     // 128
#define NTC    96                    // cols per tile (3 gates x 32 cc)
#define KPER   256                   // k per block
#define KC     32                    // k chunk
#define NCH    (KPER / KC)           // 8
#define NTHR   384                   // 12 warps

// smem: W 8 chunks x (6KB hi + 6KB lo) = 98304, A 8 chunks x (4KB+4KB) = 65536
#define SMW_CH   12288
#define SMA_OFF  98304
#define SMA_CH   8192
#define SMEM_TOT 163840

// ---------------------------------------------------------------------------
// Device scratch
// ---------------------------------------------------------------------------
__device__ float g_gx[(size_t)M_ * G3_];
__device__ float g_ghp[2][KSPLIT][B_ * G3_];        // partials, dbl-buf by t&1
__device__ float g_hf[4][B_ * HS_];                 // 4-deep (skew<=2 proof)
__device__ __nv_bfloat16 g_hhi[4][B_ * HS_];
__device__ __nv_bfloat16 g_hlo[4][B_ * HS_];
__device__ __nv_bfloat16 g_wthi[(size_t)G3_ * HS_]; // W_hh^T, PERMUTED rows
__device__ __nv_bfloat16 g_wtlo[(size_t)G3_ * HS_];
__device__ __nv_bfloat16 g_wihi[(size_t)G3_ * F_];
__device__ __nv_bfloat16 g_wilo[(size_t)G3_ * F_];
__device__ __nv_bfloat16 g_xhi[(size_t)M_ * F_];
__device__ __nv_bfloat16 g_xlo[(size_t)M_ * F_];

// Monotone counters, prezeroed each launch
__device__ unsigned g_pdone[S_ * NTILES];        // per-step per-tile partials (->4)
__device__ unsigned g_tdone[(S_ + 1) * NTILES];  // h cols of tile ready at t (->4)

// ---------------------------------------------------------------------------
// PTX helpers (compute_80-level — target is compute_103 non-'a')
// ---------------------------------------------------------------------------
__device__ __forceinline__ uint32_t s2u(const void* p) {
    uint32_t r;
    asm("{ .reg .u64 t; cvta.to.shared.u64 t, %1; cvt.u32.u64 %0, t; }"
        : "=r"(r) : "l"(p));
    return r;
}
__device__ __forceinline__ void cpasync16(uint32_t dst, const void* src) {
    asm volatile("cp.async.cg.shared.global [%0], [%1], 16;"
                 :: "r"(dst), "l"(src));
}
__device__ __forceinline__ void ldsm4(uint32_t* r, uint32_t addr) {
    asm volatile("ldmatrix.sync.aligned.m8n8.x4.shared.b16 {%0,%1,%2,%3}, [%4];"
                 : "=r"(r[0]), "=r"(r[1]), "=r"(r[2]), "=r"(r[3]) : "r"(addr));
}
__device__ __forceinline__ void mma_bf16(float* c, const uint32_t* a,
                                         const uint32_t* b) {
    asm volatile(
        "mma.sync.aligned.m16n8k16.row.col.f32.bf16.bf16.f32 "
        "{%0,%1,%2,%3}, {%4,%5,%6,%7}, {%8,%9}, {%0,%1,%2,%3};"
        : "+f"(c[0]), "+f"(c[1]), "+f"(c[2]), "+f"(c[3])
        : "r"(a[0]), "r"(a[1]), "r"(a[2]), "r"(a[3]), "r"(b[0]), "r"(b[1]));
}
__device__ __forceinline__ void prefetchL2(const void* p) {
    asm volatile("prefetch.global.L2 [%0];" :: "l"(p));
}
__device__ __forceinline__ float ldcg(const float* p) {
    float v;
    asm volatile("ld.global.cg.f32 %0, [%1];" : "=f"(v) : "l"(v = 0.0f, p));
    return v;
}
// Fast activations (error: few ulp — negligible vs 5e-6 budget)
__device__ __forceinline__ float fsig(float x) {
    return __fdividef(1.0f, 1.0f + __expf(-x));
}
__device__ __forceinline__ float ftanh(float x) {
    return 1.0f - __fdividef(2.0f, __expf(2.0f * x) + 1.0f);
}
// 16B-granule swizzle for 64B rows: conflict-free 8-row ldmatrix phases.
__device__ __forceinline__ uint32_t swz(int r, int q) {
    return (uint32_t)(r * 64 + ((q ^ ((r >> 1) & 3)) << 4));
}
#define WAITG(n) asm volatile("cp.async.wait_group %0;" :: "n"(n))

// ---------------------------------------------------------------------------
// Prep kernels
// ---------------------------------------------------------------------------
__global__ void init_kernel() {
    int i = blockIdx.x * blockDim.x + threadIdx.x;   // 64 x 1024 = 65536
    __nv_bfloat16 z = __float2bfloat16(0.0f);
    g_hf[0][i] = 0.0f;
    g_hhi[0][i] = z;
    g_hlo[0][i] = z;
    if (i < S_ * NTILES)        g_pdone[i] = 0u;
    if (i < (S_ + 1) * NTILES)  g_tdone[i] = 0u;
}
// W_hh^T with gate-grouped column permutation:
//   orig col n: gate=n/HS, cc=n%HS  ->  n_new = (cc/32)*96 + gate*32 + (cc%32)
__global__ void wprep_whh(const float* __restrict__ whh) {
    int i = blockIdx.x * blockDim.x + threadIdx.x;   // 3072 x 1024
    int k = i / G3_, n = i % G3_;
    int gate = n / HS_, cc = n % HS_;
    int n_new = (cc >> 5) * NTC + gate * 32 + (cc & 31);
    float w = whh[i];
    __nv_bfloat16 hi = __float2bfloat16(w);
    g_wthi[(size_t)n_new * HS_ + k] = hi;
    g_wtlo[(size_t)n_new * HS_ + k] = __float2bfloat16(w - __bfloat162float(hi));
}
__global__ void wprep_wih(const float* __restrict__ wih) {
    int i = blockIdx.x * blockDim.x + threadIdx.x;   // 1536 x 1024
    int k = i / G3_, n = i % G3_;
    float w = wih[i];
    __nv_bfloat16 hi = __float2bfloat16(w);
    g_wihi[(size_t)n * F_ + k] = hi;
    g_wilo[(size_t)n * F_ + k] = __float2bfloat16(w - __bfloat162float(hi));
}
__global__ void xprep(const float* __restrict__ x) {
    size_t i = (size_t)blockIdx.x * blockDim.x + threadIdx.x;
    float v = x[i];
    __nv_bfloat16 hi = __float2bfloat16(v);
    g_xhi[i] = hi;
    g_xlo[i] = __float2bfloat16(v - __bfloat162float(hi));
}

// ---------------------------------------------------------------------------
// Phase 1 GEMM (validated, unchanged): gx = x @ Wih^T (+bias), original layout.
// ---------------------------------------------------------------------------
__global__ void __launch_bounds__(128) mma_gemm_kernel(
    const __nv_bfloat16* __restrict__ Ahi, const __nv_bfloat16* __restrict__ Alo,
    const __nv_bfloat16* __restrict__ Bhi, const __nv_bfloat16* __restrict__ Blo,
    float* __restrict__ out, const float* __restrict__ bias, int K)
{
    __shared__ __align__(16) uint8_t smem_raw[2][24576];
    const int tid = threadIdx.x, lid = tid & 31, wid = tid >> 5;
    const int wm = wid & 1, wn = wid >> 1;
    const int m0 = blockIdx.y * 64, n0 = blockIdx.x * 128;
    const uint32_t sm0 = s2u(smem_raw[0]), sm1 = s2u(smem_raw[1]);

    float acc[2][8][4];
#pragma unroll
    for (int i = 0; i < 2; i++)
#pragma unroll
        for (int j = 0; j < 8; j++)
#pragma unroll
            for (int v = 0; v < 4; v++) acc[i][j][v] = 0.0f;

    const int NC = K >> 5;
    auto load_chunk = [&](uint32_t sb, int k0) {
#pragma unroll
        for (int t = 0; t < 2; t++) {
            const __nv_bfloat16* src = (t ? Alo : Ahi);
            uint32_t base = sb + t * 4096;
#pragma unroll
            for (int i = 0; i < 2; i++) {
                int cid = tid + i * 128;
                int r = cid >> 2, q = cid & 3;
                cpasync16(base + swz(r, q), src + (size_t)(m0 + r) * K + k0 + q * 8);
            }
        }
#pragma unroll
        for (int t = 0; t < 2; t++) {
            const __nv_bfloat16* src = (t ? Blo : Bhi);
            uint32_t base = sb + 8192 + t * 8192;
#pragma unroll
            for (int i = 0; i < 4; i++) {
                int cid = tid + i * 128;
                int r = cid >> 2, q = cid & 3;
                cpasync16(base + swz(r, q), src + (size_t)(n0 + r) * K + k0 + q * 8);
            }
        }
        asm volatile("cp.async.commit_group;");
    };

    load_chunk(sm0, 0);
    for (int c = 0; c < NC; c++) {
        if (c + 1 < NC) {
            load_chunk(((c + 1) & 1) ? sm1 : sm0, (c + 1) * KC);
            asm volatile("cp.async.wait_group 1;");
        } else {
            asm volatile("cp.async.wait_group 0;");
        }
        __syncthreads();
        const uint32_t sb = (c & 1) ? sm1 : sm0;
#pragma unroll
        for (int kk = 0; kk < 2; kk++) {
            const int qq = kk * 2 + (lid >> 4);
            uint32_t a_hi[2][4], a_lo[2][4];
#pragma unroll
            for (int i = 0; i < 2; i++) {
                int r = wm * 32 + i * 16 + (lid & 15);
                ldsm4(a_hi[i], sb + swz(r, qq));
                ldsm4(a_lo[i], sb + 4096 + swz(r, qq));
            }
            uint32_t b_hi[8][2], b_lo[8][2];
#pragma unroll
            for (int jj = 0; jj < 4; jj++) {
                int r = wn * 64 + jj * 16 + (lid & 15);
                uint32_t t4[4];
                ldsm4(t4, sb + 8192 + swz(r, qq));
                b_hi[2 * jj][0] = t4[0]; b_hi[2 * jj][1] = t4[2];
                b_hi[2 * jj + 1][0] = t4[1]; b_hi[2 * jj + 1][1] = t4[3];
                ldsm4(t4, sb + 16384 + swz(r, qq));
                b_lo[2 * jj][0] = t4[0]; b_lo[2 * jj][1] = t4[2];
                b_lo[2 * jj + 1][0] = t4[1]; b_lo[2 * jj + 1][1] = t4[3];
            }
#pragma unroll
            for (int i = 0; i < 2; i++)
#pragma unroll
                for (int j = 0; j < 8; j++) {
                    mma_bf16(acc[i][j], a_hi[i], b_hi[j]);
                    mma_bf16(acc[i][j], a_lo[i], b_hi[j]);
                    mma_bf16(acc[i][j], a_hi[i], b_lo[j]);
                }
        }
        __syncthreads();
    }
#pragma unroll
    for (int i = 0; i < 2; i++) {
        int m = m0 + wm * 32 + 16 * i + (lid >> 2);
#pragma unroll
        for (int j = 0; j < 8; j++) {
            int n = n0 + wn * 64 + 8 * j + 2 * (lid & 3);
            float2 v0 = make_float2(acc[i][j][0], acc[i][j][1]);
            float2 v1 = make_float2(acc[i][j][2], acc[i][j][3]);
            if (bias) {
                float b0 = bias[n], b1 = bias[n + 1];
                v0.x += b0; v0.y += b1;
                v1.x += b0; v1.y += b1;
            }
            *(float2*)(out + (size_t)m * G3_ + n) = v0;
            *(float2*)(out + (size_t)(m + 8) * G3_ + n) = v1;
        }
    }
}

// ---------------------------------------------------------------------------
// Persistent recurrence. 128 blocks = 32 tiles x 4 K-splits, 384 threads.
// Dataflow sync (vectorized producer poll), early h-publish, quarter-
// granularity load/compute pipelining.
// ---------------------------------------------------------------------------
__global__ void __launch_bounds__(NTHR) gru_persist_kernel(
    float* __restrict__ out, float* __restrict__ lastdst)
{
    extern __shared__ __align__(16) uint8_t smem[];
    const uint32_t wbase = s2u(smem);
    const uint32_t abase = wbase + SMA_OFF;

    const int tid = threadIdx.x, lid = tid & 31, wid = tid >> 5;
    const int wm = wid & 1;            // 0..1
    const int wn = wid >> 1;           // 0..5
    const int tile = blockIdx.x % NTILES;     // 0..31
    const int kh   = blockIdx.x / NTILES;     // 0..3
    const int n0   = tile * NTC;
    const int kbase = kh * KPER;

    // ---- one-time: W tile load (6144 granules, 16/thread) ----
#pragma unroll
    for (int i = 0; i < 16; i++) {
        int gid = tid + i * NTHR;
        int c   = gid / 768;
        int rem = gid % 768;
        int dt  = rem / 384;
        int g   = rem % 384;
        int r   = g >> 2, q = g & 3;
        const __nv_bfloat16* src = dt ? g_wtlo : g_wthi;
        cpasync16(wbase + c * SMW_CH + dt * 6144 + swz(r, q),
                  src + (size_t)(n0 + r) * HS_ + kbase + c * KC + q * 8);
    }
    asm volatile("cp.async.commit_group;");
    asm volatile("cp.async.wait_group 0;");
    __syncthreads();

    const int b0 = kh * 16;            // pointwise batch slice

    for (int t = 0; t < S_; t++) {
        // ---- wait for the 8 producer tiles (one vectorized L2 poll) ----
        if (t > 0) {
            if (tid == 0) {
                const unsigned* p = &g_tdone[t * NTILES + 8 * kh];
                while (true) {
                    unsigned a0, a1, a2, a3, b0_, b1_, b2_, b3_;
                    asm volatile("ld.volatile.global.v4.u32 {%0,%1,%2,%3}, [%4];"
                                 : "=r"(a0), "=r"(a1), "=r"(a2), "=r"(a3)
                                 : "l"(p));
                    asm volatile("ld.volatile.global.v4.u32 {%0,%1,%2,%3}, [%4];"
                                 : "=r"(b0_), "=r"(b1_), "=r"(b2_), "=r"(b3_)
                                 : "l"(p + 4));
                    if ((a0 & a1 & a2 & a3 & b0_ & b1_ & b2_ & b3_) == 4u &&
                        (a0 | a1 | a2 | a3 | b0_ | b1_ | b2_ | b3_) == 4u)
                        break;
                }
            }
            __syncthreads();
        }

        // ---- A (h) load: 8 chunks, one commit group each ----
        const __nv_bfloat16* __restrict__ Ahi = g_hhi[t & 3] + kbase;
        const __nv_bfloat16* __restrict__ Alo = g_hlo[t & 3] + kbase;
#pragma unroll
        for (int c = 0; c < NCH; c++) {
#pragma unroll
            for (int p = 0; p < 2; p++) {
                int idx = tid + p * NTHR;
                if (idx < 512) {
                    int dt = idx >> 8;
                    int g  = idx & 255;
                    int r  = g >> 2, q = g & 3;
                    const __nv_bfloat16* src = dt ? Alo : Ahi;
                    cpasync16(abase + c * SMA_CH + dt * 4096 + swz(r, q),
                              src + (size_t)r * HS_ + c * KC + q * 8);
                }
            }
            asm volatile("cp.async.commit_group;");
        }

        // ---- prefetch this step's gx slice into L2 ----
        {
            int e = tid;
            int b = b0 + (e >> 5);
            int cc = tile * 32 + (e & 31);
            const float* p = g_gx + ((size_t)b * S_ + t) * G3_;
            prefetchL2(p + cc);
            prefetchL2(p + HS_ + cc);
            prefetchL2(p + 2 * HS_ + cc);
        }

        float acc[2][2][4];
#pragma unroll
        for (int i = 0; i < 2; i++)
#pragma unroll
            for (int j = 0; j < 2; j++)
#pragma unroll
                for (int v = 0; v < 4; v++) acc[i][j][v] = 0.0f;

        // ---- chunk compute body ----
        auto comp = [&](int c) {
            const uint32_t sbA = abase + c * SMA_CH;
            const uint32_t sbW = wbase + c * SMW_CH;
#pragma unroll
            for (int kk = 0; kk < 2; kk++) {
                const int qq = kk * 2 + (lid >> 4);
                uint32_t a_hi[2][4], a_lo[2][4];
#pragma unroll
                for (int i = 0; i < 2; i++) {
                    int r = wm * 32 + i * 16 + (lid & 15);
                    ldsm4(a_hi[i], sbA + swz(r, qq));
                    ldsm4(a_lo[i], sbA + 4096 + swz(r, qq));
                }
                uint32_t b_hi[2][2], b_lo[2][2];
                {
                    int r = wn * 16 + (lid & 15);
                    uint32_t t4[4];
                    ldsm4(t4, sbW + swz(r, qq));
                    b_hi[0][0] = t4[0]; b_hi[0][1] = t4[2];
                    b_hi[1][0] = t4[1]; b_hi[1][1] = t4[3];
                    ldsm4(t4, sbW + 6144 + swz(r, qq));
                    b_lo[0][0] = t4[0]; b_lo[0][1] = t4[2];
                    b_lo[1][0] = t4[1]; b_lo[1][1] = t4[3];
                }
#pragma unroll
                for (int i = 0; i < 2; i++)
#pragma unroll
                    for (int j = 0; j < 2; j++) {
                        mma_bf16(acc[i][j], a_hi[i], b_hi[j]);
                        mma_bf16(acc[i][j], a_lo[i], b_hi[j]);
                        mma_bf16(acc[i][j], a_hi[i], b_lo[j]);
                    }
            }
        };

        // ---- quarter-granularity pipeline: start mma after 16 KB ----
        WAITG(6); __syncthreads(); comp(0); comp(1);
        WAITG(4); __syncthreads(); comp(2); comp(3);
        WAITG(2); __syncthreads(); comp(4); comp(5);
        WAITG(0); __syncthreads(); comp(6); comp(7);

        // ---- store partial gh tile (parity buffer) ----
        float* __restrict__ ghdst = g_ghp[t & 1][kh];
#pragma unroll
        for (int i = 0; i < 2; i++) {
            int m = wm * 32 + 16 * i + (lid >> 2);
#pragma unroll
            for (int j = 0; j < 2; j++) {
                int nc = n0 + wn * 16 + 8 * j + 2 * (lid & 3);
                *(float2*)(ghdst + (size_t)m * G3_ + nc) =
                    make_float2(acc[i][j][0], acc[i][j][1]);
                *(float2*)(ghdst + (size_t)(m + 8) * G3_ + nc) =
                    make_float2(acc[i][j][2], acc[i][j][3]);
            }
        }

        // ---- tile-local 4-way sync ----
        __threadfence();
        __syncthreads();
        if (tid == 0) {
            unsigned old = atomicAdd(&g_pdone[t * NTILES + tile], 1u);
            if (old != 3u) {
                while (*((volatile unsigned*)&g_pdone[t * NTILES + tile]) != 4u) { }
            }
        }
        __syncthreads();

        // ---- pointwise for own slice: 16 b x 32 cc = 512 elems ----
        const int tp = t & 1;
        const int o  = (t + 1) & 3;
        float hn_sv[2];
        int   hidx_sv[2];
        int   b_sv[2];
        int   cc_sv[2];
#pragma unroll
        for (int p = 0; p < 2; p++) {
            hn_sv[p] = 0.0f; hidx_sv[p] = -1; b_sv[p] = 0; cc_sv[p] = 0;
            int e = tid + p * NTHR;
            if (e < 512) {
                int b  = b0 + (e >> 5);
                int ccl = e & 31;
                int cc  = tile * 32 + ccl;
                size_t base = (size_t)b * G3_ + n0 + ccl;
                float ghz = ldcg(g_ghp[tp][0] + base)      + ldcg(g_ghp[tp][1] + base)
                          + ldcg(g_ghp[tp][2] + base)      + ldcg(g_ghp[tp][3] + base);
                float ghr = ldcg(g_ghp[tp][0] + base + 32) + ldcg(g_ghp[tp][1] + base + 32)
                          + ldcg(g_ghp[tp][2] + base + 32) + ldcg(g_ghp[tp][3] + base + 32);
                float ghe = ldcg(g_ghp[tp][0] + base + 64) + ldcg(g_ghp[tp][1] + base + 64)
                          + ldcg(g_ghp[tp][2] + base + 64) + ldcg(g_ghp[tp][3] + base + 64);
                const float* gxp = g_gx + ((size_t)b * S_ + t) * G3_;
                float z   = fsig(gxp[cc] + ghz);
                float r   = fsig(gxp[HS_ + cc] + ghr);
                float eta = ftanh(gxp[2 * HS_ + cc] + r * ftanh(ghe));
                int hidx = b * HS_ + cc;
                float hp = ldcg(&g_hf[t & 3][hidx]);
                float hn = z * hp + (1.0f - z) * eta;
                // consumers need ONLY hhi/hlo -> store those now
                __nv_bfloat16 hi = __float2bfloat16(hn);
                g_hhi[o][hidx] = hi;
                g_hlo[o][hidx] = __float2bfloat16(hn - __bfloat162float(hi));
                hn_sv[p] = hn; hidx_sv[p] = hidx; b_sv[p] = b; cc_sv[p] = cc;
            }
        }

        // ---- publish h(t+1) cols for this tile (EARLY) ----
        __threadfence();
        __syncthreads();
        if (tid == 0) atomicAdd(&g_tdone[(t + 1) * NTILES + tile], 1u);

        // ---- off-critical-path writes: hf, out, lastdst ----
#pragma unroll
        for (int p = 0; p < 2; p++) {
            if (hidx_sv[p] >= 0) {
                g_hf[o][hidx_sv[p]] = hn_sv[p];
                out[((size_t)b_sv[p] * S_ + t) * HS_ + cc_sv[p]] = hn_sv[p];
                if (lastdst && t == S_ - 1) lastdst[hidx_sv[p]] = hn_sv[p];
            }
        }
    }
}

// ---------------------------------------------------------------------------
// Host launch — 6 graph nodes.
// ---------------------------------------------------------------------------
extern "C" void kernel_launch(void* const* d_in, const int* in_sizes, int n_in,
                              void* d_out, int out_size) {
    const float* x    = (const float*)d_in[0];
    const float* wih  = (const float*)d_in[1];
    const float* whh  = (const float*)d_in[2];
    const float* bias = (const float*)d_in[3];
    float* out = (float*)d_out;

    void *p_xhi, *p_xlo, *p_wihi, *p_wilo, *p_gx;
    cudaGetSymbolAddress(&p_xhi,  g_xhi);
    cudaGetSymbolAddress(&p_xlo,  g_xlo);
    cudaGetSymbolAddress(&p_wihi, g_wihi);
    cudaGetSymbolAddress(&p_wilo, g_wilo);
    cudaGetSymbolAddress(&p_gx,   g_gx);

    cudaFuncSetAttribute(gru_persist_kernel,
                         cudaFuncAttributeMaxDynamicSharedMemorySize, SMEM_TOT);

    init_kernel<<<64, 1024>>>();
    wprep_whh<<<3072, 1024>>>(whh);
    wprep_wih<<<1536, 1024>>>(wih);
    xprep<<<16384, 1024>>>(x);

    mma_gemm_kernel<<<dim3(24, M_ / 64), 128>>>(
        (const __nv_bfloat16*)p_xhi, (const __nv_bfloat16*)p_xlo,
        (const __nv_bfloat16*)p_wihi, (const __nv_bfloat16*)p_wilo,
        (float*)p_gx, bias, F_);

    const long long seq_elems = (long long)B_ * S_ * HS_;
    float* lastdst = ((long long)out_size >= seq_elems + (long long)B_ * HS_)
                         ? out + seq_elems : nullptr;

    gru_persist_kernel<<<NBLK_P, NTHR, SMEM_TOT>>>(out, lastdst);
}

// round 11
// speedup vs baseline: 11.9961x; 1.1433x over previous
#include <cuda_runtime.h>
#include <cuda_bf16.h>
#include <cuda_fp16.h>
#include <math.h>
#include <stdint.h>

// ---------------------------------------------------------------------------
// Problem constants
// ---------------------------------------------------------------------------
#define B_   64
#define S_   512
#define F_   512
#define HS_  1024
#define G3_  3072
#define M_   (B_ * S_)

// Persistent config: 32 gate-grouped n-tiles (96 cols) x 4 K-splits = 128 blocks
#define NTILES 32
#define KSPLIT 4
#define NBLK_P (NTILES * KSPLIT)     // 128
#define NTC    96                    // cols per tile (3 gates x 32 cc)
#define KPER   256                   // k per block
#define KC     32                    // k chunk
#define NCH    (KPER / KC)           // 8
#define NTHR   384                   // 12 warps

// smem: W 8 chunks x 6KB (fp16, single term) = 49152; A 8 x (4KB hi + 4KB lo)
#define SMW_CH   6144
#define SMA_OFF  49152
#define SMA_CH   8192
#define SMEM_TOT 114688

// ---------------------------------------------------------------------------
// Device scratch
// ---------------------------------------------------------------------------
__device__ float g_gx[(size_t)M_ * G3_];
__device__ float g_ghp[2][KSPLIT][B_ * G3_];        // partials, dbl-buf by t&1
__device__ __half g_hhi[4][B_ * HS_];               // h fp16 hi (4-deep)
__device__ __half g_hlo[4][B_ * HS_];               // h fp16 lo
__device__ __half g_wt16[(size_t)G3_ * HS_];        // W_hh^T fp16, PERMUTED rows
__device__ __nv_bfloat16 g_wihi[(size_t)G3_ * F_];  // phase1 (unchanged, bf16)
__device__ __nv_bfloat16 g_wilo[(size_t)G3_ * F_];
__device__ __nv_bfloat16 g_xhi[(size_t)M_ * F_];
__device__ __nv_bfloat16 g_xlo[(size_t)M_ * F_];

// Monotone counters, prezeroed each launch
__device__ unsigned g_pdone[S_ * NTILES];        // per-step per-tile partials (->4)
__device__ unsigned g_tdone[(S_ + 1) * NTILES];  // h cols of tile ready at t (->4)

// ---------------------------------------------------------------------------
// PTX helpers (compute_80-level — target is compute_103 non-'a')
// ---------------------------------------------------------------------------
__device__ __forceinline__ uint32_t s2u(const void* p) {
    uint32_t r;
    asm("{ .reg .u64 t; cvta.to.shared.u64 t, %1; cvt.u32.u64 %0, t; }"
        : "=r"(r) : "l"(p));
    return r;
}
__device__ __forceinline__ void cpasync16(uint32_t dst, const void* src) {
    asm volatile("cp.async.cg.shared.global [%0], [%1], 16;"
                 :: "r"(dst), "l"(src));
}
__device__ __forceinline__ void ldsm4(uint32_t* r, uint32_t addr) {
    asm volatile("ldmatrix.sync.aligned.m8n8.x4.shared.b16 {%0,%1,%2,%3}, [%4];"
                 : "=r"(r[0]), "=r"(r[1]), "=r"(r[2]), "=r"(r[3]) : "r"(addr));
}
__device__ __forceinline__ void mma_bf16(float* c, const uint32_t* a,
                                         const uint32_t* b) {
    asm volatile(
        "mma.sync.aligned.m16n8k16.row.col.f32.bf16.bf16.f32 "
        "{%0,%1,%2,%3}, {%4,%5,%6,%7}, {%8,%9}, {%0,%1,%2,%3};"
        : "+f"(c[0]), "+f"(c[1]), "+f"(c[2]), "+f"(c[3])
        : "r"(a[0]), "r"(a[1]), "r"(a[2]), "r"(a[3]), "r"(b[0]), "r"(b[1]));
}
__device__ __forceinline__ void mma_f16(float* c, const uint32_t* a,
                                        const uint32_t* b) {
    asm volatile(
        "mma.sync.aligned.m16n8k16.row.col.f32.f16.f16.f32 "
        "{%0,%1,%2,%3}, {%4,%5,%6,%7}, {%8,%9}, {%0,%1,%2,%3};"
        : "+f"(c[0]), "+f"(c[1]), "+f"(c[2]), "+f"(c[3])
        : "r"(a[0]), "r"(a[1]), "r"(a[2]), "r"(a[3]), "r"(b[0]), "r"(b[1]));
}
__device__ __forceinline__ float ldcg(const float* p) {
    float v;
    asm volatile("ld.global.cg.f32 %0, [%1];" : "=f"(v) : "l"(p));
    return v;
}
// Fast activations (error: few ulp — negligible vs budget)
__device__ __forceinline__ float fsig(float x) {
    return __fdividef(1.0f, 1.0f + __expf(-x));
}
__device__ __forceinline__ float ftanh(float x) {
    return 1.0f - __fdividef(2.0f, __expf(2.0f * x) + 1.0f);
}
// 16B-granule swizzle for 64B rows: conflict-free 8-row ldmatrix phases.
__device__ __forceinline__ uint32_t swz(int r, int q) {
    return (uint32_t)(r * 64 + ((q ^ ((r >> 1) & 3)) << 4));
}
#define WAITG(n) asm volatile("cp.async.wait_group %0;" :: "n"(n))

// ---------------------------------------------------------------------------
// Prep kernels
// ---------------------------------------------------------------------------
__global__ void init_kernel() {
    int i = blockIdx.x * blockDim.x + threadIdx.x;   // 64 x 1024 = 65536
    __half z = __float2half(0.0f);
    g_hhi[0][i] = z;
    g_hlo[0][i] = z;
    if (i < S_ * NTILES)        g_pdone[i] = 0u;
    if (i < (S_ + 1) * NTILES)  g_tdone[i] = 0u;
}
// W_hh^T fp16 with gate-grouped column permutation:
//   orig col n: gate=n/HS, cc=n%HS  ->  n_new = (cc/32)*96 + gate*32 + (cc%32)
__global__ void wprep_whh(const float* __restrict__ whh) {
    int i = blockIdx.x * blockDim.x + threadIdx.x;   // 3072 x 1024
    int k = i / G3_, n = i % G3_;
    int gate = n / HS_, cc = n % HS_;
    int n_new = (cc >> 5) * NTC + gate * 32 + (cc & 31);
    g_wt16[(size_t)n_new * HS_ + k] = __float2half(whh[i]);
}
__global__ void wprep_wih(const float* __restrict__ wih) {
    int i = blockIdx.x * blockDim.x + threadIdx.x;   // 1536 x 1024
    int k = i / G3_, n = i % G3_;
    float w = wih[i];
    __nv_bfloat16 hi = __float2bfloat16(w);
    g_wihi[(size_t)n * F_ + k] = hi;
    g_wilo[(size_t)n * F_ + k] = __float2bfloat16(w - __bfloat162float(hi));
}
__global__ void xprep(const float* __restrict__ x) {
    size_t i = (size_t)blockIdx.x * blockDim.x + threadIdx.x;
    float v = x[i];
    __nv_bfloat16 hi = __float2bfloat16(v);
    g_xhi[i] = hi;
    g_xlo[i] = __float2bfloat16(v - __bfloat162float(hi));
}

// ---------------------------------------------------------------------------
// Phase 1 GEMM (validated, unchanged): gx = x @ Wih^T (+bias), 3-term bf16.
// ---------------------------------------------------------------------------
__global__ void __launch_bounds__(128) mma_gemm_kernel(
    const __nv_bfloat16* __restrict__ Ahi, const __nv_bfloat16* __restrict__ Alo,
    const __nv_bfloat16* __restrict__ Bhi, const __nv_bfloat16* __restrict__ Blo,
    float* __restrict__ out, const float* __restrict__ bias, int K)
{
    __shared__ __align__(16) uint8_t smem_raw[2][24576];
    const int tid = threadIdx.x, lid = tid & 31, wid = tid >> 5;
    const int wm = wid & 1, wn = wid >> 1;
    const int m0 = blockIdx.y * 64, n0 = blockIdx.x * 128;
    const uint32_t sm0 = s2u(smem_raw[0]), sm1 = s2u(smem_raw[1]);

    float acc[2][8][4];
#pragma unroll
    for (int i = 0; i < 2; i++)
#pragma unroll
        for (int j = 0; j < 8; j++)
#pragma unroll
            for (int v = 0; v < 4; v++) acc[i][j][v] = 0.0f;

    const int NC = K >> 5;
    auto load_chunk = [&](uint32_t sb, int k0) {
#pragma unroll
        for (int t = 0; t < 2; t++) {
            const __nv_bfloat16* src = (t ? Alo : Ahi);
            uint32_t base = sb + t * 4096;
#pragma unroll
            for (int i = 0; i < 2; i++) {
                int cid = tid + i * 128;
                int r = cid >> 2, q = cid & 3;
                cpasync16(base + swz(r, q), src + (size_t)(m0 + r) * K + k0 + q * 8);
            }
        }
#pragma unroll
        for (int t = 0; t < 2; t++) {
            const __nv_bfloat16* src = (t ? Blo : Bhi);
            uint32_t base = sb + 8192 + t * 8192;
#pragma unroll
            for (int i = 0; i < 4; i++) {
                int cid = tid + i * 128;
                int r = cid >> 2, q = cid & 3;
                cpasync16(base + swz(r, q), src + (size_t)(n0 + r) * K + k0 + q * 8);
            }
        }
        asm volatile("cp.async.commit_group;");
    };

    load_chunk(sm0, 0);
    for (int c = 0; c < NC; c++) {
        if (c + 1 < NC) {
            load_chunk(((c + 1) & 1) ? sm1 : sm0, (c + 1) * KC);
            asm volatile("cp.async.wait_group 1;");
        } else {
            asm volatile("cp.async.wait_group 0;");
        }
        __syncthreads();
        const uint32_t sb = (c & 1) ? sm1 : sm0;
#pragma unroll
        for (int kk = 0; kk < 2; kk++) {
            const int qq = kk * 2 + (lid >> 4);
            uint32_t a_hi[2][4], a_lo[2][4];
#pragma unroll
            for (int i = 0; i < 2; i++) {
                int r = wm * 32 + i * 16 + (lid & 15);
                ldsm4(a_hi[i], sb + swz(r, qq));
                ldsm4(a_lo[i], sb + 4096 + swz(r, qq));
            }
            uint32_t b_hi[8][2], b_lo[8][2];
#pragma unroll
            for (int jj = 0; jj < 4; jj++) {
                int r = wn * 64 + jj * 16 + (lid & 15);
                uint32_t t4[4];
                ldsm4(t4, sb + 8192 + swz(r, qq));
                b_hi[2 * jj][0] = t4[0]; b_hi[2 * jj][1] = t4[2];
                b_hi[2 * jj + 1][0] = t4[1]; b_hi[2 * jj + 1][1] = t4[3];
                ldsm4(t4, sb + 16384 + swz(r, qq));
                b_lo[2 * jj][0] = t4[0]; b_lo[2 * jj][1] = t4[2];
                b_lo[2 * jj + 1][0] = t4[1]; b_lo[2 * jj + 1][1] = t4[3];
            }
#pragma unroll
            for (int i = 0; i < 2; i++)
#pragma unroll
                for (int j = 0; j < 8; j++) {
                    mma_bf16(acc[i][j], a_hi[i], b_hi[j]);
                    mma_bf16(acc[i][j], a_lo[i], b_hi[j]);
                    mma_bf16(acc[i][j], a_hi[i], b_lo[j]);
                }
        }
        __syncthreads();
    }
#pragma unroll
    for (int i = 0; i < 2; i++) {
        int m = m0 + wm * 32 + 16 * i + (lid >> 2);
#pragma unroll
        for (int j = 0; j < 8; j++) {
            int n = n0 + wn * 64 + 8 * j + 2 * (lid & 3);
            float2 v0 = make_float2(acc[i][j][0], acc[i][j][1]);
            float2 v1 = make_float2(acc[i][j][2], acc[i][j][3]);
            if (bias) {
                float b0 = bias[n], b1 = bias[n + 1];
                v0.x += b0; v0.y += b1;
                v1.x += b0; v1.y += b1;
            }
            *(float2*)(out + (size_t)m * G3_ + n) = v0;
            *(float2*)(out + (size_t)(m + 8) * G3_ + n) = v1;
        }
    }
}

// ---------------------------------------------------------------------------
// Persistent recurrence. 128 blocks = 32 tiles x 4 K-splits, 384 threads.
// 2-term fp16: gh = h_hi@W16 + h_lo@W16 (shared B fragment). h carried in
// registers; gx pre-loaded to registers; dataflow sync; early publish.
// ---------------------------------------------------------------------------
__global__ void __launch_bounds__(NTHR) gru_persist_kernel(
    float* __restrict__ out, float* __restrict__ lastdst)
{
    extern __shared__ __align__(16) uint8_t smem[];
    const uint32_t wbase = s2u(smem);
    const uint32_t abase = wbase + SMA_OFF;

    const int tid = threadIdx.x, lid = tid & 31, wid = tid >> 5;
    const int wm = wid & 1;            // 0..1
    const int wn = wid >> 1;           // 0..5
    const int tile = blockIdx.x % NTILES;     // 0..31
    const int kh   = blockIdx.x / NTILES;     // 0..3
    const int n0   = tile * NTC;
    const int kbase = kh * KPER;

    // ---- one-time: W16 tile load (3072 granules, 8/thread) ----
#pragma unroll
    for (int i = 0; i < 8; i++) {
        int gid = tid + i * NTHR;
        int c   = gid / 384;           // chunk 0..7
        int g   = gid % 384;
        int r   = g >> 2, q = g & 3;   // row 0..95
        cpasync16(wbase + c * SMW_CH + swz(r, q),
                  g_wt16 + (size_t)(n0 + r) * HS_ + kbase + c * KC + q * 8);
    }
    asm volatile("cp.async.commit_group;");
    asm volatile("cp.async.wait_group 0;");
    __syncthreads();

    const int b0 = kh * 16;            // pointwise batch slice
    float hreg[2] = {0.0f, 0.0f};      // register-carried h for own slice

    for (int t = 0; t < S_; t++) {
        // ---- wait for the 8 producer tiles (one vectorized L2 poll) ----
        if (t > 0) {
            if (tid == 0) {
                const unsigned* p = &g_tdone[t * NTILES + 8 * kh];
                while (true) {
                    unsigned a0, a1, a2, a3, c0, c1, c2, c3;
                    asm volatile("ld.volatile.global.v4.u32 {%0,%1,%2,%3}, [%4];"
                                 : "=r"(a0), "=r"(a1), "=r"(a2), "=r"(a3)
                                 : "l"(p));
                    asm volatile("ld.volatile.global.v4.u32 {%0,%1,%2,%3}, [%4];"
                                 : "=r"(c0), "=r"(c1), "=r"(c2), "=r"(c3)
                                 : "l"(p + 4));
                    if ((a0 & a1 & a2 & a3 & c0 & c1 & c2 & c3) == 4u &&
                        (a0 | a1 | a2 | a3 | c0 | c1 | c2 | c3) == 4u)
                        break;
                }
            }
            __syncthreads();
        }

        // ---- A (h hi/lo fp16) load: 8 chunks, one commit group each ----
        const __half* __restrict__ Ahi = g_hhi[t & 3] + kbase;
        const __half* __restrict__ Alo = g_hlo[t & 3] + kbase;
#pragma unroll
        for (int c = 0; c < NCH; c++) {
#pragma unroll
            for (int p = 0; p < 2; p++) {
                int idx = tid + p * NTHR;
                if (idx < 512) {
                    int dt = idx >> 8;
                    int g  = idx & 255;
                    int r  = g >> 2, q = g & 3;
                    const __half* src = dt ? Alo : Ahi;
                    cpasync16(abase + c * SMA_CH + dt * 4096 + swz(r, q),
                              src + (size_t)r * HS_ + c * KC + q * 8);
                }
            }
            asm volatile("cp.async.commit_group;");
        }

        // ---- load this step's gx values into registers (off-chain) ----
        float gxv[2][3];
#pragma unroll
        for (int p = 0; p < 2; p++) {
            int e = tid + p * NTHR;
            if (e < 512) {
                int b  = b0 + (e >> 5);
                int cc = tile * 32 + (e & 31);
                const float* gxp = g_gx + ((size_t)b * S_ + t) * G3_;
                gxv[p][0] = gxp[cc];
                gxv[p][1] = gxp[HS_ + cc];
                gxv[p][2] = gxp[2 * HS_ + cc];
            } else {
                gxv[p][0] = gxv[p][1] = gxv[p][2] = 0.0f;
            }
        }

        float acc[2][2][4];
#pragma unroll
        for (int i = 0; i < 2; i++)
#pragma unroll
            for (int j = 0; j < 2; j++)
#pragma unroll
                for (int v = 0; v < 4; v++) acc[i][j][v] = 0.0f;

        // ---- chunk compute body: 2-term fp16, shared B fragment ----
        auto comp = [&](int c) {
            const uint32_t sbA = abase + c * SMA_CH;
            const uint32_t sbW = wbase + c * SMW_CH;
#pragma unroll
            for (int kk = 0; kk < 2; kk++) {
                const int qq = kk * 2 + (lid >> 4);
                uint32_t a_hi[2][4], a_lo[2][4];
#pragma unroll
                for (int i = 0; i < 2; i++) {
                    int r = wm * 32 + i * 16 + (lid & 15);
                    ldsm4(a_hi[i], sbA + swz(r, qq));
                    ldsm4(a_lo[i], sbA + 4096 + swz(r, qq));
                }
                uint32_t bfr[2][2];
                {
                    int r = wn * 16 + (lid & 15);
                    uint32_t t4[4];
                    ldsm4(t4, sbW + swz(r, qq));
                    bfr[0][0] = t4[0]; bfr[0][1] = t4[2];
                    bfr[1][0] = t4[1]; bfr[1][1] = t4[3];
                }
#pragma unroll
                for (int i = 0; i < 2; i++)
#pragma unroll
                    for (int j = 0; j < 2; j++) {
                        mma_f16(acc[i][j], a_hi[i], bfr[j]);
                        mma_f16(acc[i][j], a_lo[i], bfr[j]);
                    }
            }
        };

        // ---- quarter-granularity pipeline ----
        WAITG(6); __syncthreads(); comp(0); comp(1);
        WAITG(4); __syncthreads(); comp(2); comp(3);
        WAITG(2); __syncthreads(); comp(4); comp(5);
        WAITG(0); __syncthreads(); comp(6); comp(7);

        // ---- store partial gh tile (parity buffer) ----
        float* __restrict__ ghdst = g_ghp[t & 1][kh];
#pragma unroll
        for (int i = 0; i < 2; i++) {
            int m = wm * 32 + 16 * i + (lid >> 2);
#pragma unroll
            for (int j = 0; j < 2; j++) {
                int nc = n0 + wn * 16 + 8 * j + 2 * (lid & 3);
                *(float2*)(ghdst + (size_t)m * G3_ + nc) =
                    make_float2(acc[i][j][0], acc[i][j][1]);
                *(float2*)(ghdst + (size_t)(m + 8) * G3_ + nc) =
                    make_float2(acc[i][j][2], acc[i][j][3]);
            }
        }

        // ---- tile-local 4-way sync ----
        __threadfence();
        __syncthreads();
        if (tid == 0) {
            unsigned old = atomicAdd(&g_pdone[t * NTILES + tile], 1u);
            if (old != 3u) {
                while (*((volatile unsigned*)&g_pdone[t * NTILES + tile]) != 4u) { }
            }
        }
        __syncthreads();

        // ---- pointwise for own slice: 16 b x 32 cc = 512 elems ----
        const int tp = t & 1;
        const int o  = (t + 1) & 3;
        float hn_sv[2];
        int   hidx_sv[2];
        int   b_sv[2];
        int   cc_sv[2];
#pragma unroll
        for (int p = 0; p < 2; p++) {
            hn_sv[p] = 0.0f; hidx_sv[p] = -1; b_sv[p] = 0; cc_sv[p] = 0;
            int e = tid + p * NTHR;
            if (e < 512) {
                int b  = b0 + (e >> 5);
                int ccl = e & 31;
                int cc  = tile * 32 + ccl;
                size_t base = (size_t)b * G3_ + n0 + ccl;
                float ghz = ldcg(g_ghp[tp][0] + base)      + ldcg(g_ghp[tp][1] + base)
                          + ldcg(g_ghp[tp][2] + base)      + ldcg(g_ghp[tp][3] + base);
                float ghr = ldcg(g_ghp[tp][0] + base + 32) + ldcg(g_ghp[tp][1] + base + 32)
                          + ldcg(g_ghp[tp][2] + base + 32) + ldcg(g_ghp[tp][3] + base + 32);
                float ghe = ldcg(g_ghp[tp][0] + base + 64) + ldcg(g_ghp[tp][1] + base + 64)
                          + ldcg(g_ghp[tp][2] + base + 64) + ldcg(g_ghp[tp][3] + base + 64);
                float z   = fsig(gxv[p][0] + ghz);
                float r   = fsig(gxv[p][1] + ghr);
                float eta = ftanh(gxv[p][2] + r * ftanh(ghe));
                float hn  = z * hreg[p] + (1.0f - z) * eta;
                hreg[p] = hn;
                int hidx = b * HS_ + cc;
                // consumers need ONLY hhi/hlo -> store those now
                __half hi16 = __float2half(hn);
                g_hhi[o][hidx] = hi16;
                g_hlo[o][hidx] = __float2half(hn - __half2float(hi16));
                hn_sv[p] = hn; hidx_sv[p] = hidx; b_sv[p] = b; cc_sv[p] = cc;
            }
        }

        // ---- publish h(t+1) cols for this tile (EARLY) ----
        __threadfence();
        __syncthreads();
        if (tid == 0) atomicAdd(&g_tdone[(t + 1) * NTILES + tile], 1u);

        // ---- off-critical-path writes: out, lastdst ----
#pragma unroll
        for (int p = 0; p < 2; p++) {
            if (hidx_sv[p] >= 0) {
                out[((size_t)b_sv[p] * S_ + t) * HS_ + cc_sv[p]] = hn_sv[p];
                if (lastdst && t == S_ - 1) lastdst[hidx_sv[p]] = hn_sv[p];
            }
        }
    }
}

// ---------------------------------------------------------------------------
// Host launch — 6 graph nodes.
// ---------------------------------------------------------------------------
extern "C" void kernel_launch(void* const* d_in, const int* in_sizes, int n_in,
                              void* d_out, int out_size) {
    const float* x    = (const float*)d_in[0];
    const float* wih  = (const float*)d_in[1];
    const float* whh  = (const float*)d_in[2];
    const float* bias = (const float*)d_in[3];
    float* out = (float*)d_out;

    void *p_xhi, *p_xlo, *p_wihi, *p_wilo, *p_gx;
    cudaGetSymbolAddress(&p_xhi,  g_xhi);
    cudaGetSymbolAddress(&p_xlo,  g_xlo);
    cudaGetSymbolAddress(&p_wihi, g_wihi);
    cudaGetSymbolAddress(&p_wilo, g_wilo);
    cudaGetSymbolAddress(&p_gx,   g_gx);

    cudaFuncSetAttribute(gru_persist_kernel,
                         cudaFuncAttributeMaxDynamicSharedMemorySize, SMEM_TOT);

    init_kernel<<<64, 1024>>>();
    wprep_whh<<<3072, 1024>>>(whh);
    wprep_wih<<<1536, 1024>>>(wih);
    xprep<<<16384, 1024>>>(x);

    mma_gemm_kernel<<<dim3(24, M_ / 64), 128>>>(
        (const __nv_bfloat16*)p_xhi, (const __nv_bfloat16*)p_xlo,
        (const __nv_bfloat16*)p_wihi, (const __nv_bfloat16*)p_wilo,
        (float*)p_gx, bias, F_);

    const long long seq_elems = (long long)B_ * S_ * HS_;
    float* lastdst = ((long long)out_size >= seq_elems + (long long)B_ * HS_)
                         ? out + seq_elems : nullptr;

    gru_persist_kernel<<<NBLK_P, NTHR, SMEM_TOT>>>(out, lastdst);
}

// round 13
// speedup vs baseline: 13.5982x; 1.1335x over previous
#include <cuda_runtime.h>
#include <cuda_bf16.h>
#include <cuda_fp16.h>
#include <math.h>
#include <stdint.h>

// ---------------------------------------------------------------------------
// Problem constants
// ---------------------------------------------------------------------------
#define B_   64
#define S_   512
#define F_   512
#define HS_  1024
#define G3_  3072
#define M_   (B_ * S_)

// Persistent config: 32 gate-grouped n-tiles (96 cols) x 4 K-splits = 128 blocks
#define NTILES 32
#define KSPLIT 4
#define NBLK_P (NTILES * KSPLIT)     // 128
#define NTC    96                    // cols per tile (3 gates x 32 cc)
#define KPER   256                   // k per block
#define KC     32                    // k chunk
#define NCH    (KPER / KC)           // 8
#define NTHR   384                   // 12 warps

// smem: W 8 chunks x 6KB (fp16) = 49152; A 8 chunks x 4KB (fp16, 1 term)
#define SMW_CH   6144
#define SMA_OFF  49152
#define SMA_CH   4096
#define SMEM_TOT 81920

// ---------------------------------------------------------------------------
// Device scratch
// ---------------------------------------------------------------------------
__device__ float g_gx[(size_t)M_ * G3_];
__device__ float g_ghp[2][KSPLIT][B_ * G3_];        // partials, dbl-buf by t&1
__device__ __half g_hh16[4][B_ * HS_];              // h fp16 (4-deep)
__device__ __half g_wt16[(size_t)G3_ * HS_];        // W_hh^T fp16, PERMUTED rows
__device__ __nv_bfloat16 g_wihi[(size_t)G3_ * F_];  // phase1 (unchanged, bf16)
__device__ __nv_bfloat16 g_wilo[(size_t)G3_ * F_];
__device__ __nv_bfloat16 g_xhi[(size_t)M_ * F_];
__device__ __nv_bfloat16 g_xlo[(size_t)M_ * F_];

// Monotone counters, prezeroed each launch
__device__ unsigned g_pdone[S_ * NTILES];        // per-step per-tile partials (->4)
__device__ unsigned g_tdone[(S_ + 1) * NTILES];  // h cols of tile ready at t (->4)

// ---------------------------------------------------------------------------
// PTX helpers (compute_80-level — target is compute_103 non-'a')
// ---------------------------------------------------------------------------
__device__ __forceinline__ uint32_t s2u(const void* p) {
    uint32_t r;
    asm("{ .reg .u64 t; cvta.to.shared.u64 t, %1; cvt.u32.u64 %0, t; }"
        : "=r"(r) : "l"(p));
    return r;
}
__device__ __forceinline__ void cpasync16(uint32_t dst, const void* src) {
    asm volatile("cp.async.cg.shared.global [%0], [%1], 16;"
                 :: "r"(dst), "l"(src));
}
__device__ __forceinline__ void ldsm4(uint32_t* r, uint32_t addr) {
    asm volatile("ldmatrix.sync.aligned.m8n8.x4.shared.b16 {%0,%1,%2,%3}, [%4];"
                 : "=r"(r[0]), "=r"(r[1]), "=r"(r[2]), "=r"(r[3]) : "r"(addr));
}
__device__ __forceinline__ void mma_bf16(float* c, const uint32_t* a,
                                         const uint32_t* b) {
    asm volatile(
        "mma.sync.aligned.m16n8k16.row.col.f32.bf16.bf16.f32 "
        "{%0,%1,%2,%3}, {%4,%5,%6,%7}, {%8,%9}, {%0,%1,%2,%3};"
        : "+f"(c[0]), "+f"(c[1]), "+f"(c[2]), "+f"(c[3])
        : "r"(a[0]), "r"(a[1]), "r"(a[2]), "r"(a[3]), "r"(b[0]), "r"(b[1]));
}
__device__ __forceinline__ void mma_f16(float* c, const uint32_t* a,
                                        const uint32_t* b) {
    asm volatile(
        "mma.sync.aligned.m16n8k16.row.col.f32.f16.f16.f32 "
        "{%0,%1,%2,%3}, {%4,%5,%6,%7}, {%8,%9}, {%0,%1,%2,%3};"
        : "+f"(c[0]), "+f"(c[1]), "+f"(c[2]), "+f"(c[3])
        : "r"(a[0]), "r"(a[1]), "r"(a[2]), "r"(a[3]), "r"(b[0]), "r"(b[1]));
}
__device__ __forceinline__ float ldcg(const float* p) {
    float v;
    asm volatile("ld.global.cg.f32 %0, [%1];" : "=f"(v) : "l"(p));
    return v;
}
// Fast activations (error: few ulp — negligible vs budget)
__device__ __forceinline__ float fsig(float x) {
    return __fdividef(1.0f, 1.0f + __expf(-x));
}
__device__ __forceinline__ float ftanh(float x) {
    return 1.0f - __fdividef(2.0f, __expf(2.0f * x) + 1.0f);
}
// 16B-granule swizzle for 64B rows: conflict-free 8-row ldmatrix phases.
__device__ __forceinline__ uint32_t swz(int r, int q) {
    return (uint32_t)(r * 64 + ((q ^ ((r >> 1) & 3)) << 4));
}
#define WAITG(n) asm volatile("cp.async.wait_group %0;" :: "n"(n))

// ---------------------------------------------------------------------------
// Prep kernels
// ---------------------------------------------------------------------------
__global__ void init_kernel() {
    int i = blockIdx.x * blockDim.x + threadIdx.x;   // 64 x 1024 = 65536
    g_hh16[0][i] = __float2half(0.0f);
    if (i < S_ * NTILES)        g_pdone[i] = 0u;
    if (i < (S_ + 1) * NTILES)  g_tdone[i] = 0u;
}
// W_hh^T fp16 with gate-grouped column permutation:
//   orig col n: gate=n/HS, cc=n%HS  ->  n_new = (cc/32)*96 + gate*32 + (cc%32)
__global__ void wprep_whh(const float* __restrict__ whh) {
    int i = blockIdx.x * blockDim.x + threadIdx.x;   // 3072 x 1024
    int k = i / G3_, n = i % G3_;
    int gate = n / HS_, cc = n % HS_;
    int n_new = (cc >> 5) * NTC + gate * 32 + (cc & 31);
    g_wt16[(size_t)n_new * HS_ + k] = __float2half(whh[i]);
}
__global__ void wprep_wih(const float* __restrict__ wih) {
    int i = blockIdx.x * blockDim.x + threadIdx.x;   // 1536 x 1024
    int k = i / G3_, n = i % G3_;
    float w = wih[i];
    __nv_bfloat16 hi = __float2bfloat16(w);
    g_wihi[(size_t)n * F_ + k] = hi;
    g_wilo[(size_t)n * F_ + k] = __float2bfloat16(w - __bfloat162float(hi));
}
__global__ void xprep(const float* __restrict__ x) {
    size_t i = (size_t)blockIdx.x * blockDim.x + threadIdx.x;
    float v = x[i];
    __nv_bfloat16 hi = __float2bfloat16(v);
    g_xhi[i] = hi;
    g_xlo[i] = __float2bfloat16(v - __bfloat162float(hi));
}

// ---------------------------------------------------------------------------
// Phase 1 GEMM (validated, unchanged): gx = x @ Wih^T (+bias), 3-term bf16.
// ---------------------------------------------------------------------------
__global__ void __launch_bounds__(128) mma_gemm_kernel(
    const __nv_bfloat16* __restrict__ Ahi, const __nv_bfloat16* __restrict__ Alo,
    const __nv_bfloat16* __restrict__ Bhi, const __nv_bfloat16* __restrict__ Blo,
    float* __restrict__ out, const float* __restrict__ bias, int K)
{
    __shared__ __align__(16) uint8_t smem_raw[2][24576];
    const int tid = threadIdx.x, lid = tid & 31, wid = tid >> 5;
    const int wm = wid & 1, wn = wid >> 1;
    const int m0 = blockIdx.y * 64, n0 = blockIdx.x * 128;
    const uint32_t sm0 = s2u(smem_raw[0]), sm1 = s2u(smem_raw[1]);

    float acc[2][8][4];
#pragma unroll
    for (int i = 0; i < 2; i++)
#pragma unroll
        for (int j = 0; j < 8; j++)
#pragma unroll
            for (int v = 0; v < 4; v++) acc[i][j][v] = 0.0f;

    const int NC = K >> 5;
    auto load_chunk = [&](uint32_t sb, int k0) {
#pragma unroll
        for (int t = 0; t < 2; t++) {
            const __nv_bfloat16* src = (t ? Alo : Ahi);
            uint32_t base = sb + t * 4096;
#pragma unroll
            for (int i = 0; i < 2; i++) {
                int cid = tid + i * 128;
                int r = cid >> 2, q = cid & 3;
                cpasync16(base + swz(r, q), src + (size_t)(m0 + r) * K + k0 + q * 8);
            }
        }
#pragma unroll
        for (int t = 0; t < 2; t++) {
            const __nv_bfloat16* src = (t ? Blo : Bhi);
            uint32_t base = sb + 8192 + t * 8192;
#pragma unroll
            for (int i = 0; i < 4; i++) {
                int cid = tid + i * 128;
                int r = cid >> 2, q = cid & 3;
                cpasync16(base + swz(r, q), src + (size_t)(n0 + r) * K + k0 + q * 8);
            }
        }
        asm volatile("cp.async.commit_group;");
    };

    load_chunk(sm0, 0);
    for (int c = 0; c < NC; c++) {
        if (c + 1 < NC) {
            load_chunk(((c + 1) & 1) ? sm1 : sm0, (c + 1) * KC);
            asm volatile("cp.async.wait_group 1;");
        } else {
            asm volatile("cp.async.wait_group 0;");
        }
        __syncthreads();
        const uint32_t sb = (c & 1) ? sm1 : sm0;
#pragma unroll
        for (int kk = 0; kk < 2; kk++) {
            const int qq = kk * 2 + (lid >> 4);
            uint32_t a_hi[2][4], a_lo[2][4];
#pragma unroll
            for (int i = 0; i < 2; i++) {
                int r = wm * 32 + i * 16 + (lid & 15);
                ldsm4(a_hi[i], sb + swz(r, qq));
                ldsm4(a_lo[i], sb + 4096 + swz(r, qq));
            }
            uint32_t b_hi[8][2], b_lo[8][2];
#pragma unroll
            for (int jj = 0; jj < 4; jj++) {
                int r = wn * 64 + jj * 16 + (lid & 15);
                uint32_t t4[4];
                ldsm4(t4, sb + 8192 + swz(r, qq));
                b_hi[2 * jj][0] = t4[0]; b_hi[2 * jj][1] = t4[2];
                b_hi[2 * jj + 1][0] = t4[1]; b_hi[2 * jj + 1][1] = t4[3];
                ldsm4(t4, sb + 16384 + swz(r, qq));
                b_lo[2 * jj][0] = t4[0]; b_lo[2 * jj][1] = t4[2];
                b_lo[2 * jj + 1][0] = t4[1]; b_lo[2 * jj + 1][1] = t4[3];
            }
#pragma unroll
            for (int i = 0; i < 2; i++)
#pragma unroll
                for (int j = 0; j < 8; j++) {
                    mma_bf16(acc[i][j], a_hi[i], b_hi[j]);
                    mma_bf16(acc[i][j], a_lo[i], b_hi[j]);
                    mma_bf16(acc[i][j], a_hi[i], b_lo[j]);
                }
        }
        __syncthreads();
    }
#pragma unroll
    for (int i = 0; i < 2; i++) {
        int m = m0 + wm * 32 + 16 * i + (lid >> 2);
#pragma unroll
        for (int j = 0; j < 8; j++) {
            int n = n0 + wn * 64 + 8 * j + 2 * (lid & 3);
            float2 v0 = make_float2(acc[i][j][0], acc[i][j][1]);
            float2 v1 = make_float2(acc[i][j][2], acc[i][j][3]);
            if (bias) {
                float b0 = bias[n], b1 = bias[n + 1];
                v0.x += b0; v0.y += b1;
                v1.x += b0; v1.y += b1;
            }
            *(float2*)(out + (size_t)m * G3_ + n) = v0;
            *(float2*)(out + (size_t)(m + 8) * G3_ + n) = v1;
        }
    }
}

// ---------------------------------------------------------------------------
// Persistent recurrence. 128 blocks = 32 tiles x 4 K-splits, 384 threads.
// 1-term fp16: gh = h16 @ W16. h carried in registers; gx pre-loaded;
// dataflow sync; early publish.
// ---------------------------------------------------------------------------
__global__ void __launch_bounds__(NTHR) gru_persist_kernel(
    float* __restrict__ out, float* __restrict__ lastdst)
{
    extern __shared__ __align__(16) uint8_t smem[];
    const uint32_t wbase = s2u(smem);
    const uint32_t abase = wbase + SMA_OFF;

    const int tid = threadIdx.x, lid = tid & 31, wid = tid >> 5;
    const int wm = wid & 1;            // 0..1
    const int wn = wid >> 1;           // 0..5
    const int tile = blockIdx.x % NTILES;     // 0..31
    const int kh   = blockIdx.x / NTILES;     // 0..3
    const int n0   = tile * NTC;
    const int kbase = kh * KPER;

    // ---- one-time: W16 tile load (3072 granules, 8/thread) ----
#pragma unroll
    for (int i = 0; i < 8; i++) {
        int gid = tid + i * NTHR;
        int c   = gid / 384;           // chunk 0..7
        int g   = gid % 384;
        int r   = g >> 2, q = g & 3;   // row 0..95
        cpasync16(wbase + c * SMW_CH + swz(r, q),
                  g_wt16 + (size_t)(n0 + r) * HS_ + kbase + c * KC + q * 8);
    }
    asm volatile("cp.async.commit_group;");
    asm volatile("cp.async.wait_group 0;");
    __syncthreads();

    const int b0 = kh * 16;            // pointwise batch slice
    float hreg[2] = {0.0f, 0.0f};      // register-carried h for own slice

    for (int t = 0; t < S_; t++) {
        // ---- wait for the 8 producer tiles (one vectorized L2 poll) ----
        if (t > 0) {
            if (tid == 0) {
                const unsigned* p = &g_tdone[t * NTILES + 8 * kh];
                while (true) {
                    unsigned a0, a1, a2, a3, c0, c1, c2, c3;
                    asm volatile("ld.volatile.global.v4.u32 {%0,%1,%2,%3}, [%4];"
                                 : "=r"(a0), "=r"(a1), "=r"(a2), "=r"(a3)
                                 : "l"(p));
                    asm volatile("ld.volatile.global.v4.u32 {%0,%1,%2,%3}, [%4];"
                                 : "=r"(c0), "=r"(c1), "=r"(c2), "=r"(c3)
                                 : "l"(p + 4));
                    if ((a0 & a1 & a2 & a3 & c0 & c1 & c2 & c3) == 4u &&
                        (a0 | a1 | a2 | a3 | c0 | c1 | c2 | c3) == 4u)
                        break;
                }
            }
            __syncthreads();
        }

        // ---- A (h fp16, single term) load: 8 chunks, 256 granules each ----
        const __half* __restrict__ Ah = g_hh16[t & 3] + kbase;
#pragma unroll
        for (int c = 0; c < NCH; c++) {
            if (tid < 256) {
                int r = tid >> 2, q = tid & 3;
                cpasync16(abase + c * SMA_CH + swz(r, q),
                          Ah + (size_t)r * HS_ + c * KC + q * 8);
            }
            asm volatile("cp.async.commit_group;");
        }

        // ---- load this step's gx values into registers (off-chain) ----
        float gxv[2][3];
#pragma unroll
        for (int p = 0; p < 2; p++) {
            int e = tid + p * NTHR;
            if (e < 512) {
                int b  = b0 + (e >> 5);
                int cc = tile * 32 + (e & 31);
                const float* gxp = g_gx + ((size_t)b * S_ + t) * G3_;
                gxv[p][0] = gxp[cc];
                gxv[p][1] = gxp[HS_ + cc];
                gxv[p][2] = gxp[2 * HS_ + cc];
            } else {
                gxv[p][0] = gxv[p][1] = gxv[p][2] = 0.0f;
            }
        }

        float acc[2][2][4];
#pragma unroll
        for (int i = 0; i < 2; i++)
#pragma unroll
            for (int j = 0; j < 2; j++)
#pragma unroll
                for (int v = 0; v < 4; v++) acc[i][j][v] = 0.0f;

        // ---- chunk compute body: 1-term fp16 ----
        auto comp = [&](int c) {
            const uint32_t sbA = abase + c * SMA_CH;
            const uint32_t sbW = wbase + c * SMW_CH;
#pragma unroll
            for (int kk = 0; kk < 2; kk++) {
                const int qq = kk * 2 + (lid >> 4);
                uint32_t afr[2][4];
#pragma unroll
                for (int i = 0; i < 2; i++) {
                    int r = wm * 32 + i * 16 + (lid & 15);
                    ldsm4(afr[i], sbA + swz(r, qq));
                }
                uint32_t bfr[2][2];
                {
                    int r = wn * 16 + (lid & 15);
                    uint32_t t4[4];
                    ldsm4(t4, sbW + swz(r, qq));
                    bfr[0][0] = t4[0]; bfr[0][1] = t4[2];
                    bfr[1][0] = t4[1]; bfr[1][1] = t4[3];
                }
#pragma unroll
                for (int i = 0; i < 2; i++)
#pragma unroll
                    for (int j = 0; j < 2; j++)
                        mma_f16(acc[i][j], afr[i], bfr[j]);
            }
        };

        // ---- quarter-granularity pipeline ----
        WAITG(6); __syncthreads(); comp(0); comp(1);
        WAITG(4); __syncthreads(); comp(2); comp(3);
        WAITG(2); __syncthreads(); comp(4); comp(5);
        WAITG(0); __syncthreads(); comp(6); comp(7);

        // ---- store partial gh tile (parity buffer) ----
        float* __restrict__ ghdst = g_ghp[t & 1][kh];
#pragma unroll
        for (int i = 0; i < 2; i++) {
            int m = wm * 32 + 16 * i + (lid >> 2);
#pragma unroll
            for (int j = 0; j < 2; j++) {
                int nc = n0 + wn * 16 + 8 * j + 2 * (lid & 3);
                *(float2*)(ghdst + (size_t)m * G3_ + nc) =
                    make_float2(acc[i][j][0], acc[i][j][1]);
                *(float2*)(ghdst + (size_t)(m + 8) * G3_ + nc) =
                    make_float2(acc[i][j][2], acc[i][j][3]);
            }
        }

        // ---- tile-local 4-way sync ----
        __threadfence();
        __syncthreads();
        if (tid == 0) {
            unsigned old = atomicAdd(&g_pdone[t * NTILES + tile], 1u);
            if (old != 3u) {
                while (*((volatile unsigned*)&g_pdone[t * NTILES + tile]) != 4u) { }
            }
        }
        __syncthreads();

        // ---- pointwise for own slice: 16 b x 32 cc = 512 elems ----
        const int tp = t & 1;
        const int o  = (t + 1) & 3;
        float hn_sv[2];
        int   hidx_sv[2];
        int   b_sv[2];
        int   cc_sv[2];
#pragma unroll
        for (int p = 0; p < 2; p++) {
            hn_sv[p] = 0.0f; hidx_sv[p] = -1; b_sv[p] = 0; cc_sv[p] = 0;
            int e = tid + p * NTHR;
            if (e < 512) {
                int b  = b0 + (e >> 5);
                int ccl = e & 31;
                int cc  = tile * 32 + ccl;
                size_t base = (size_t)b * G3_ + n0 + ccl;
                float ghz = ldcg(g_ghp[tp][0] + base)      + ldcg(g_ghp[tp][1] + base)
                          + ldcg(g_ghp[tp][2] + base)      + ldcg(g_ghp[tp][3] + base);
                float ghr = ldcg(g_ghp[tp][0] + base + 32) + ldcg(g_ghp[tp][1] + base + 32)
                          + ldcg(g_ghp[tp][2] + base + 32) + ldcg(g_ghp[tp][3] + base + 32);
                float ghe = ldcg(g_ghp[tp][0] + base + 64) + ldcg(g_ghp[tp][1] + base + 64)
                          + ldcg(g_ghp[tp][2] + base + 64) + ldcg(g_ghp[tp][3] + base + 64);
                float z   = fsig(gxv[p][0] + ghz);
                float r   = fsig(gxv[p][1] + ghr);
                float eta = ftanh(gxv[p][2] + r * ftanh(ghe));
                float hn  = z * hreg[p] + (1.0f - z) * eta;
                hreg[p] = hn;
                int hidx = b * HS_ + cc;
                // consumers need ONLY hh16 -> store it now
                g_hh16[o][hidx] = __float2half(hn);
                hn_sv[p] = hn; hidx_sv[p] = hidx; b_sv[p] = b; cc_sv[p] = cc;
            }
        }

        // ---- publish h(t+1) cols for this tile (EARLY) ----
        __threadfence();
        __syncthreads();
        if (tid == 0) atomicAdd(&g_tdone[(t + 1) * NTILES + tile], 1u);

        // ---- off-critical-path writes: out, lastdst ----
#pragma unroll
        for (int p = 0; p < 2; p++) {
            if (hidx_sv[p] >= 0) {
                out[((size_t)b_sv[p] * S_ + t) * HS_ + cc_sv[p]] = hn_sv[p];
                if (lastdst && t == S_ - 1) lastdst[hidx_sv[p]] = hn_sv[p];
            }
        }
    }
}

// ---------------------------------------------------------------------------
// Host launch — 6 graph nodes.
// ---------------------------------------------------------------------------
extern "C" void kernel_launch(void* const* d_in, const int* in_sizes, int n_in,
                              void* d_out, int out_size) {
    const float* x    = (const float*)d_in[0];
    const float* wih  = (const float*)d_in[1];
    const float* whh  = (const float*)d_in[2];
    const float* bias = (const float*)d_in[3];
    float* out = (float*)d_out;

    void *p_xhi, *p_xlo, *p_wihi, *p_wilo, *p_gx;
    cudaGetSymbolAddress(&p_xhi,  g_xhi);
    cudaGetSymbolAddress(&p_xlo,  g_xlo);
    cudaGetSymbolAddress(&p_wihi, g_wihi);
    cudaGetSymbolAddress(&p_wilo, g_wilo);
    cudaGetSymbolAddress(&p_gx,   g_gx);

    cudaFuncSetAttribute(gru_persist_kernel,
                         cudaFuncAttributeMaxDynamicSharedMemorySize, SMEM_TOT);

    init_kernel<<<64, 1024>>>();
    wprep_whh<<<3072, 1024>>>(whh);
    wprep_wih<<<1536, 1024>>>(wih);
    xprep<<<16384, 1024>>>(x);

    mma_gemm_kernel<<<dim3(24, M_ / 64), 128>>>(
        (const __nv_bfloat16*)p_xhi, (const __nv_bfloat16*)p_xlo,
        (const __nv_bfloat16*)p_wihi, (const __nv_bfloat16*)p_wilo,
        (float*)p_gx, bias, F_);

    const long long seq_elems = (long long)B_ * S_ * HS_;
    float* lastdst = ((long long)out_size >= seq_elems + (long long)B_ * HS_)
                         ? out + seq_elems : nullptr;

    gru_persist_kernel<<<NBLK_P, NTHR, SMEM_TOT>>>(out, lastdst);
}

// round 14
// speedup vs baseline: 15.4313x; 1.1348x over previous
#include <cuda_runtime.h>
#include <cuda_fp16.h>
#include <math.h>
#include <stdint.h>

// ---------------------------------------------------------------------------
// Problem constants
// ---------------------------------------------------------------------------
#define B_   64
#define S_   512
#define F_   512
#define HS_  1024
#define G3_  3072
#define M_   (B_ * S_)

// Persistent config: 32 gate-grouped n-tiles (96 cols) x 4 K-splits = 128 blocks
#define NTILES 32
#define KSPLIT 4
#define NBLK_P (NTILES * KSPLIT)     // 128
#define NTC    96                    // cols per tile (3 gates x 32 cc)
#define KPER   256                   // k per block
#define KC     32                    // k chunk
#define NCH    (KPER / KC)           // 8
#define NTHR   384                   // 12 warps

// smem (recurrence): W 8 chunks x 6KB = 49152; A 8 chunks x 4KB
#define SMW_CH   6144
#define SMA_OFF  49152
#define SMA_CH   4096
#define SMEM_TOT 81920

// ---------------------------------------------------------------------------
// Device scratch
// ---------------------------------------------------------------------------
__device__ float g_gx[(size_t)M_ * G3_];
__device__ float g_ghp[2][KSPLIT][B_ * G3_];        // partials, dbl-buf by t&1
__device__ __half g_hh16[4][B_ * HS_];              // h fp16 (4-deep)
__device__ __half g_wt16[(size_t)G3_ * HS_];        // W_hh^T fp16, PERMUTED rows
__device__ __half g_wi16[(size_t)G3_ * F_];         // W_ih^T fp16 [3072][512]
__device__ __half g_x16[(size_t)M_ * F_];           // x fp16 [32768][512]

// Monotone counters, prezeroed each launch
__device__ unsigned g_pdone[S_ * NTILES];        // per-step per-tile partials (->4)
__device__ unsigned g_tdone[(S_ + 1) * NTILES];  // h cols of tile ready at t (->4)

// ---------------------------------------------------------------------------
// PTX helpers (compute_80-level — target is compute_103 non-'a')
// ---------------------------------------------------------------------------
__device__ __forceinline__ uint32_t s2u(const void* p) {
    uint32_t r;
    asm("{ .reg .u64 t; cvta.to.shared.u64 t, %1; cvt.u32.u64 %0, t; }"
        : "=r"(r) : "l"(p));
    return r;
}
__device__ __forceinline__ void cpasync16(uint32_t dst, const void* src) {
    asm volatile("cp.async.cg.shared.global [%0], [%1], 16;"
                 :: "r"(dst), "l"(src));
}
__device__ __forceinline__ void ldsm4(uint32_t* r, uint32_t addr) {
    asm volatile("ldmatrix.sync.aligned.m8n8.x4.shared.b16 {%0,%1,%2,%3}, [%4];"
                 : "=r"(r[0]), "=r"(r[1]), "=r"(r[2]), "=r"(r[3]) : "r"(addr));
}
__device__ __forceinline__ void mma_f16(float* c, const uint32_t* a,
                                        const uint32_t* b) {
    asm volatile(
        "mma.sync.aligned.m16n8k16.row.col.f32.f16.f16.f32 "
        "{%0,%1,%2,%3}, {%4,%5,%6,%7}, {%8,%9}, {%0,%1,%2,%3};"
        : "+f"(c[0]), "+f"(c[1]), "+f"(c[2]), "+f"(c[3])
        : "r"(a[0]), "r"(a[1]), "r"(a[2]), "r"(a[3]), "r"(b[0]), "r"(b[1]));
}
__device__ __forceinline__ float ldcg(const float* p) {
    float v;
    asm volatile("ld.global.cg.f32 %0, [%1];" : "=f"(v) : "l"(p));
    return v;
}
// Fast activations (error: few ulp — negligible vs budget)
__device__ __forceinline__ float fsig(float x) {
    return __fdividef(1.0f, 1.0f + __expf(-x));
}
__device__ __forceinline__ float ftanh(float x) {
    return 1.0f - __fdividef(2.0f, __expf(2.0f * x) + 1.0f);
}
// 16B-granule swizzle for 64B rows: conflict-free 8-row ldmatrix phases.
__device__ __forceinline__ uint32_t swz(int r, int q) {
    return (uint32_t)(r * 64 + ((q ^ ((r >> 1) & 3)) << 4));
}
#define WAITG(n) asm volatile("cp.async.wait_group %0;" :: "n"(n))

// ---------------------------------------------------------------------------
// Prep kernels
// ---------------------------------------------------------------------------
__global__ void init_kernel() {
    int i = blockIdx.x * blockDim.x + threadIdx.x;   // 64 x 1024 = 65536
    g_hh16[0][i] = __float2half(0.0f);
    if (i < S_ * NTILES)        g_pdone[i] = 0u;
    if (i < (S_ + 1) * NTILES)  g_tdone[i] = 0u;
}
// W_hh^T fp16 with gate-grouped column permutation:
//   orig col n: gate=n/HS, cc=n%HS  ->  n_new = (cc/32)*96 + gate*32 + (cc%32)
__global__ void wprep_whh(const float* __restrict__ whh) {
    int i = blockIdx.x * blockDim.x + threadIdx.x;   // 3072 x 1024
    int k = i / G3_, n = i % G3_;
    int gate = n / HS_, cc = n % HS_;
    int n_new = (cc >> 5) * NTC + gate * 32 + (cc & 31);
    g_wt16[(size_t)n_new * HS_ + k] = __float2half(whh[i]);
}
__global__ void wprep_wih(const float* __restrict__ wih) {
    int i = blockIdx.x * blockDim.x + threadIdx.x;   // 1536 x 1024
    int k = i / G3_, n = i % G3_;
    g_wi16[(size_t)n * F_ + k] = __float2half(wih[i]);
}
__global__ void xprep(const float* __restrict__ x) {
    size_t i = (size_t)blockIdx.x * blockDim.x + threadIdx.x;  // 16384 x 1024
    g_x16[i] = __float2half(x[i]);
}

// ---------------------------------------------------------------------------
// Phase 1 GEMM, 1-term fp16: gx = x16 @ Wih16^T (+bias), original col layout.
// Block 64m x 128n, 4 warps 2x2, warp 32x64, KC=32 double-buffered.
// ---------------------------------------------------------------------------
__global__ void __launch_bounds__(128) mma_gemm16_kernel(
    const __half* __restrict__ A, const __half* __restrict__ Bw,
    float* __restrict__ out, const float* __restrict__ bias, int K)
{
    __shared__ __align__(16) uint8_t smem_raw[2][12288];  // A 4KB + B 8KB
    const int tid = threadIdx.x, lid = tid & 31, wid = tid >> 5;
    const int wm = wid & 1, wn = wid >> 1;
    const int m0 = blockIdx.y * 64, n0 = blockIdx.x * 128;
    const uint32_t sm0 = s2u(smem_raw[0]), sm1 = s2u(smem_raw[1]);

    float acc[2][8][4];
#pragma unroll
    for (int i = 0; i < 2; i++)
#pragma unroll
        for (int j = 0; j < 8; j++)
#pragma unroll
            for (int v = 0; v < 4; v++) acc[i][j][v] = 0.0f;

    const int NC = K >> 5;
    auto load_chunk = [&](uint32_t sb, int k0) {
        // A: 64 rows x 4 granules = 256 -> 2/thread
#pragma unroll
        for (int i = 0; i < 2; i++) {
            int cid = tid + i * 128;
            int r = cid >> 2, q = cid & 3;
            cpasync16(sb + swz(r, q), A + (size_t)(m0 + r) * K + k0 + q * 8);
        }
        // B: 128 rows x 4 granules = 512 -> 4/thread
#pragma unroll
        for (int i = 0; i < 4; i++) {
            int cid = tid + i * 128;
            int r = cid >> 2, q = cid & 3;
            cpasync16(sb + 4096 + swz(r, q), Bw + (size_t)(n0 + r) * K + k0 + q * 8);
        }
        asm volatile("cp.async.commit_group;");
    };

    load_chunk(sm0, 0);
    for (int c = 0; c < NC; c++) {
        if (c + 1 < NC) {
            load_chunk(((c + 1) & 1) ? sm1 : sm0, (c + 1) * KC);
            asm volatile("cp.async.wait_group 1;");
        } else {
            asm volatile("cp.async.wait_group 0;");
        }
        __syncthreads();
        const uint32_t sb = (c & 1) ? sm1 : sm0;
#pragma unroll
        for (int kk = 0; kk < 2; kk++) {
            const int qq = kk * 2 + (lid >> 4);
            uint32_t afr[2][4];
#pragma unroll
            for (int i = 0; i < 2; i++) {
                int r = wm * 32 + i * 16 + (lid & 15);
                ldsm4(afr[i], sb + swz(r, qq));
            }
            uint32_t bfr[8][2];
#pragma unroll
            for (int jj = 0; jj < 4; jj++) {
                int r = wn * 64 + jj * 16 + (lid & 15);
                uint32_t t4[4];
                ldsm4(t4, sb + 4096 + swz(r, qq));
                bfr[2 * jj][0] = t4[0]; bfr[2 * jj][1] = t4[2];
                bfr[2 * jj + 1][0] = t4[1]; bfr[2 * jj + 1][1] = t4[3];
            }
#pragma unroll
            for (int i = 0; i < 2; i++)
#pragma unroll
                for (int j = 0; j < 8; j++)
                    mma_f16(acc[i][j], afr[i], bfr[j]);
        }
        __syncthreads();
    }
#pragma unroll
    for (int i = 0; i < 2; i++) {
        int m = m0 + wm * 32 + 16 * i + (lid >> 2);
#pragma unroll
        for (int j = 0; j < 8; j++) {
            int n = n0 + wn * 64 + 8 * j + 2 * (lid & 3);
            float b0 = bias[n], b1 = bias[n + 1];
            *(float2*)(out + (size_t)m * G3_ + n) =
                make_float2(acc[i][j][0] + b0, acc[i][j][1] + b1);
            *(float2*)(out + (size_t)(m + 8) * G3_ + n) =
                make_float2(acc[i][j][2] + b0, acc[i][j][3] + b1);
        }
    }
}

// ---------------------------------------------------------------------------
// Persistent recurrence (FROZEN from R13). 128 blocks = 32 tiles x 4 K-splits,
// 384 threads. 1-term fp16: gh = h16 @ W16. h in registers; gx pre-loaded;
// dataflow sync; early publish.
// ---------------------------------------------------------------------------
__global__ void __launch_bounds__(NTHR) gru_persist_kernel(
    float* __restrict__ out, float* __restrict__ lastdst)
{
    extern __shared__ __align__(16) uint8_t smem[];
    const uint32_t wbase = s2u(smem);
    const uint32_t abase = wbase + SMA_OFF;

    const int tid = threadIdx.x, lid = tid & 31, wid = tid >> 5;
    const int wm = wid & 1;            // 0..1
    const int wn = wid >> 1;           // 0..5
    const int tile = blockIdx.x % NTILES;     // 0..31
    const int kh   = blockIdx.x / NTILES;     // 0..3
    const int n0   = tile * NTC;
    const int kbase = kh * KPER;

    // ---- one-time: W16 tile load (3072 granules, 8/thread) ----
#pragma unroll
    for (int i = 0; i < 8; i++) {
        int gid = tid + i * NTHR;
        int c   = gid / 384;           // chunk 0..7
        int g   = gid % 384;
        int r   = g >> 2, q = g & 3;   // row 0..95
        cpasync16(wbase + c * SMW_CH + swz(r, q),
                  g_wt16 + (size_t)(n0 + r) * HS_ + kbase + c * KC + q * 8);
    }
    asm volatile("cp.async.commit_group;");
    asm volatile("cp.async.wait_group 0;");
    __syncthreads();

    const int b0 = kh * 16;            // pointwise batch slice
    float hreg[2] = {0.0f, 0.0f};      // register-carried h for own slice

    for (int t = 0; t < S_; t++) {
        // ---- wait for the 8 producer tiles (one vectorized L2 poll) ----
        if (t > 0) {
            if (tid == 0) {
                const unsigned* p = &g_tdone[t * NTILES + 8 * kh];
                while (true) {
                    unsigned a0, a1, a2, a3, c0, c1, c2, c3;
                    asm volatile("ld.volatile.global.v4.u32 {%0,%1,%2,%3}, [%4];"
                                 : "=r"(a0), "=r"(a1), "=r"(a2), "=r"(a3)
                                 : "l"(p));
                    asm volatile("ld.volatile.global.v4.u32 {%0,%1,%2,%3}, [%4];"
                                 : "=r"(c0), "=r"(c1), "=r"(c2), "=r"(c3)
                                 : "l"(p + 4));
                    if ((a0 & a1 & a2 & a3 & c0 & c1 & c2 & c3) == 4u &&
                        (a0 | a1 | a2 | a3 | c0 | c1 | c2 | c3) == 4u)
                        break;
                }
            }
            __syncthreads();
        }

        // ---- A (h fp16, single term) load: 8 chunks, 256 granules each ----
        const __half* __restrict__ Ah = g_hh16[t & 3] + kbase;
#pragma unroll
        for (int c = 0; c < NCH; c++) {
            if (tid < 256) {
                int r = tid >> 2, q = tid & 3;
                cpasync16(abase + c * SMA_CH + swz(r, q),
                          Ah + (size_t)r * HS_ + c * KC + q * 8);
            }
            asm volatile("cp.async.commit_group;");
        }

        // ---- load this step's gx values into registers (off-chain) ----
        float gxv[2][3];
#pragma unroll
        for (int p = 0; p < 2; p++) {
            int e = tid + p * NTHR;
            if (e < 512) {
                int b  = b0 + (e >> 5);
                int cc = tile * 32 + (e & 31);
                const float* gxp = g_gx + ((size_t)b * S_ + t) * G3_;
                gxv[p][0] = gxp[cc];
                gxv[p][1] = gxp[HS_ + cc];
                gxv[p][2] = gxp[2 * HS_ + cc];
            } else {
                gxv[p][0] = gxv[p][1] = gxv[p][2] = 0.0f;
            }
        }

        float acc[2][2][4];
#pragma unroll
        for (int i = 0; i < 2; i++)
#pragma unroll
            for (int j = 0; j < 2; j++)
#pragma unroll
                for (int v = 0; v < 4; v++) acc[i][j][v] = 0.0f;

        // ---- chunk compute body: 1-term fp16 ----
        auto comp = [&](int c) {
            const uint32_t sbA = abase + c * SMA_CH;
            const uint32_t sbW = wbase + c * SMW_CH;
#pragma unroll
            for (int kk = 0; kk < 2; kk++) {
                const int qq = kk * 2 + (lid >> 4);
                uint32_t afr[2][4];
#pragma unroll
                for (int i = 0; i < 2; i++) {
                    int r = wm * 32 + i * 16 + (lid & 15);
                    ldsm4(afr[i], sbA + swz(r, qq));
                }
                uint32_t bfr[2][2];
                {
                    int r = wn * 16 + (lid & 15);
                    uint32_t t4[4];
                    ldsm4(t4, sbW + swz(r, qq));
                    bfr[0][0] = t4[0]; bfr[0][1] = t4[2];
                    bfr[1][0] = t4[1]; bfr[1][1] = t4[3];
                }
#pragma unroll
                for (int i = 0; i < 2; i++)
#pragma unroll
                    for (int j = 0; j < 2; j++)
                        mma_f16(acc[i][j], afr[i], bfr[j]);
            }
        };

        // ---- quarter-granularity pipeline ----
        WAITG(6); __syncthreads(); comp(0); comp(1);
        WAITG(4); __syncthreads(); comp(2); comp(3);
        WAITG(2); __syncthreads(); comp(4); comp(5);
        WAITG(0); __syncthreads(); comp(6); comp(7);

        // ---- store partial gh tile (parity buffer) ----
        float* __restrict__ ghdst = g_ghp[t & 1][kh];
#pragma unroll
        for (int i = 0; i < 2; i++) {
            int m = wm * 32 + 16 * i + (lid >> 2);
#pragma unroll
            for (int j = 0; j < 2; j++) {
                int nc = n0 + wn * 16 + 8 * j + 2 * (lid & 3);
                *(float2*)(ghdst + (size_t)m * G3_ + nc) =
                    make_float2(acc[i][j][0], acc[i][j][1]);
                *(float2*)(ghdst + (size_t)(m + 8) * G3_ + nc) =
                    make_float2(acc[i][j][2], acc[i][j][3]);
            }
        }

        // ---- tile-local 4-way sync ----
        __threadfence();
        __syncthreads();
        if (tid == 0) {
            unsigned old = atomicAdd(&g_pdone[t * NTILES + tile], 1u);
            if (old != 3u) {
                while (*((volatile unsigned*)&g_pdone[t * NTILES + tile]) != 4u) { }
            }
        }
        __syncthreads();

        // ---- pointwise for own slice: 16 b x 32 cc = 512 elems ----
        const int tp = t & 1;
        const int o  = (t + 1) & 3;
        float hn_sv[2];
        int   hidx_sv[2];
        int   b_sv[2];
        int   cc_sv[2];
#pragma unroll
        for (int p = 0; p < 2; p++) {
            hn_sv[p] = 0.0f; hidx_sv[p] = -1; b_sv[p] = 0; cc_sv[p] = 0;
            int e = tid + p * NTHR;
            if (e < 512) {
                int b  = b0 + (e >> 5);
                int ccl = e & 31;
                int cc  = tile * 32 + ccl;
                size_t base = (size_t)b * G3_ + n0 + ccl;
                float ghz = ldcg(g_ghp[tp][0] + base)      + ldcg(g_ghp[tp][1] + base)
                          + ldcg(g_ghp[tp][2] + base)      + ldcg(g_ghp[tp][3] + base);
                float ghr = ldcg(g_ghp[tp][0] + base + 32) + ldcg(g_ghp[tp][1] + base + 32)
                          + ldcg(g_ghp[tp][2] + base + 32) + ldcg(g_ghp[tp][3] + base + 32);
                float ghe = ldcg(g_ghp[tp][0] + base + 64) + ldcg(g_ghp[tp][1] + base + 64)
                          + ldcg(g_ghp[tp][2] + base + 64) + ldcg(g_ghp[tp][3] + base + 64);
                float z   = fsig(gxv[p][0] + ghz);
                float r   = fsig(gxv[p][1] + ghr);
                float eta = ftanh(gxv[p][2] + r * ftanh(ghe));
                float hn  = z * hreg[p] + (1.0f - z) * eta;
                hreg[p] = hn;
                int hidx = b * HS_ + cc;
                // consumers need ONLY hh16 -> store it now
                g_hh16[o][hidx] = __float2half(hn);
                hn_sv[p] = hn; hidx_sv[p] = hidx; b_sv[p] = b; cc_sv[p] = cc;
            }
        }

        // ---- publish h(t+1) cols for this tile (EARLY) ----
        __threadfence();
        __syncthreads();
        if (tid == 0) atomicAdd(&g_tdone[(t + 1) * NTILES + tile], 1u);

        // ---- off-critical-path writes: out, lastdst ----
#pragma unroll
        for (int p = 0; p < 2; p++) {
            if (hidx_sv[p] >= 0) {
                out[((size_t)b_sv[p] * S_ + t) * HS_ + cc_sv[p]] = hn_sv[p];
                if (lastdst && t == S_ - 1) lastdst[hidx_sv[p]] = hn_sv[p];
            }
        }
    }
}

// ---------------------------------------------------------------------------
// Host launch — 6 graph nodes.
// ---------------------------------------------------------------------------
extern "C" void kernel_launch(void* const* d_in, const int* in_sizes, int n_in,
                              void* d_out, int out_size) {
    const float* x    = (const float*)d_in[0];
    const float* wih  = (const float*)d_in[1];
    const float* whh  = (const float*)d_in[2];
    const float* bias = (const float*)d_in[3];
    float* out = (float*)d_out;

    void *p_x16, *p_wi16, *p_gx;
    cudaGetSymbolAddress(&p_x16,  g_x16);
    cudaGetSymbolAddress(&p_wi16, g_wi16);
    cudaGetSymbolAddress(&p_gx,   g_gx);

    cudaFuncSetAttribute(gru_persist_kernel,
                         cudaFuncAttributeMaxDynamicSharedMemorySize, SMEM_TOT);

    init_kernel<<<64, 1024>>>();
    wprep_whh<<<3072, 1024>>>(whh);
    wprep_wih<<<1536, 1024>>>(wih);
    xprep<<<16384, 1024>>>(x);

    mma_gemm16_kernel<<<dim3(24, M_ / 64), 128>>>(
        (const __half*)p_x16, (const __half*)p_wi16,
        (float*)p_gx, bias, F_);

    const long long seq_elems = (long long)B_ * S_ * HS_;
    float* lastdst = ((long long)out_size >= seq_elems + (long long)B_ * HS_)
                         ? out + seq_elems : nullptr;

    gru_persist_kernel<<<NBLK_P, NTHR, SMEM_TOT>>>(out, lastdst);
}